// round 10
// baseline (speedup 1.0000x reference)
#include <cuda_runtime.h>
#include <cuda_bf16.h>
#include <math.h>
#include <stdint.h>

#define NTOK 13320
#define BATCH 240
#define DM 512
#define DI 2048
#define NH 8
#define DKH 64
#define LNEPS 1e-5f
#define NQ 1024
#define NKV 2048

typedef unsigned long long u64;

// ================= scratch (static device globals; no allocation) =================
__device__ float g_t14  [4 * NTOK * DM];
__device__ float g_out14[4 * NTOK * DM];
__device__ int   g_offs[BATCH + 1];
__device__ float g_bq4 [2 * NQ];
__device__ float g_bkv4[2 * NKV];

__device__ __nv_bfloat16 g_Qb4[2 * NTOK * NQ];     // bf16 Q, row stride 1024
__device__ __nv_bfloat16 g_KB4[2 * NTOK * NQ];     // bf16 K, [src][row][half*512+sub]
__device__ float         g_VF4[2 * NTOK * NQ];     // f32  V, same layout

__device__ __nv_bfloat16 g_visb  [NTOK * DM];
__device__ __nv_bfloat16 g_txtb  [NTOK * DM];
__device__ __nv_bfloat16 g_ctxb4 [4 * NTOK * DM];
__device__ __nv_bfloat16 g_out1b4[4 * NTOK * DM];
__device__ __nv_bfloat16 g_hb4   [4 * NTOK * DI];

__device__ __nv_bfloat16 g_WqT4 [2 * NQ * DM];
__device__ __nv_bfloat16 g_WkvT4[2 * NKV * DM];
__device__ __nv_bfloat16 g_WoT  [4 * DM * DM];
__device__ __nv_bfloat16 g_W1T  [4 * DI * DM];
__device__ __nv_bfloat16 g_W2T  [4 * DM * DI];

// ================= helpers =================
__device__ __forceinline__ uint32_t smem_u32(const void* p) {
    uint32_t a;
    asm("{ .reg .u64 t; cvta.to.shared.u64 t, %1; cvt.u32.u64 %0, t; }" : "=r"(a) : "l"(p));
    return a;
}
__device__ __forceinline__ void cp_async16(uint32_t dst, const void* src) {
    asm volatile("cp.async.cg.shared.global [%0], [%1], 16;" :: "r"(dst), "l"(src));
}
#define CP_COMMIT() asm volatile("cp.async.commit_group;" ::: "memory")
#define CP_WAIT(n)  asm volatile("cp.async.wait_group %0;" :: "n"(n) : "memory")

__device__ __forceinline__ void ldmatrix_x4(uint32_t& r0, uint32_t& r1, uint32_t& r2, uint32_t& r3, uint32_t addr) {
    asm volatile("ldmatrix.sync.aligned.m8n8.x4.shared.b16 {%0,%1,%2,%3}, [%4];"
        : "=r"(r0), "=r"(r1), "=r"(r2), "=r"(r3) : "r"(addr));
}
__device__ __forceinline__ void mma_bf16(float* d, const uint32_t* a, const uint32_t* b) {
    asm volatile("mma.sync.aligned.m16n8k16.row.col.f32.bf16.bf16.f32 "
        "{%0,%1,%2,%3}, {%4,%5,%6,%7}, {%8,%9}, {%0,%1,%2,%3};"
        : "+f"(d[0]), "+f"(d[1]), "+f"(d[2]), "+f"(d[3])
        : "r"(a[0]), "r"(a[1]), "r"(a[2]), "r"(a[3]), "r"(b[0]), "r"(b[1]));
}
__device__ __forceinline__ u64 q_at(const ulong4& q, int z) {
    u64 v;
    switch (z) { case 0: v = q.x; break; case 1: v = q.y; break;
                 case 2: v = q.z; break; default: v = q.w; }
    return v;
}
__device__ __forceinline__ void bf8_to_f8(uint4 u, float* dst) {
    float2 f;
    f = __bfloat1622float2(*reinterpret_cast<const __nv_bfloat162*>(&u.x)); dst[0] = f.x; dst[1] = f.y;
    f = __bfloat1622float2(*reinterpret_cast<const __nv_bfloat162*>(&u.y)); dst[2] = f.x; dst[3] = f.y;
    f = __bfloat1622float2(*reinterpret_cast<const __nv_bfloat162*>(&u.z)); dst[4] = f.x; dst[5] = f.y;
    f = __bfloat1622float2(*reinterpret_cast<const __nv_bfloat162*>(&u.w)); dst[6] = f.x; dst[7] = f.y;
}

// ---- packed f32x2 (sm_100+) ----
#define FMA2(d, a, b, c) asm("fma.rn.f32x2 %0, %1, %2, %3;" : "=l"(d) : "l"(a), "l"(b), "l"(c))
#define MUL2(d, a, b)    asm("mul.rn.f32x2 %0, %1, %2;" : "=l"(d) : "l"(a), "l"(b))
__device__ __forceinline__ u64 pack2(float lo, float hi) {
    u64 r; asm("mov.b64 %0, {%1, %2};" : "=l"(r) : "f"(lo), "f"(hi)); return r;
}
__device__ __forceinline__ void unpack2(u64 v, float& lo, float& hi) {
    asm("mov.b64 {%0, %1}, %2;" : "=f"(lo), "=f"(hi) : "l"(v));
}

// ================= fused prepass: cvt(vis,txt) + bias concat + offsets =================
#define NC4 (NTOK * DM / 4)
__global__ __launch_bounds__(256) void prepass_kernel(
    const float* __restrict__ Vsrc, const float* __restrict__ Tsrc,
    const float* __restrict__ bq, const float* __restrict__ bk, const float* __restrict__ bv,
    const int* __restrict__ nobj)
{
    int bid = blockIdx.x;
    if (bid < 13320) {
        int i = bid * 256 + threadIdx.x;
        const float* X; __nv_bfloat16* Y; int j;
        if (i < NC4) { X = Vsrc; Y = g_visb; j = i; }
        else { X = Tsrc; Y = g_txtb; j = i - NC4; }
        float4 v = ((const float4*)X)[j];
        __nv_bfloat162 a, b;
        a.x = __float2bfloat16_rn(v.x); a.y = __float2bfloat16_rn(v.y);
        b.x = __float2bfloat16_rn(v.z); b.y = __float2bfloat16_rn(v.w);
        ((__nv_bfloat162*)Y)[j * 2 + 0] = a;
        ((__nv_bfloat162*)Y)[j * 2 + 1] = b;
    } else if (bid < 13344) {
        int i = (bid - 13320) * 256 + threadIdx.x;
        if (i < 2 * NQ) {
            int src = i >> 10, half = (i >> 9) & 1, j = i & 511;
            int p = src + 2 * half;
            g_bq4[i] = bq[p * DM + j];
        } else if (i < 2 * NQ + 2 * NKV) {
            int k = i - 2 * NQ;
            int src = k >> 11, r = k & 2047;
            int half = r >> 10, part = (r >> 9) & 1, j = r & 511;
            const int pt[2][2] = { {0, 3}, {2, 1} };
            int p = pt[src][half];
            g_bkv4[k] = (part ? bv : bk)[p * DM + j];
        }
    } else {
        if (threadIdx.x == 0) {
            int s = 0;
            for (int i = 0; i < BATCH; i++) { g_offs[i] = s; s += nobj[i]; }
            g_offs[BATCH] = s;
        }
    }
}

// ================= one-launch transpose of all 24 weight blocks =================
struct TT { u64 src[24]; u64 dst[24]; };
__global__ __launch_bounds__(256) void transpose_all_kernel(TT tt) {
    int bid = blockIdx.x;
    int e, t, R, C;
    if (bid < 4096)      { e = bid >> 8, t = bid & 255;  R = 512;  C = 512;  }
    else if (bid < 8192) { e = 16 + ((bid - 4096) >> 10); t = (bid - 4096) & 1023; R = 512;  C = 2048; }
    else                 { e = 20 + ((bid - 8192) >> 10); t = (bid - 8192) & 1023; R = 2048; C = 512;  }
    const float* Sp = (const float*)tt.src[e];
    __nv_bfloat16* Dp = (__nv_bfloat16*)tt.dst[e];
    int tpr = C >> 5;
    int bx = (t % tpr) * 32, by = (t / tpr) * 32;

    __shared__ float tile[32][33];
    int x = bx + threadIdx.x;
#pragma unroll
    for (int yy = threadIdx.y; yy < 32; yy += 8)
        tile[yy][threadIdx.x] = Sp[(size_t)(by + yy) * C + x];
    __syncthreads();
    int x2 = by + threadIdx.x;
#pragma unroll
    for (int yy = threadIdx.y; yy < 32; yy += 8)
        Dp[(size_t)(bx + yy) * R + x2] = __float2bfloat16_rn(tile[threadIdx.x][yy]);
}

// ======== bf16 mma.sync GEMM, 128x128 tile, BK=64, 3-stage, z-batched ========
#define LDSH 72                            // 64 halves + 8 pad
#define TILEB (128 * LDSH * 2)             // 18432
#define STAGEB (2 * TILEB)                 // 36864
#define NSTAGE 3
#define GEMM_SMEM (NSTAGE * STAGEB)        // 110592

template <bool RELU, bool RESID, bool OF32, bool OBF16, bool OSPLIT>
__global__ __launch_bounds__(256, 2) void gemm_bf16_k(
    ulong4 Aq, ulong4 Btq, ulong4 biasq, ulong4 Rq,
    float* __restrict__ C, size_t cStr, __nv_bfloat16* __restrict__ Cb, size_t cbStr,
    int M, int K, int N)
{
    extern __shared__ char smem[];
    const uint32_t sb = smem_u32(smem);
    const int tid = threadIdx.x;
    const int lane = tid & 31;
    const int wid = tid >> 5;
    const int z = blockIdx.z;
    const int m0 = blockIdx.y * 128;
    const int n0 = blockIdx.x * 128;
    const int warp_m = wid & 1;
    const int warp_n = wid >> 1;

    const __nv_bfloat16* A  = (const __nv_bfloat16*)q_at(Aq, z);
    const __nv_bfloat16* Bt = (const __nv_bfloat16*)q_at(Btq, z);
    const float* bias = (const float*)q_at(biasq, z);
    const float* R = RESID ? (const float*)q_at(Rq, z) : nullptr;
    if (OF32 || OSPLIT)  C  += (size_t)z * cStr;
    if (OBF16 || OSPLIT) Cb += (size_t)z * cbStr;

    float acc[4][4][4];
#pragma unroll
    for (int i = 0; i < 4; i++)
#pragma unroll
        for (int j = 0; j < 4; j++)
#pragma unroll
            for (int r = 0; r < 4; r++) acc[i][j][r] = 0.f;

    // hoisted per-thread load addressing (k-invariant)
    const __nv_bfloat16* aptr[4];
    const __nv_bfloat16* bptr[4];
    uint32_t adst[4], bdst[4];
#pragma unroll
    for (int i = 0; i < 4; i++) {
        int c = tid + i * 256;
        int row = c >> 3, c16 = c & 7;
        int gr = m0 + row; gr = gr < M ? gr : M - 1;
        aptr[i] = A + (size_t)gr * K + c16 * 8;
        bptr[i] = Bt + (size_t)(n0 + row) * K + c16 * 8;
        adst[i] = row * (LDSH * 2) + c16 * 16;
        bdst[i] = TILEB + row * (LDSH * 2) + c16 * 16;
    }

    const int lmrow  = lane & 15;
    const int lmbyte = (lane >> 4) * 16;
    const int KT = K >> 6;               // BK=64

    auto load_stage_at = [&](uint32_t base, int k0) {
#pragma unroll
        for (int i = 0; i < 4; i++)
            cp_async16(base + adst[i], aptr[i] + k0);
#pragma unroll
        for (int i = 0; i < 4; i++)
            cp_async16(base + bdst[i], bptr[i] + k0);
        CP_COMMIT();
    };

    load_stage_at(sb, 0);
    load_stage_at(sb + STAGEB, 64);

    uint32_t cons = sb;                  // stage consumed this iteration
    uint32_t loadb = sb + 2 * STAGEB;    // stage to fill this iteration (it+2)

#pragma unroll 1
    for (int it = 0; it < KT; it++) {
        CP_WAIT(NSTAGE - 2);
        __syncthreads();
        int nk = it + NSTAGE - 1;
        if (nk < KT) load_stage_at(loadb, nk << 6);
        else CP_COMMIT();

        const uint32_t ab = cons;
        const uint32_t bb = cons + TILEB;

#pragma unroll
        for (int kk = 0; kk < 4; kk++) {
            uint32_t af[4][4];
#pragma unroll
            for (int mi = 0; mi < 4; mi++) {
                uint32_t addr = ab + (warp_m * 64 + mi * 16 + lmrow) * (LDSH * 2) + kk * 32 + lmbyte;
                ldmatrix_x4(af[mi][0], af[mi][1], af[mi][2], af[mi][3], addr);
            }
            uint32_t bf[4][2];
#pragma unroll
            for (int t = 0; t < 2; t++) {
                uint32_t addr = bb + (warp_n * 32 + t * 16 + lmrow) * (LDSH * 2) + kk * 32 + lmbyte;
                uint32_t r0, r1, r2, r3;
                ldmatrix_x4(r0, r1, r2, r3, addr);
                bf[t * 2 + 0][0] = r0; bf[t * 2 + 0][1] = r2;
                bf[t * 2 + 1][0] = r1; bf[t * 2 + 1][1] = r3;
            }
#pragma unroll
            for (int mi = 0; mi < 4; mi++)
#pragma unroll
                for (int nj = 0; nj < 4; nj++)
                    mma_bf16(acc[mi][nj], af[mi], bf[nj]);
        }

        loadb = cons;
        cons += STAGEB;
        if (cons == sb + NSTAGE * STAGEB) cons = sb;
    }

    const int er = lane >> 2;
    const int ec = (lane & 3) * 2;
#pragma unroll
    for (int mi = 0; mi < 4; mi++) {
#pragma unroll
        for (int half = 0; half < 2; half++) {
            int row = m0 + warp_m * 64 + mi * 16 + half * 8 + er;
            if (row >= M) continue;
#pragma unroll
            for (int nj = 0; nj < 4; nj++) {
                int col = n0 + warp_n * 32 + nj * 8 + ec;
                float2 v;
                v.x = acc[mi][nj][half * 2 + 0] + bias[col + 0];
                v.y = acc[mi][nj][half * 2 + 1] + bias[col + 1];
                if (RESID) {
                    const float2 rv = *(const float2*)(R + (size_t)row * N + col);
                    v.x += rv.x; v.y += rv.y;
                }
                if (RELU) { v.x = fmaxf(v.x, 0.f); v.y = fmaxf(v.y, 0.f); }
                if (OSPLIT) {
                    int colk = ((n0 >> 10) << 9) + (col & 511);
                    if ((n0 >> 9) & 1) {
                        *(float2*)(C + (size_t)row * 1024 + colk) = v;
                    } else {
                        __nv_bfloat162 h2;
                        h2.x = __float2bfloat16_rn(v.x);
                        h2.y = __float2bfloat16_rn(v.y);
                        *(__nv_bfloat162*)(Cb + (size_t)row * 1024 + colk) = h2;
                    }
                } else {
                    if (OF32)
                        *(float2*)(C + (size_t)row * N + col) = v;
                    if (OBF16) {
                        __nv_bfloat162 h2;
                        h2.x = __float2bfloat16_rn(v.x);
                        h2.y = __float2bfloat16_rn(v.y);
                        *(__nv_bfloat162*)(Cb + (size_t)row * N + col) = h2;
                    }
                }
            }
        }
    }
}

// ================= LN1 (z-batched, f32 + bf16 out) =================
__global__ __launch_bounds__(128) void ln1_kernel(
    const float* __restrict__ X, size_t xStr, ulong4 gq, ulong4 bq,
    float* __restrict__ out, size_t oStr, __nv_bfloat16* __restrict__ outb, size_t obStr)
{
    int row = blockIdx.x;
    int e = blockIdx.y;
    int tid = threadIdx.x;
    X += (size_t)e * xStr;
    out += (size_t)e * oStr;
    const float* g = (const float*)q_at(gq, e);
    const float* b = (const float*)q_at(bq, e);

    float4 v = ((const float4*)(X + (size_t)row * DM))[tid];
    __shared__ float sbuf[8];
    int wid = tid >> 5, lane = tid & 31;

    float s = v.x + v.y + v.z + v.w;
#pragma unroll
    for (int o = 16; o > 0; o >>= 1) s += __shfl_xor_sync(0xffffffffu, s, o);
    if (lane == 0) sbuf[wid] = s;
    __syncthreads();
    float mean = (sbuf[0] + sbuf[1] + sbuf[2] + sbuf[3]) * (1.0f / DM);
    __syncthreads();

    float dx0 = v.x - mean, dx1 = v.y - mean, dx2 = v.z - mean, dx3 = v.w - mean;
    float sq = dx0 * dx0 + dx1 * dx1 + dx2 * dx2 + dx3 * dx3;
#pragma unroll
    for (int o = 16; o > 0; o >>= 1) sq += __shfl_xor_sync(0xffffffffu, sq, o);
    if (lane == 0) sbuf[wid] = sq;
    __syncthreads();
    float var = (sbuf[0] + sbuf[1] + sbuf[2] + sbuf[3]) * (1.0f / DM);
    float rstd = rsqrtf(var + LNEPS);

    float4 gg = ((const float4*)g)[tid];
    float4 bb = ((const float4*)b)[tid];
    float4 y;
    y.x = dx0 * rstd * gg.x + bb.x;
    y.y = dx1 * rstd * gg.y + bb.y;
    y.z = dx2 * rstd * gg.z + bb.z;
    y.w = dx3 * rstd * gg.w + bb.w;

    ((float4*)(out + (size_t)row * DM))[tid] = y;
    __nv_bfloat16* ob = outb + (size_t)e * obStr + (size_t)row * DM;
    __nv_bfloat162 a, c;
    a.x = __float2bfloat16_rn(y.x); a.y = __float2bfloat16_rn(y.y);
    c.x = __float2bfloat16_rn(y.z); c.y = __float2bfloat16_rn(y.w);
    ((__nv_bfloat162*)ob)[tid * 2 + 0] = a;
    ((__nv_bfloat162*)ob)[tid * 2 + 1] = c;
}

// ============ LN2 pair + sum: out[p] = LN(T14[2p]) + LN(T14[2p+1]) ============
__global__ __launch_bounds__(128) void ln2_pair_kernel(
    const float* __restrict__ X, size_t xStr, ulong4 gq, ulong4 bq, float* __restrict__ out)
{
    int row = blockIdx.x;
    int p = blockIdx.y;
    int tid = threadIdx.x;
    int wid = tid >> 5, lane = tid & 31;

    const float* X0 = X + (size_t)(2 * p) * xStr + (size_t)row * DM;
    const float* X1 = X + (size_t)(2 * p + 1) * xStr + (size_t)row * DM;
    float4 v0 = ((const float4*)X0)[tid];
    float4 v1 = ((const float4*)X1)[tid];

    __shared__ float sbuf[16];
    float s0 = v0.x + v0.y + v0.z + v0.w;
    float s1 = v1.x + v1.y + v1.z + v1.w;
#pragma unroll
    for (int o = 16; o > 0; o >>= 1) {
        s0 += __shfl_xor_sync(0xffffffffu, s0, o);
        s1 += __shfl_xor_sync(0xffffffffu, s1, o);
    }
    if (lane == 0) { sbuf[wid] = s0; sbuf[8 + wid] = s1; }
    __syncthreads();
    float mean0 = (sbuf[0] + sbuf[1] + sbuf[2] + sbuf[3]) * (1.0f / DM);
    float mean1 = (sbuf[8] + sbuf[9] + sbuf[10] + sbuf[11]) * (1.0f / DM);
    __syncthreads();

    float a0 = v0.x - mean0, a1 = v0.y - mean0, a2 = v0.z - mean0, a3 = v0.w - mean0;
    float c0 = v1.x - mean1, c1 = v1.y - mean1, c2 = v1.z - mean1, c3 = v1.w - mean1;
    float q0 = a0 * a0 + a1 * a1 + a2 * a2 + a3 * a3;
    float q1 = c0 * c0 + c1 * c1 + c2 * c2 + c3 * c3;
#pragma unroll
    for (int o = 16; o > 0; o >>= 1) {
        q0 += __shfl_xor_sync(0xffffffffu, q0, o);
        q1 += __shfl_xor_sync(0xffffffffu, q1, o);
    }
    if (lane == 0) { sbuf[wid] = q0; sbuf[8 + wid] = q1; }
    __syncthreads();
    float rstd0 = rsqrtf((sbuf[0] + sbuf[1] + sbuf[2] + sbuf[3]) * (1.0f / DM) + LNEPS);
    float rstd1 = rsqrtf((sbuf[8] + sbuf[9] + sbuf[10] + sbuf[11]) * (1.0f / DM) + LNEPS);

    const float* g0 = (const float*)q_at(gq, 2 * p);
    const float* b0 = (const float*)q_at(bq, 2 * p);
    const float* g1 = (const float*)q_at(gq, 2 * p + 1);
    const float* b1 = (const float*)q_at(bq, 2 * p + 1);
    float4 gg0 = ((const float4*)g0)[tid], bb0 = ((const float4*)b0)[tid];
    float4 gg1 = ((const float4*)g1)[tid], bb1 = ((const float4*)b1)[tid];

    float4 y;
    y.x = (a0 * rstd0 * gg0.x + bb0.x) + (c0 * rstd1 * gg1.x + bb1.x);
    y.y = (a1 * rstd0 * gg0.y + bb0.y) + (c1 * rstd1 * gg1.y + bb1.y);
    y.z = (a2 * rstd0 * gg0.z + bb0.z) + (c2 * rstd1 * gg1.z + bb1.z);
    y.w = (a3 * rstd0 * gg0.w + bb0.w) + (c3 * rstd1 * gg1.w + bb1.w);

    ((float4*)(out + (size_t)p * NTOK * DM + (size_t)row * DM))[tid] = y;
}

// ================= segment attention (bf16 Q/K, fp32 V, f32x2 math) =================
__global__ __launch_bounds__(96) void attn_kernel()
{
    int s = blockIdx.x;
    int h = blockIdx.y;
    int e = blockIdx.z;
    int off = g_offs[s];
    int L = g_offs[s + 1] - off;

    const int srcQ = e >> 1, halfQ = e & 1;
    const int srcKV_t[4]  = {0, 1, 1, 0};
    const int halfKV_t[4] = {0, 0, 1, 1};
    const int srcKV = srcKV_t[e], halfKV = halfKV_t[e];

    const __nv_bfloat16* Qb = g_Qb4 + (size_t)srcQ  * NTOK * NQ + halfQ  * 512 + h * DKH;
    const __nv_bfloat16* Kb = g_KB4 + (size_t)srcKV * NTOK * NQ + halfKV * 512 + h * DKH;
    const float*         Vf = g_VF4 + (size_t)srcKV * NTOK * NQ + halfKV * 512 + h * DKH;

    __shared__ __align__(16) float Ks[95 * DKH];
    __shared__ __align__(16) float Vs[95 * DKH];
    for (int idx = threadIdx.x; idx < L * 16; idx += 96) {
        int j = idx >> 4, d4 = idx & 15;
        ((float4*)Vs)[j * 16 + d4] = ((const float4*)(Vf + (size_t)(off + j) * NQ))[d4];
    }
    for (int idx = threadIdx.x; idx < L * 8; idx += 96) {
        int j = idx >> 3, c = idx & 7;
        uint4 u = ((const uint4*)(Kb + (size_t)(off + j) * NQ))[c];
        bf8_to_f8(u, &Ks[j * DKH + c * 8]);
    }
    __syncthreads();

    int i = threadIdx.x;
    if (i >= L) return;

    // q packed as 32 f32x2 registers
    u64 q2[32];
    {
        const uint4* qp = (const uint4*)(Qb + (size_t)(off + i) * NQ);
#pragma unroll
        for (int t = 0; t < 8; t++) {
            uint4 u = qp[t];
            float2 f;
            f = __bfloat1622float2(*reinterpret_cast<const __nv_bfloat162*>(&u.x)); q2[t * 4 + 0] = pack2(f.x, f.y);
            f = __bfloat1622float2(*reinterpret_cast<const __nv_bfloat162*>(&u.y)); q2[t * 4 + 1] = pack2(f.x, f.y);
            f = __bfloat1622float2(*reinterpret_cast<const __nv_bfloat162*>(&u.z)); q2[t * 4 + 2] = pack2(f.x, f.y);
            f = __bfloat1622float2(*reinterpret_cast<const __nv_bfloat162*>(&u.w)); q2[t * 4 + 3] = pack2(f.x, f.y);
        }
    }

    float m = -INFINITY, l = 0.f;
    u64 acc2[32];
#pragma unroll
    for (int d = 0; d < 32; d++) acc2[d] = 0ull;

    for (int j0 = 0; j0 < L; j0 += 8) {
        int nj = L - j0; if (nj > 8) nj = 8;
        float sc[8];
#pragma unroll
        for (int jj = 0; jj < 8; jj++) {
            if (jj < nj) {
                const ulonglong2* kr = (const ulonglong2*)&Ks[(j0 + jj) * DKH];
                u64 sa = 0ull, sbp = 0ull;
#pragma unroll
                for (int t = 0; t < 16; t++) {
                    ulonglong2 kk = kr[t];
                    FMA2(sa, q2[2 * t + 0], kk.x, sa);
                    FMA2(sbp, q2[2 * t + 1], kk.y, sbp);
                }
                float a0, a1, b0, b1;
                unpack2(sa, a0, a1);
                unpack2(sbp, b0, b1);
                sc[jj] = ((a0 + a1) + (b0 + b1)) * 0.125f;
            } else sc[jj] = -INFINITY;
        }
        float cm = sc[0];
#pragma unroll
        for (int jj = 1; jj < 8; jj++) cm = fmaxf(cm, sc[jj]);
        float mn = fmaxf(m, cm);
        float corr = __expf(m - mn);
        l *= corr;
        u64 corr2 = pack2(corr, corr);
#pragma unroll
        for (int d = 0; d < 32; d++) MUL2(acc2[d], acc2[d], corr2);
#pragma unroll
        for (int jj = 0; jj < 8; jj++) {
            if (jj < nj) {
                float p = __expf(sc[jj] - mn);
                l += p;
                u64 p2 = pack2(p, p);
                const ulonglong2* vr = (const ulonglong2*)&Vs[(j0 + jj) * DKH];
#pragma unroll
                for (int t = 0; t < 16; t++) {
                    ulonglong2 vv = vr[t];
                    FMA2(acc2[2 * t + 0], p2, vv.x, acc2[2 * t + 0]);
                    FMA2(acc2[2 * t + 1], p2, vv.y, acc2[2 * t + 1]);
                }
            }
        }
        m = mn;
    }

    float inv = 1.0f / l;
    __nv_bfloat162* o = (__nv_bfloat162*)(g_ctxb4 + (size_t)e * NTOK * DM + (size_t)(off + i) * DM + h * DKH);
#pragma unroll
    for (int t = 0; t < 32; t++) {
        float lo, hi;
        unpack2(acc2[t], lo, hi);
        __nv_bfloat162 h2;
        h2.x = __float2bfloat16_rn(lo * inv);
        h2.y = __float2bfloat16_rn(hi * inv);
        o[t] = h2;
    }
}

// ================= host =================
extern "C" void kernel_launch(void* const* d_in, const int* in_sizes, int n_in,
                              void* d_out, int out_size)
{
    const float* vis  = (const float*)d_in[0];
    const float* txt  = (const float*)d_in[1];
    const float* Wq   = (const float*)d_in[2];
    const float* bq   = (const float*)d_in[3];
    const float* Wk   = (const float*)d_in[4];
    const float* bk   = (const float*)d_in[5];
    const float* Wv   = (const float*)d_in[6];
    const float* bv   = (const float*)d_in[7];
    const float* Wo   = (const float*)d_in[8];
    const float* bo   = (const float*)d_in[9];
    const float* g1   = (const float*)d_in[10];
    const float* be1  = (const float*)d_in[11];
    const float* W1   = (const float*)d_in[12];
    const float* b1   = (const float*)d_in[13];
    const float* W2   = (const float*)d_in[14];
    const float* b2   = (const float*)d_in[15];
    const float* g2   = (const float*)d_in[16];
    const float* be2  = (const float*)d_in[17];
    const int*   nobj = (const int*)d_in[18];
    float* out = (float*)d_out;

    float *T14, *OUT14, *BQ4, *BKV4, *VF4;
    __nv_bfloat16 *QB4, *KB4, *VISB, *TXTB, *CTXB4, *OUT1B4, *HB4;
    __nv_bfloat16 *WqT4, *WkvT4, *WoT, *W1T, *W2T;
    cudaGetSymbolAddress((void**)&T14, g_t14);
    cudaGetSymbolAddress((void**)&OUT14, g_out14);
    cudaGetSymbolAddress((void**)&BQ4, g_bq4);
    cudaGetSymbolAddress((void**)&BKV4, g_bkv4);
    cudaGetSymbolAddress((void**)&QB4, g_Qb4);
    cudaGetSymbolAddress((void**)&KB4, g_KB4);
    cudaGetSymbolAddress((void**)&VF4, g_VF4);
    cudaGetSymbolAddress((void**)&VISB, g_visb);
    cudaGetSymbolAddress((void**)&TXTB, g_txtb);
    cudaGetSymbolAddress((void**)&CTXB4, g_ctxb4);
    cudaGetSymbolAddress((void**)&OUT1B4, g_out1b4);
    cudaGetSymbolAddress((void**)&HB4, g_hb4);
    cudaGetSymbolAddress((void**)&WqT4, g_WqT4);
    cudaGetSymbolAddress((void**)&WkvT4, g_WkvT4);
    cudaGetSymbolAddress((void**)&WoT, g_WoT);
    cudaGetSymbolAddress((void**)&W1T, g_W1T);
    cudaGetSymbolAddress((void**)&W2T, g_W2T);

    cudaFuncSetAttribute(gemm_bf16_k<false, false, false, true,  false>, cudaFuncAttributeMaxDynamicSharedMemorySize, GEMM_SMEM);
    cudaFuncSetAttribute(gemm_bf16_k<false, false, false, false, true >, cudaFuncAttributeMaxDynamicSharedMemorySize, GEMM_SMEM);
    cudaFuncSetAttribute(gemm_bf16_k<false, true,  true,  false, false>, cudaFuncAttributeMaxDynamicSharedMemorySize, GEMM_SMEM);
    cudaFuncSetAttribute(gemm_bf16_k<true,  false, false, true,  false>, cudaFuncAttributeMaxDynamicSharedMemorySize, GEMM_SMEM);

    auto U4 = [](const void* a, const void* b, const void* c, const void* d) {
        ulong4 u; u.x = (u64)a; u.y = (u64)b; u.z = (u64)c; u.w = (u64)d; return u;
    };

    // 0: fused prepass
    prepass_kernel<<<13345, 256>>>(vis, txt, bq, bk, bv, nobj);

    // 1: weight transposes
    {
        TT tt;
        const size_t BLK = (size_t)DM * DM;
        const u64 qoff[4] = {0, 2 * BLK, BLK, 3 * BLK};
        const u64 koff[4] = {0, 6 * BLK, 4 * BLK, 2 * BLK};
        const u64 voff[4] = {BLK, 7 * BLK, 5 * BLK, 3 * BLK};
        for (int p = 0; p < 4; p++) {
            tt.src[p]      = (u64)(Wq + (size_t)p * BLK); tt.dst[p]      = (u64)(WqT4 + qoff[p]);
            tt.src[4 + p]  = (u64)(Wk + (size_t)p * BLK); tt.dst[4 + p]  = (u64)(WkvT4 + koff[p]);
            tt.src[8 + p]  = (u64)(Wv + (size_t)p * BLK); tt.dst[8 + p]  = (u64)(WkvT4 + voff[p]);
            tt.src[12 + p] = (u64)(Wo + (size_t)p * BLK); tt.dst[12 + p] = (u64)(WoT + (size_t)p * BLK);
            tt.src[16 + p] = (u64)(W1 + (size_t)p * DM * DI); tt.dst[16 + p] = (u64)(W1T + (size_t)p * DI * DM);
            tt.src[20 + p] = (u64)(W2 + (size_t)p * DI * DM); tt.dst[20 + p] = (u64)(W2T + (size_t)p * DM * DI);
        }
        transpose_all_kernel<<<12288, dim3(32, 8)>>>(tt);
    }

    const int MT = (NTOK + 127) / 128;    // 105
    const size_t SL = (size_t)NTOK * DM;
    const int perm[4] = {0, 2, 1, 3};
    ulong4 nullq; nullq.x = nullq.y = nullq.z = nullq.w = 0;

    // 2: Q GEMM (bf16 out)
    {
        ulong4 Aq = U4(VISB, TXTB, VISB, TXTB);
        ulong4 Bq = U4(WqT4, WqT4 + (size_t)NQ * DM, nullptr, nullptr);
        ulong4 bq_ = U4(BQ4, BQ4 + NQ, nullptr, nullptr);
        gemm_bf16_k<false, false, false, true, false><<<dim3(NQ / 128, MT, 2), 256, GEMM_SMEM>>>(
            Aq, Bq, bq_, nullq, nullptr, 0, QB4, (size_t)NTOK * NQ, NTOK, DM, NQ);
    }
    // 3: KV GEMM (split K bf16 / V f32)
    {
        ulong4 Aq = U4(VISB, TXTB, VISB, TXTB);
        ulong4 Bkv = U4(WkvT4, WkvT4 + (size_t)NKV * DM, nullptr, nullptr);
        ulong4 bkv_ = U4(BKV4, BKV4 + NKV, nullptr, nullptr);
        gemm_bf16_k<false, false, false, false, true><<<dim3(NKV / 128, MT, 2), 256, GEMM_SMEM>>>(
            Aq, Bkv, bkv_, nullq, VF4, (size_t)NTOK * NQ, KB4, (size_t)NTOK * NQ, NTOK, DM, NKV);
    }

    // 4: attention
    attn_kernel<<<dim3(BATCH, NH, 4), 96>>>();

    // 5: proj + residual
    {
        const size_t BLK = (size_t)DM * DM;
        ulong4 Aq = U4(CTXB4, CTXB4 + SL, CTXB4 + 2 * SL, CTXB4 + 3 * SL);
        ulong4 Bq = U4(WoT + perm[0] * BLK, WoT + perm[1] * BLK, WoT + perm[2] * BLK, WoT + perm[3] * BLK);
        ulong4 bq_ = U4(bo + perm[0] * DM, bo + perm[1] * DM, bo + perm[2] * DM, bo + perm[3] * DM);
        ulong4 Rq = U4(vis, vis, txt, txt);
        gemm_bf16_k<false, true, true, false, false><<<dim3(DM / 128, MT, 4), 256, GEMM_SMEM>>>(
            Aq, Bq, bq_, Rq, T14, SL, nullptr, 0, NTOK, DM, DM);
    }
    // 6: LN1
    {
        ulong4 gq = U4(g1 + perm[0] * DM, g1 + perm[1] * DM, g1 + perm[2] * DM, g1 + perm[3] * DM);
        ulong4 bq_ = U4(be1 + perm[0] * DM, be1 + perm[1] * DM, be1 + perm[2] * DM, be1 + perm[3] * DM);
        ln1_kernel<<<dim3(NTOK, 4), 128>>>(T14, SL, gq, bq_, OUT14, SL, OUT1B4, SL);
    }
    // 7: FFN1
    {
        ulong4 Aq = U4(OUT1B4, OUT1B4 + SL, OUT1B4 + 2 * SL, OUT1B4 + 3 * SL);
        const size_t WB = (size_t)DI * DM;
        ulong4 Bq = U4(W1T + perm[0] * WB, W1T + perm[1] * WB, W1T + perm[2] * WB, W1T + perm[3] * WB);
        ulong4 bq_ = U4(b1 + perm[0] * DI, b1 + perm[1] * DI, b1 + perm[2] * DI, b1 + perm[3] * DI);
        gemm_bf16_k<true, false, false, true, false><<<dim3(DI / 128, MT, 4), 256, GEMM_SMEM>>>(
            Aq, Bq, bq_, nullq, nullptr, 0, HB4, (size_t)NTOK * DI, NTOK, DM, DI);
    }
    // 8: FFN2 + residual
    {
        const size_t HL = (size_t)NTOK * DI;
        ulong4 Aq = U4(HB4, HB4 + HL, HB4 + 2 * HL, HB4 + 3 * HL);
        const size_t WB = (size_t)DM * DI;
        ulong4 Bq = U4(W2T + perm[0] * WB, W2T + perm[1] * WB, W2T + perm[2] * WB, W2T + perm[3] * WB);
        ulong4 bq_ = U4(b2 + perm[0] * DM, b2 + perm[1] * DM, b2 + perm[2] * DM, b2 + perm[3] * DM);
        ulong4 Rq = U4(OUT14, OUT14 + SL, OUT14 + 2 * SL, OUT14 + 3 * SL);
        gemm_bf16_k<false, true, true, false, false><<<dim3(DM / 128, MT, 4), 256, GEMM_SMEM>>>(
            Aq, Bq, bq_, Rq, T14, SL, nullptr, 0, NTOK, DI, DM);
    }
    // 9: LN2 + sum -> d_out
    {
        ulong4 gq = U4(g2 + perm[0] * DM, g2 + perm[1] * DM, g2 + perm[2] * DM, g2 + perm[3] * DM);
        ulong4 bq_ = U4(be2 + perm[0] * DM, be2 + perm[1] * DM, be2 + perm[2] * DM, be2 + perm[3] * DM);
        ln2_pair_kernel<<<dim3(NTOK, 2), 128>>>(T14, SL, gq, bq_, out);
    }
}

// round 11
// speedup vs baseline: 1.0208x; 1.0208x over previous
#include <cuda_runtime.h>
#include <cuda_bf16.h>
#include <math.h>
#include <stdint.h>

#define NTOK 13320
#define BATCH 240
#define DM 512
#define DI 2048
#define NH 8
#define DKH 64
#define LNEPS 1e-5f
#define NQ 1024
#define NKV 2048

typedef unsigned long long u64;

// ================= scratch (static device globals; no allocation) =================
__device__ float g_t14  [4 * NTOK * DM];
__device__ float g_out14[4 * NTOK * DM];
__device__ int   g_offs[BATCH + 1];
__device__ float g_bq4 [2 * NQ];
__device__ float g_bkv4[2 * NKV];

__device__ __nv_bfloat16 g_Qb4[2 * NTOK * NQ];     // bf16 Q, row stride 1024
__device__ __nv_bfloat16 g_KB4[2 * NTOK * NQ];     // bf16 K, [src][row][half*512+sub]
__device__ float         g_VF4[2 * NTOK * NQ];     // f32  V, same layout

__device__ __nv_bfloat16 g_visb  [NTOK * DM];
__device__ __nv_bfloat16 g_txtb  [NTOK * DM];
__device__ __nv_bfloat16 g_ctxb4 [4 * NTOK * DM];
__device__ __nv_bfloat16 g_out1b4[4 * NTOK * DM];
__device__ __nv_bfloat16 g_hb4   [4 * NTOK * DI];

__device__ __nv_bfloat16 g_WqT4 [2 * NQ * DM];
__device__ __nv_bfloat16 g_WkvT4[2 * NKV * DM];
__device__ __nv_bfloat16 g_WoT  [4 * DM * DM];
__device__ __nv_bfloat16 g_W1T  [4 * DI * DM];
__device__ __nv_bfloat16 g_W2T  [4 * DM * DI];

// ================= helpers =================
__device__ __forceinline__ uint32_t smem_u32(const void* p) {
    uint32_t a;
    asm("{ .reg .u64 t; cvta.to.shared.u64 t, %1; cvt.u32.u64 %0, t; }" : "=r"(a) : "l"(p));
    return a;
}
__device__ __forceinline__ void cp_async16(uint32_t dst, const void* src) {
    asm volatile("cp.async.cg.shared.global [%0], [%1], 16;" :: "r"(dst), "l"(src));
}
#define CP_COMMIT() asm volatile("cp.async.commit_group;" ::: "memory")
#define CP_WAIT(n)  asm volatile("cp.async.wait_group %0;" :: "n"(n) : "memory")

__device__ __forceinline__ void ldmatrix_x4(uint32_t& r0, uint32_t& r1, uint32_t& r2, uint32_t& r3, uint32_t addr) {
    asm volatile("ldmatrix.sync.aligned.m8n8.x4.shared.b16 {%0,%1,%2,%3}, [%4];"
        : "=r"(r0), "=r"(r1), "=r"(r2), "=r"(r3) : "r"(addr));
}
__device__ __forceinline__ void mma_bf16(float* d, const uint32_t* a, const uint32_t* b) {
    asm volatile("mma.sync.aligned.m16n8k16.row.col.f32.bf16.bf16.f32 "
        "{%0,%1,%2,%3}, {%4,%5,%6,%7}, {%8,%9}, {%0,%1,%2,%3};"
        : "+f"(d[0]), "+f"(d[1]), "+f"(d[2]), "+f"(d[3])
        : "r"(a[0]), "r"(a[1]), "r"(a[2]), "r"(a[3]), "r"(b[0]), "r"(b[1]));
}
__device__ __forceinline__ u64 q_at(const ulong4& q, int z) {
    u64 v;
    switch (z) { case 0: v = q.x; break; case 1: v = q.y; break;
                 case 2: v = q.z; break; default: v = q.w; }
    return v;
}
__device__ __forceinline__ void bf8_to_f8(uint4 u, float* dst) {
    float2 f;
    f = __bfloat1622float2(*reinterpret_cast<const __nv_bfloat162*>(&u.x)); dst[0] = f.x; dst[1] = f.y;
    f = __bfloat1622float2(*reinterpret_cast<const __nv_bfloat162*>(&u.y)); dst[2] = f.x; dst[3] = f.y;
    f = __bfloat1622float2(*reinterpret_cast<const __nv_bfloat162*>(&u.z)); dst[4] = f.x; dst[5] = f.y;
    f = __bfloat1622float2(*reinterpret_cast<const __nv_bfloat162*>(&u.w)); dst[6] = f.x; dst[7] = f.y;
}

// ================= fused prepass: cvt(vis,txt) + bias concat + offsets =================
#define NC4 (NTOK * DM / 4)
__global__ __launch_bounds__(256) void prepass_kernel(
    const float* __restrict__ Vsrc, const float* __restrict__ Tsrc,
    const float* __restrict__ bq, const float* __restrict__ bk, const float* __restrict__ bv,
    const int* __restrict__ nobj)
{
    int bid = blockIdx.x;
    if (bid < 13320) {
        int i = bid * 256 + threadIdx.x;
        const float* X; __nv_bfloat16* Y; int j;
        if (i < NC4) { X = Vsrc; Y = g_visb; j = i; }
        else { X = Tsrc; Y = g_txtb; j = i - NC4; }
        float4 v = ((const float4*)X)[j];
        __nv_bfloat162 a, b;
        a.x = __float2bfloat16_rn(v.x); a.y = __float2bfloat16_rn(v.y);
        b.x = __float2bfloat16_rn(v.z); b.y = __float2bfloat16_rn(v.w);
        ((__nv_bfloat162*)Y)[j * 2 + 0] = a;
        ((__nv_bfloat162*)Y)[j * 2 + 1] = b;
    } else if (bid < 13344) {
        int i = (bid - 13320) * 256 + threadIdx.x;
        if (i < 2 * NQ) {
            int src = i >> 10, half = (i >> 9) & 1, j = i & 511;
            int p = src + 2 * half;
            g_bq4[i] = bq[p * DM + j];
        } else if (i < 2 * NQ + 2 * NKV) {
            int k = i - 2 * NQ;
            int src = k >> 11, r = k & 2047;
            int half = r >> 10, part = (r >> 9) & 1, j = r & 511;
            const int pt[2][2] = { {0, 3}, {2, 1} };
            int p = pt[src][half];
            g_bkv4[k] = (part ? bv : bk)[p * DM + j];
        }
    } else {
        if (threadIdx.x == 0) {
            int s = 0;
            for (int i = 0; i < BATCH; i++) { g_offs[i] = s; s += nobj[i]; }
            g_offs[BATCH] = s;
        }
    }
}

// ================= one-launch transpose of all 24 weight blocks =================
struct TT { u64 src[24]; u64 dst[24]; };
__global__ __launch_bounds__(256) void transpose_all_kernel(TT tt) {
    int bid = blockIdx.x;
    int e, t, R, C;
    if (bid < 4096)      { e = bid >> 8, t = bid & 255;  R = 512;  C = 512;  }
    else if (bid < 8192) { e = 16 + ((bid - 4096) >> 10); t = (bid - 4096) & 1023; R = 512;  C = 2048; }
    else                 { e = 20 + ((bid - 8192) >> 10); t = (bid - 8192) & 1023; R = 2048; C = 512;  }
    const float* Sp = (const float*)tt.src[e];
    __nv_bfloat16* Dp = (__nv_bfloat16*)tt.dst[e];
    int tpr = C >> 5;
    int bx = (t % tpr) * 32, by = (t / tpr) * 32;

    __shared__ float tile[32][33];
    int x = bx + threadIdx.x;
#pragma unroll
    for (int yy = threadIdx.y; yy < 32; yy += 8)
        tile[yy][threadIdx.x] = Sp[(size_t)(by + yy) * C + x];
    __syncthreads();
    int x2 = by + threadIdx.x;
#pragma unroll
    for (int yy = threadIdx.y; yy < 32; yy += 8)
        Dp[(size_t)(bx + yy) * R + x2] = __float2bfloat16_rn(tile[threadIdx.x][yy]);
}

// ======== bf16 mma.sync GEMM, 128x128 CTA tile, 4 warps of 64x64, BK=64, 3-stage ========
#define LDSH 72                            // 64 halves + 8 pad
#define TILEB (128 * LDSH * 2)             // 18432
#define STAGEB (2 * TILEB)                 // 36864
#define NSTAGE 3
#define GEMM_SMEM (NSTAGE * STAGEB)        // 110592

template <bool RELU, bool RESID, bool OF32, bool OBF16, bool OSPLIT>
__global__ __launch_bounds__(128, 2) void gemm_bf16_k(
    ulong4 Aq, ulong4 Btq, ulong4 biasq, ulong4 Rq,
    float* __restrict__ C, size_t cStr, __nv_bfloat16* __restrict__ Cb, size_t cbStr,
    int M, int K, int N)
{
    extern __shared__ char smem[];
    const uint32_t sb = smem_u32(smem);
    const int tid = threadIdx.x;
    const int lane = tid & 31;
    const int wid = tid >> 5;
    const int z = blockIdx.z;
    const int m0 = blockIdx.y * 128;
    const int n0 = blockIdx.x * 128;
    const int warp_m = wid & 1;          // 2 -> 64-row bands
    const int warp_n = wid >> 1;         // 2 -> 64-col bands

    const __nv_bfloat16* A  = (const __nv_bfloat16*)q_at(Aq, z);
    const __nv_bfloat16* Bt = (const __nv_bfloat16*)q_at(Btq, z);
    const float* bias = (const float*)q_at(biasq, z);
    const float* R = RESID ? (const float*)q_at(Rq, z) : nullptr;
    if (OF32 || OSPLIT)  C  += (size_t)z * cStr;
    if (OBF16 || OSPLIT) Cb += (size_t)z * cbStr;

    float acc[4][8][4];
#pragma unroll
    for (int i = 0; i < 4; i++)
#pragma unroll
        for (int j = 0; j < 8; j++)
#pragma unroll
            for (int r = 0; r < 4; r++) acc[i][j][r] = 0.f;

    const int lmrow  = lane & 15;
    const int lmbyte = (lane >> 4) * 16;
    const int KT = K >> 6;               // BK=64

    // 128 threads: 8 A-chunks + 8 B-chunks of 16B per thread per stage
    auto load_stage_at = [&](uint32_t base, int k0) {
#pragma unroll
        for (int i = 0; i < 8; i++) {
            int c = tid + i * 128;
            int row = c >> 3, c16 = c & 7;
            int gr = m0 + row; gr = gr < M ? gr : M - 1;
            cp_async16(base + row * (LDSH * 2) + c16 * 16,
                       A + (size_t)gr * K + k0 + c16 * 8);
        }
#pragma unroll
        for (int i = 0; i < 8; i++) {
            int c = tid + i * 128;
            int row = c >> 3, c16 = c & 7;
            cp_async16(base + TILEB + row * (LDSH * 2) + c16 * 16,
                       Bt + (size_t)(n0 + row) * K + k0 + c16 * 8);
        }
        CP_COMMIT();
    };

    load_stage_at(sb, 0);
    load_stage_at(sb + STAGEB, 64);

    uint32_t cons = sb;
    uint32_t loadb = sb + 2 * STAGEB;

#pragma unroll 1
    for (int it = 0; it < KT; it++) {
        CP_WAIT(NSTAGE - 2);
        __syncthreads();
        int nk = it + NSTAGE - 1;
        if (nk < KT) load_stage_at(loadb, nk << 6);
        else CP_COMMIT();

        const uint32_t ab = cons;
        const uint32_t bb = cons + TILEB;

#pragma unroll
        for (int kk = 0; kk < 4; kk++) {
            uint32_t af[4][4];
#pragma unroll
            for (int mi = 0; mi < 4; mi++) {
                uint32_t addr = ab + (warp_m * 64 + mi * 16 + lmrow) * (LDSH * 2) + kk * 32 + lmbyte;
                ldmatrix_x4(af[mi][0], af[mi][1], af[mi][2], af[mi][3], addr);
            }
            uint32_t bf[8][2];
#pragma unroll
            for (int t = 0; t < 4; t++) {
                uint32_t addr = bb + (warp_n * 64 + t * 16 + lmrow) * (LDSH * 2) + kk * 32 + lmbyte;
                uint32_t r0, r1, r2, r3;
                ldmatrix_x4(r0, r1, r2, r3, addr);
                bf[t * 2 + 0][0] = r0; bf[t * 2 + 0][1] = r2;
                bf[t * 2 + 1][0] = r1; bf[t * 2 + 1][1] = r3;
            }
#pragma unroll
            for (int mi = 0; mi < 4; mi++)
#pragma unroll
                for (int nj = 0; nj < 8; nj++)
                    mma_bf16(acc[mi][nj], af[mi], bf[nj]);
        }

        loadb = cons;
        cons += STAGEB;
        if (cons == sb + NSTAGE * STAGEB) cons = sb;
    }

    const int er = lane >> 2;
    const int ec = (lane & 3) * 2;
#pragma unroll
    for (int mi = 0; mi < 4; mi++) {
#pragma unroll
        for (int half = 0; half < 2; half++) {
            int row = m0 + warp_m * 64 + mi * 16 + half * 8 + er;
            if (row >= M) continue;
#pragma unroll
            for (int nj = 0; nj < 8; nj++) {
                int col = n0 + warp_n * 64 + nj * 8 + ec;
                float2 v;
                v.x = acc[mi][nj][half * 2 + 0] + bias[col + 0];
                v.y = acc[mi][nj][half * 2 + 1] + bias[col + 1];
                if (RESID) {
                    const float2 rv = *(const float2*)(R + (size_t)row * N + col);
                    v.x += rv.x; v.y += rv.y;
                }
                if (RELU) { v.x = fmaxf(v.x, 0.f); v.y = fmaxf(v.y, 0.f); }
                if (OSPLIT) {
                    int colk = ((n0 >> 10) << 9) + (col & 511);
                    if ((n0 >> 9) & 1) {
                        *(float2*)(C + (size_t)row * 1024 + colk) = v;
                    } else {
                        __nv_bfloat162 h2;
                        h2.x = __float2bfloat16_rn(v.x);
                        h2.y = __float2bfloat16_rn(v.y);
                        *(__nv_bfloat162*)(Cb + (size_t)row * 1024 + colk) = h2;
                    }
                } else {
                    if (OF32)
                        *(float2*)(C + (size_t)row * N + col) = v;
                    if (OBF16) {
                        __nv_bfloat162 h2;
                        h2.x = __float2bfloat16_rn(v.x);
                        h2.y = __float2bfloat16_rn(v.y);
                        *(__nv_bfloat162*)(Cb + (size_t)row * N + col) = h2;
                    }
                }
            }
        }
    }
}

// ================= LN1 (z-batched, f32 + bf16 out) =================
__global__ __launch_bounds__(128) void ln1_kernel(
    const float* __restrict__ X, size_t xStr, ulong4 gq, ulong4 bq,
    float* __restrict__ out, size_t oStr, __nv_bfloat16* __restrict__ outb, size_t obStr)
{
    int row = blockIdx.x;
    int e = blockIdx.y;
    int tid = threadIdx.x;
    X += (size_t)e * xStr;
    out += (size_t)e * oStr;
    const float* g = (const float*)q_at(gq, e);
    const float* b = (const float*)q_at(bq, e);

    float4 v = ((const float4*)(X + (size_t)row * DM))[tid];
    __shared__ float sbuf[8];
    int wid = tid >> 5, lane = tid & 31;

    float s = v.x + v.y + v.z + v.w;
#pragma unroll
    for (int o = 16; o > 0; o >>= 1) s += __shfl_xor_sync(0xffffffffu, s, o);
    if (lane == 0) sbuf[wid] = s;
    __syncthreads();
    float mean = (sbuf[0] + sbuf[1] + sbuf[2] + sbuf[3]) * (1.0f / DM);
    __syncthreads();

    float dx0 = v.x - mean, dx1 = v.y - mean, dx2 = v.z - mean, dx3 = v.w - mean;
    float sq = dx0 * dx0 + dx1 * dx1 + dx2 * dx2 + dx3 * dx3;
#pragma unroll
    for (int o = 16; o > 0; o >>= 1) sq += __shfl_xor_sync(0xffffffffu, sq, o);
    if (lane == 0) sbuf[wid] = sq;
    __syncthreads();
    float var = (sbuf[0] + sbuf[1] + sbuf[2] + sbuf[3]) * (1.0f / DM);
    float rstd = rsqrtf(var + LNEPS);

    float4 gg = ((const float4*)g)[tid];
    float4 bb = ((const float4*)b)[tid];
    float4 y;
    y.x = dx0 * rstd * gg.x + bb.x;
    y.y = dx1 * rstd * gg.y + bb.y;
    y.z = dx2 * rstd * gg.z + bb.z;
    y.w = dx3 * rstd * gg.w + bb.w;

    ((float4*)(out + (size_t)row * DM))[tid] = y;
    __nv_bfloat16* ob = outb + (size_t)e * obStr + (size_t)row * DM;
    __nv_bfloat162 a, c;
    a.x = __float2bfloat16_rn(y.x); a.y = __float2bfloat16_rn(y.y);
    c.x = __float2bfloat16_rn(y.z); c.y = __float2bfloat16_rn(y.w);
    ((__nv_bfloat162*)ob)[tid * 2 + 0] = a;
    ((__nv_bfloat162*)ob)[tid * 2 + 1] = c;
}

// ============ LN2 pair + sum: out[p] = LN(T14[2p]) + LN(T14[2p+1]) ============
__global__ __launch_bounds__(128) void ln2_pair_kernel(
    const float* __restrict__ X, size_t xStr, ulong4 gq, ulong4 bq, float* __restrict__ out)
{
    int row = blockIdx.x;
    int p = blockIdx.y;
    int tid = threadIdx.x;
    int wid = tid >> 5, lane = tid & 31;

    const float* X0 = X + (size_t)(2 * p) * xStr + (size_t)row * DM;
    const float* X1 = X + (size_t)(2 * p + 1) * xStr + (size_t)row * DM;
    float4 v0 = ((const float4*)X0)[tid];
    float4 v1 = ((const float4*)X1)[tid];

    __shared__ float sbuf[16];
    float s0 = v0.x + v0.y + v0.z + v0.w;
    float s1 = v1.x + v1.y + v1.z + v1.w;
#pragma unroll
    for (int o = 16; o > 0; o >>= 1) {
        s0 += __shfl_xor_sync(0xffffffffu, s0, o);
        s1 += __shfl_xor_sync(0xffffffffu, s1, o);
    }
    if (lane == 0) { sbuf[wid] = s0; sbuf[8 + wid] = s1; }
    __syncthreads();
    float mean0 = (sbuf[0] + sbuf[1] + sbuf[2] + sbuf[3]) * (1.0f / DM);
    float mean1 = (sbuf[8] + sbuf[9] + sbuf[10] + sbuf[11]) * (1.0f / DM);
    __syncthreads();

    float a0 = v0.x - mean0, a1 = v0.y - mean0, a2 = v0.z - mean0, a3 = v0.w - mean0;
    float c0 = v1.x - mean1, c1 = v1.y - mean1, c2 = v1.z - mean1, c3 = v1.w - mean1;
    float q0 = a0 * a0 + a1 * a1 + a2 * a2 + a3 * a3;
    float q1 = c0 * c0 + c1 * c1 + c2 * c2 + c3 * c3;
#pragma unroll
    for (int o = 16; o > 0; o >>= 1) {
        q0 += __shfl_xor_sync(0xffffffffu, q0, o);
        q1 += __shfl_xor_sync(0xffffffffu, q1, o);
    }
    if (lane == 0) { sbuf[wid] = q0; sbuf[8 + wid] = q1; }
    __syncthreads();
    float rstd0 = rsqrtf((sbuf[0] + sbuf[1] + sbuf[2] + sbuf[3]) * (1.0f / DM) + LNEPS);
    float rstd1 = rsqrtf((sbuf[8] + sbuf[9] + sbuf[10] + sbuf[11]) * (1.0f / DM) + LNEPS);

    const float* g0 = (const float*)q_at(gq, 2 * p);
    const float* b0 = (const float*)q_at(bq, 2 * p);
    const float* g1 = (const float*)q_at(gq, 2 * p + 1);
    const float* b1 = (const float*)q_at(bq, 2 * p + 1);
    float4 gg0 = ((const float4*)g0)[tid], bb0 = ((const float4*)b0)[tid];
    float4 gg1 = ((const float4*)g1)[tid], bb1 = ((const float4*)b1)[tid];

    float4 y;
    y.x = (a0 * rstd0 * gg0.x + bb0.x) + (c0 * rstd1 * gg1.x + bb1.x);
    y.y = (a1 * rstd0 * gg0.y + bb0.y) + (c1 * rstd1 * gg1.y + bb1.y);
    y.z = (a2 * rstd0 * gg0.z + bb0.z) + (c2 * rstd1 * gg1.z + bb1.z);
    y.w = (a3 * rstd0 * gg0.w + bb0.w) + (c3 * rstd1 * gg1.w + bb1.w);

    ((float4*)(out + (size_t)p * NTOK * DM + (size_t)row * DM))[tid] = y;
}

// ================= segment attention (bf16 Q/K, fp32 V, scalar FMA) =================
__global__ __launch_bounds__(96) void attn_kernel()
{
    int s = blockIdx.x;
    int h = blockIdx.y;
    int e = blockIdx.z;
    int off = g_offs[s];
    int L = g_offs[s + 1] - off;

    const int srcQ = e >> 1, halfQ = e & 1;
    const int srcKV_t[4]  = {0, 1, 1, 0};
    const int halfKV_t[4] = {0, 0, 1, 1};
    const int srcKV = srcKV_t[e], halfKV = halfKV_t[e];

    const __nv_bfloat16* Qb = g_Qb4 + (size_t)srcQ  * NTOK * NQ + halfQ  * 512 + h * DKH;
    const __nv_bfloat16* Kb = g_KB4 + (size_t)srcKV * NTOK * NQ + halfKV * 512 + h * DKH;
    const float*         Vf = g_VF4 + (size_t)srcKV * NTOK * NQ + halfKV * 512 + h * DKH;

    __shared__ __align__(16) float Ks[95 * DKH];
    __shared__ __align__(16) float Vs[95 * DKH];
    for (int idx = threadIdx.x; idx < L * 16; idx += 96) {
        int j = idx >> 4, d4 = idx & 15;
        ((float4*)Vs)[j * 16 + d4] = ((const float4*)(Vf + (size_t)(off + j) * NQ))[d4];
    }
    for (int idx = threadIdx.x; idx < L * 8; idx += 96) {
        int j = idx >> 3, c = idx & 7;
        uint4 u = ((const uint4*)(Kb + (size_t)(off + j) * NQ))[c];
        bf8_to_f8(u, &Ks[j * DKH + c * 8]);
    }
    __syncthreads();

    int i = threadIdx.x;
    if (i >= L) return;

    float q[DKH];
    {
        const uint4* qp = (const uint4*)(Qb + (size_t)(off + i) * NQ);
#pragma unroll
        for (int t = 0; t < 8; t++) {
            uint4 u = qp[t];
            bf8_to_f8(u, &q[t * 8]);
        }
    }

    float m = -INFINITY, l = 0.f;
    float acc[DKH];
#pragma unroll
    for (int d = 0; d < DKH; d++) acc[d] = 0.f;

    for (int j0 = 0; j0 < L; j0 += 8) {
        int nj = L - j0; if (nj > 8) nj = 8;
        float sc[8];
#pragma unroll
        for (int jj = 0; jj < 8; jj++) {
            if (jj < nj) {
                const float4* kr = (const float4*)&Ks[(j0 + jj) * DKH];
                float sd = 0.f;
#pragma unroll
                for (int t = 0; t < 16; t++) {
                    float4 kv = kr[t];
                    sd = fmaf(q[4 * t + 0], kv.x, sd);
                    sd = fmaf(q[4 * t + 1], kv.y, sd);
                    sd = fmaf(q[4 * t + 2], kv.z, sd);
                    sd = fmaf(q[4 * t + 3], kv.w, sd);
                }
                sc[jj] = sd * 0.125f;
            } else sc[jj] = -INFINITY;
        }
        float cm = sc[0];
#pragma unroll
        for (int jj = 1; jj < 8; jj++) cm = fmaxf(cm, sc[jj]);
        float mn = fmaxf(m, cm);
        float corr = __expf(m - mn);
        l *= corr;
#pragma unroll
        for (int d = 0; d < DKH; d++) acc[d] *= corr;
#pragma unroll
        for (int jj = 0; jj < 8; jj++) {
            if (jj < nj) {
                float p = __expf(sc[jj] - mn);
                l += p;
                const float4* vr = (const float4*)&Vs[(j0 + jj) * DKH];
#pragma unroll
                for (int t = 0; t < 16; t++) {
                    float4 vv = vr[t];
                    acc[4 * t + 0] = fmaf(p, vv.x, acc[4 * t + 0]);
                    acc[4 * t + 1] = fmaf(p, vv.y, acc[4 * t + 1]);
                    acc[4 * t + 2] = fmaf(p, vv.z, acc[4 * t + 2]);
                    acc[4 * t + 3] = fmaf(p, vv.w, acc[4 * t + 3]);
                }
            }
        }
        m = mn;
    }

    float inv = 1.0f / l;
    __nv_bfloat162* o = (__nv_bfloat162*)(g_ctxb4 + (size_t)e * NTOK * DM + (size_t)(off + i) * DM + h * DKH);
#pragma unroll
    for (int t = 0; t < 32; t++) {
        __nv_bfloat162 h2;
        h2.x = __float2bfloat16_rn(acc[2 * t + 0] * inv);
        h2.y = __float2bfloat16_rn(acc[2 * t + 1] * inv);
        o[t] = h2;
    }
}

// ================= host =================
extern "C" void kernel_launch(void* const* d_in, const int* in_sizes, int n_in,
                              void* d_out, int out_size)
{
    const float* vis  = (const float*)d_in[0];
    const float* txt  = (const float*)d_in[1];
    const float* Wq   = (const float*)d_in[2];
    const float* bq   = (const float*)d_in[3];
    const float* Wk   = (const float*)d_in[4];
    const float* bk   = (const float*)d_in[5];
    const float* Wv   = (const float*)d_in[6];
    const float* bv   = (const float*)d_in[7];
    const float* Wo   = (const float*)d_in[8];
    const float* bo   = (const float*)d_in[9];
    const float* g1   = (const float*)d_in[10];
    const float* be1  = (const float*)d_in[11];
    const float* W1   = (const float*)d_in[12];
    const float* b1   = (const float*)d_in[13];
    const float* W2   = (const float*)d_in[14];
    const float* b2   = (const float*)d_in[15];
    const float* g2   = (const float*)d_in[16];
    const float* be2  = (const float*)d_in[17];
    const int*   nobj = (const int*)d_in[18];
    float* out = (float*)d_out;

    float *T14, *OUT14, *BQ4, *BKV4, *VF4;
    __nv_bfloat16 *QB4, *KB4, *VISB, *TXTB, *CTXB4, *OUT1B4, *HB4;
    __nv_bfloat16 *WqT4, *WkvT4, *WoT, *W1T, *W2T;
    cudaGetSymbolAddress((void**)&T14, g_t14);
    cudaGetSymbolAddress((void**)&OUT14, g_out14);
    cudaGetSymbolAddress((void**)&BQ4, g_bq4);
    cudaGetSymbolAddress((void**)&BKV4, g_bkv4);
    cudaGetSymbolAddress((void**)&QB4, g_Qb4);
    cudaGetSymbolAddress((void**)&KB4, g_KB4);
    cudaGetSymbolAddress((void**)&VF4, g_VF4);
    cudaGetSymbolAddress((void**)&VISB, g_visb);
    cudaGetSymbolAddress((void**)&TXTB, g_txtb);
    cudaGetSymbolAddress((void**)&CTXB4, g_ctxb4);
    cudaGetSymbolAddress((void**)&OUT1B4, g_out1b4);
    cudaGetSymbolAddress((void**)&HB4, g_hb4);
    cudaGetSymbolAddress((void**)&WqT4, g_WqT4);
    cudaGetSymbolAddress((void**)&WkvT4, g_WkvT4);
    cudaGetSymbolAddress((void**)&WoT, g_WoT);
    cudaGetSymbolAddress((void**)&W1T, g_W1T);
    cudaGetSymbolAddress((void**)&W2T, g_W2T);

    cudaFuncSetAttribute(gemm_bf16_k<false, false, false, true,  false>, cudaFuncAttributeMaxDynamicSharedMemorySize, GEMM_SMEM);
    cudaFuncSetAttribute(gemm_bf16_k<false, false, false, false, true >, cudaFuncAttributeMaxDynamicSharedMemorySize, GEMM_SMEM);
    cudaFuncSetAttribute(gemm_bf16_k<false, true,  true,  false, false>, cudaFuncAttributeMaxDynamicSharedMemorySize, GEMM_SMEM);
    cudaFuncSetAttribute(gemm_bf16_k<true,  false, false, true,  false>, cudaFuncAttributeMaxDynamicSharedMemorySize, GEMM_SMEM);

    auto U4 = [](const void* a, const void* b, const void* c, const void* d) {
        ulong4 u; u.x = (u64)a; u.y = (u64)b; u.z = (u64)c; u.w = (u64)d; return u;
    };

    // 0: fused prepass
    prepass_kernel<<<13345, 256>>>(vis, txt, bq, bk, bv, nobj);

    // 1: weight transposes
    {
        TT tt;
        const size_t BLK = (size_t)DM * DM;
        const u64 qoff[4] = {0, 2 * BLK, BLK, 3 * BLK};
        const u64 koff[4] = {0, 6 * BLK, 4 * BLK, 2 * BLK};
        const u64 voff[4] = {BLK, 7 * BLK, 5 * BLK, 3 * BLK};
        for (int p = 0; p < 4; p++) {
            tt.src[p]      = (u64)(Wq + (size_t)p * BLK); tt.dst[p]      = (u64)(WqT4 + qoff[p]);
            tt.src[4 + p]  = (u64)(Wk + (size_t)p * BLK); tt.dst[4 + p]  = (u64)(WkvT4 + koff[p]);
            tt.src[8 + p]  = (u64)(Wv + (size_t)p * BLK); tt.dst[8 + p]  = (u64)(WkvT4 + voff[p]);
            tt.src[12 + p] = (u64)(Wo + (size_t)p * BLK); tt.dst[12 + p] = (u64)(WoT + (size_t)p * BLK);
            tt.src[16 + p] = (u64)(W1 + (size_t)p * DM * DI); tt.dst[16 + p] = (u64)(W1T + (size_t)p * DI * DM);
            tt.src[20 + p] = (u64)(W2 + (size_t)p * DI * DM); tt.dst[20 + p] = (u64)(W2T + (size_t)p * DM * DI);
        }
        transpose_all_kernel<<<12288, dim3(32, 8)>>>(tt);
    }

    const int MT = (NTOK + 127) / 128;    // 105
    const size_t SL = (size_t)NTOK * DM;
    const int perm[4] = {0, 2, 1, 3};
    ulong4 nullq; nullq.x = nullq.y = nullq.z = nullq.w = 0;

    // 2: Q GEMM (bf16 out)
    {
        ulong4 Aq = U4(VISB, TXTB, VISB, TXTB);
        ulong4 Bq = U4(WqT4, WqT4 + (size_t)NQ * DM, nullptr, nullptr);
        ulong4 bq_ = U4(BQ4, BQ4 + NQ, nullptr, nullptr);
        gemm_bf16_k<false, false, false, true, false><<<dim3(NQ / 128, MT, 2), 128, GEMM_SMEM>>>(
            Aq, Bq, bq_, nullq, nullptr, 0, QB4, (size_t)NTOK * NQ, NTOK, DM, NQ);
    }
    // 3: KV GEMM (split K bf16 / V f32)
    {
        ulong4 Aq = U4(VISB, TXTB, VISB, TXTB);
        ulong4 Bkv = U4(WkvT4, WkvT4 + (size_t)NKV * DM, nullptr, nullptr);
        ulong4 bkv_ = U4(BKV4, BKV4 + NKV, nullptr, nullptr);
        gemm_bf16_k<false, false, false, false, true><<<dim3(NKV / 128, MT, 2), 128, GEMM_SMEM>>>(
            Aq, Bkv, bkv_, nullq, VF4, (size_t)NTOK * NQ, KB4, (size_t)NTOK * NQ, NTOK, DM, NKV);
    }

    // 4: attention
    attn_kernel<<<dim3(BATCH, NH, 4), 96>>>();

    // 5: proj + residual
    {
        const size_t BLK = (size_t)DM * DM;
        ulong4 Aq = U4(CTXB4, CTXB4 + SL, CTXB4 + 2 * SL, CTXB4 + 3 * SL);
        ulong4 Bq = U4(WoT + perm[0] * BLK, WoT + perm[1] * BLK, WoT + perm[2] * BLK, WoT + perm[3] * BLK);
        ulong4 bq_ = U4(bo + perm[0] * DM, bo + perm[1] * DM, bo + perm[2] * DM, bo + perm[3] * DM);
        ulong4 Rq = U4(vis, vis, txt, txt);
        gemm_bf16_k<false, true, true, false, false><<<dim3(DM / 128, MT, 4), 128, GEMM_SMEM>>>(
            Aq, Bq, bq_, Rq, T14, SL, nullptr, 0, NTOK, DM, DM);
    }
    // 6: LN1
    {
        ulong4 gq = U4(g1 + perm[0] * DM, g1 + perm[1] * DM, g1 + perm[2] * DM, g1 + perm[3] * DM);
        ulong4 bq_ = U4(be1 + perm[0] * DM, be1 + perm[1] * DM, be1 + perm[2] * DM, be1 + perm[3] * DM);
        ln1_kernel<<<dim3(NTOK, 4), 128>>>(T14, SL, gq, bq_, OUT14, SL, OUT1B4, SL);
    }
    // 7: FFN1
    {
        ulong4 Aq = U4(OUT1B4, OUT1B4 + SL, OUT1B4 + 2 * SL, OUT1B4 + 3 * SL);
        const size_t WB = (size_t)DI * DM;
        ulong4 Bq = U4(W1T + perm[0] * WB, W1T + perm[1] * WB, W1T + perm[2] * WB, W1T + perm[3] * WB);
        ulong4 bq_ = U4(b1 + perm[0] * DI, b1 + perm[1] * DI, b1 + perm[2] * DI, b1 + perm[3] * DI);
        gemm_bf16_k<true, false, false, true, false><<<dim3(DI / 128, MT, 4), 128, GEMM_SMEM>>>(
            Aq, Bq, bq_, nullq, nullptr, 0, HB4, (size_t)NTOK * DI, NTOK, DM, DI);
    }
    // 8: FFN2 + residual
    {
        const size_t HL = (size_t)NTOK * DI;
        ulong4 Aq = U4(HB4, HB4 + HL, HB4 + 2 * HL, HB4 + 3 * HL);
        const size_t WB = (size_t)DM * DI;
        ulong4 Bq = U4(W2T + perm[0] * WB, W2T + perm[1] * WB, W2T + perm[2] * WB, W2T + perm[3] * WB);
        ulong4 bq_ = U4(b2 + perm[0] * DM, b2 + perm[1] * DM, b2 + perm[2] * DM, b2 + perm[3] * DM);
        ulong4 Rq = U4(OUT14, OUT14 + SL, OUT14 + 2 * SL, OUT14 + 3 * SL);
        gemm_bf16_k<false, true, true, false, false><<<dim3(DM / 128, MT, 4), 128, GEMM_SMEM>>>(
            Aq, Bq, bq_, Rq, T14, SL, nullptr, 0, NTOK, DI, DM);
    }
    // 9: LN2 + sum -> d_out
    {
        ulong4 gq = U4(g2 + perm[0] * DM, g2 + perm[1] * DM, g2 + perm[2] * DM, g2 + perm[3] * DM);
        ulong4 bq_ = U4(be2 + perm[0] * DM, be2 + perm[1] * DM, be2 + perm[2] * DM, be2 + perm[3] * DM);
        ln2_pair_kernel<<<dim3(NTOK, 2), 128>>>(T14, SL, gq, bq_, out);
    }
}

// round 12
// speedup vs baseline: 1.0959x; 1.0736x over previous
#include <cuda_runtime.h>
#include <cuda_bf16.h>
#include <math.h>
#include <stdint.h>

#define NTOK 13320
#define BATCH 240
#define DM 512
#define DI 2048
#define NH 8
#define DKH 64
#define LNEPS 1e-5f
#define NQ 1024
#define NKV 2048
#define NQKV 3072

typedef unsigned long long u64;

// ================= scratch (static device globals; no allocation) =================
__device__ float g_t14  [4 * NTOK * DM];
__device__ float g_out14[4 * NTOK * DM];
__device__ int   g_offs[BATCH + 1];
__device__ float g_bqkv[2 * NQKV];

__device__ __nv_bfloat16 g_Qb4[2 * NTOK * NQ];     // bf16 Q, row stride 1024
__device__ __nv_bfloat16 g_KB4[2 * NTOK * NQ];     // bf16 K, [src][row][half*512+sub]
__device__ float         g_VF4[2 * NTOK * NQ];     // f32  V, same layout

__device__ __nv_bfloat16 g_visb  [NTOK * DM];
__device__ __nv_bfloat16 g_txtb  [NTOK * DM];
__device__ __nv_bfloat16 g_ctxb4 [4 * NTOK * DM];
__device__ __nv_bfloat16 g_out1b4[4 * NTOK * DM];
__device__ __nv_bfloat16 g_hb4   [4 * NTOK * DI];

__device__ __nv_bfloat16 g_WqkvT4[2 * NQKV * DM];  // [src][3072 rows][512], rows: 0-1023 Q, 1024-3071 KV
__device__ __nv_bfloat16 g_WoT  [4 * DM * DM];
__device__ __nv_bfloat16 g_W1T  [4 * DI * DM];
__device__ __nv_bfloat16 g_W2T  [4 * DM * DI];

// ================= helpers =================
__device__ __forceinline__ uint32_t smem_u32(const void* p) {
    uint32_t a;
    asm("{ .reg .u64 t; cvta.to.shared.u64 t, %1; cvt.u32.u64 %0, t; }" : "=r"(a) : "l"(p));
    return a;
}
__device__ __forceinline__ void cp_async16(uint32_t dst, const void* src) {
    asm volatile("cp.async.cg.shared.global [%0], [%1], 16;" :: "r"(dst), "l"(src));
}
#define CP_COMMIT() asm volatile("cp.async.commit_group;" ::: "memory")
#define CP_WAIT(n)  asm volatile("cp.async.wait_group %0;" :: "n"(n) : "memory")

__device__ __forceinline__ void ldmatrix_x4(uint32_t& r0, uint32_t& r1, uint32_t& r2, uint32_t& r3, uint32_t addr) {
    asm volatile("ldmatrix.sync.aligned.m8n8.x4.shared.b16 {%0,%1,%2,%3}, [%4];"
        : "=r"(r0), "=r"(r1), "=r"(r2), "=r"(r3) : "r"(addr));
}
__device__ __forceinline__ void mma_bf16(float* d, const uint32_t* a, const uint32_t* b) {
    asm volatile("mma.sync.aligned.m16n8k16.row.col.f32.bf16.bf16.f32 "
        "{%0,%1,%2,%3}, {%4,%5,%6,%7}, {%8,%9}, {%0,%1,%2,%3};"
        : "+f"(d[0]), "+f"(d[1]), "+f"(d[2]), "+f"(d[3])
        : "r"(a[0]), "r"(a[1]), "r"(a[2]), "r"(a[3]), "r"(b[0]), "r"(b[1]));
}
__device__ __forceinline__ u64 q_at(const ulong4& q, int z) {
    u64 v;
    switch (z) { case 0: v = q.x; break; case 1: v = q.y; break;
                 case 2: v = q.z; break; default: v = q.w; }
    return v;
}
__device__ __forceinline__ void bf8_to_f8(uint4 u, float* dst) {
    float2 f;
    f = __bfloat1622float2(*reinterpret_cast<const __nv_bfloat162*>(&u.x)); dst[0] = f.x; dst[1] = f.y;
    f = __bfloat1622float2(*reinterpret_cast<const __nv_bfloat162*>(&u.y)); dst[2] = f.x; dst[3] = f.y;
    f = __bfloat1622float2(*reinterpret_cast<const __nv_bfloat162*>(&u.z)); dst[4] = f.x; dst[5] = f.y;
    f = __bfloat1622float2(*reinterpret_cast<const __nv_bfloat162*>(&u.w)); dst[6] = f.x; dst[7] = f.y;
}

// ========== fused mega-prepass: cvt(vis,txt) + bias concat + offsets + 24 transposes ==========
#define NC4 (NTOK * DM / 4)
struct TT { u64 src[24]; u64 dst[24]; };

__global__ __launch_bounds__(256) void megaprep_kernel(
    TT tt,
    const float* __restrict__ Vsrc, const float* __restrict__ Tsrc,
    const float* __restrict__ bq, const float* __restrict__ bk, const float* __restrict__ bv,
    const int* __restrict__ nobj)
{
    int bid = blockIdx.x;
    int tid = threadIdx.x;
    if (bid < 13320) {
        int i = bid * 256 + tid;
        const float* X; __nv_bfloat16* Y; int j;
        if (i < NC4) { X = Vsrc; Y = g_visb; j = i; }
        else { X = Tsrc; Y = g_txtb; j = i - NC4; }
        float4 v = ((const float4*)X)[j];
        __nv_bfloat162 a, b;
        a.x = __float2bfloat16_rn(v.x); a.y = __float2bfloat16_rn(v.y);
        b.x = __float2bfloat16_rn(v.z); b.y = __float2bfloat16_rn(v.w);
        ((__nv_bfloat162*)Y)[j * 2 + 0] = a;
        ((__nv_bfloat162*)Y)[j * 2 + 1] = b;
    } else if (bid < 13344) {
        int i = (bid - 13320) * 256 + tid;   // 0..6143
        int src = i / NQKV, r = i % NQKV;
        float val;
        if (r < 1024) {
            int half = (r >> 9) & 1, j = r & 511;
            int p = src + 2 * half;
            val = bq[p * DM + j];
        } else {
            int rr = r - 1024;
            int half = rr >> 10, part = (rr >> 9) & 1, j = rr & 511;
            const int pt[2][2] = { {0, 3}, {2, 1} };
            int p = pt[src][half];
            val = (part ? bv : bk)[p * DM + j];
        }
        g_bqkv[i] = val;
    } else if (bid == 13344) {
        if (tid == 0) {
            int s = 0;
            for (int i = 0; i < BATCH; i++) { g_offs[i] = s; s += nobj[i]; }
            g_offs[BATCH] = s;
        }
    } else {
        int b2 = bid - 13345;
        int e, t, R, C;
        if (b2 < 4096)      { e = b2 >> 8;               t = b2 & 255;            R = 512;  C = 512;  }
        else if (b2 < 8192) { e = 16 + ((b2 - 4096) >> 10); t = (b2 - 4096) & 1023; R = 512;  C = 2048; }
        else                { e = 20 + ((b2 - 8192) >> 10); t = (b2 - 8192) & 1023; R = 2048; C = 512;  }
        const float* Sp = (const float*)tt.src[e];
        __nv_bfloat16* Dp = (__nv_bfloat16*)tt.dst[e];
        int tpr = C >> 5;
        int bx = (t % tpr) * 32, by = (t / tpr) * 32;
        int tx = tid & 31, ty = tid >> 5;

        __shared__ float tile[32][33];
        int x = bx + tx;
#pragma unroll
        for (int yy = ty; yy < 32; yy += 8)
            tile[yy][tx] = Sp[(size_t)(by + yy) * C + x];
        __syncthreads();
        int x2 = by + tx;
#pragma unroll
        for (int yy = ty; yy < 32; yy += 8)
            Dp[(size_t)(bx + yy) * R + x2] = __float2bfloat16_rn(tile[tx][yy]);
    }
}

// ======== bf16 mma.sync GEMM, 128x128 tile (8 warps of 64x32), BK=64, 3-stage ========
#define LDSH 72                            // 64 halves + 8 pad
#define TILEB (128 * LDSH * 2)             // 18432
#define STAGEB (2 * TILEB)                 // 36864
#define NSTAGE 3
#define GEMM_SMEM (NSTAGE * STAGEB)        // 110592

template <bool RELU, bool RESID, bool OF32, bool OBF16, bool OQKV>
__global__ __launch_bounds__(256, 2) void gemm_bf16_k(
    ulong4 Aq, ulong4 Btq, ulong4 biasq, ulong4 Rq,
    float* __restrict__ C, size_t cStr, __nv_bfloat16* __restrict__ Cb, size_t cbStr,
    __nv_bfloat16* __restrict__ Cb2,
    int M, int K, int N)
{
    extern __shared__ char smem[];
    const uint32_t sb = smem_u32(smem);
    const int tid = threadIdx.x;
    const int lane = tid & 31;
    const int wid = tid >> 5;
    const int z = blockIdx.z;
    const int m0 = blockIdx.y * 128;
    const int n0 = blockIdx.x * 128;
    const int warp_m = wid & 1;
    const int warp_n = wid >> 1;

    const __nv_bfloat16* A  = (const __nv_bfloat16*)q_at(Aq, z);
    const __nv_bfloat16* Bt = (const __nv_bfloat16*)q_at(Btq, z);
    const float* bias = (const float*)q_at(biasq, z);
    const float* R = RESID ? (const float*)q_at(Rq, z) : nullptr;
    if (OF32 || OQKV)  C   += (size_t)z * cStr;
    if (OBF16 || OQKV) Cb  += (size_t)z * cbStr;
    if (OQKV)          Cb2 += (size_t)z * cbStr;

    float acc[4][4][4];
#pragma unroll
    for (int i = 0; i < 4; i++)
#pragma unroll
        for (int j = 0; j < 4; j++)
#pragma unroll
            for (int r = 0; r < 4; r++) acc[i][j][r] = 0.f;

    // hoisted per-thread load addressing (k-invariant)
    const __nv_bfloat16* aptr[4];
    const __nv_bfloat16* bptr[4];
    uint32_t adst[4], bdst[4];
#pragma unroll
    for (int i = 0; i < 4; i++) {
        int c = tid + i * 256;
        int row = c >> 3, c16 = c & 7;
        int gr = m0 + row; gr = gr < M ? gr : M - 1;
        aptr[i] = A + (size_t)gr * K + c16 * 8;
        bptr[i] = Bt + (size_t)(n0 + row) * K + c16 * 8;
        adst[i] = row * (LDSH * 2) + c16 * 16;
        bdst[i] = TILEB + row * (LDSH * 2) + c16 * 16;
    }

    const int lmrow  = lane & 15;
    const int lmbyte = (lane >> 4) * 16;
    const int KT = K >> 6;               // BK=64

    auto load_stage_at = [&](uint32_t base, int k0) {
#pragma unroll
        for (int i = 0; i < 4; i++)
            cp_async16(base + adst[i], aptr[i] + k0);
#pragma unroll
        for (int i = 0; i < 4; i++)
            cp_async16(base + bdst[i], bptr[i] + k0);
        CP_COMMIT();
    };

    load_stage_at(sb, 0);
    load_stage_at(sb + STAGEB, 64);

    uint32_t cons = sb;
    uint32_t loadb = sb + 2 * STAGEB;

#pragma unroll 1
    for (int it = 0; it < KT; it++) {
        CP_WAIT(NSTAGE - 2);
        __syncthreads();
        int nk = it + NSTAGE - 1;
        if (nk < KT) load_stage_at(loadb, nk << 6);
        else CP_COMMIT();

        const uint32_t ab = cons;
        const uint32_t bb = cons + TILEB;

#pragma unroll
        for (int kk = 0; kk < 4; kk++) {
            uint32_t af[4][4];
#pragma unroll
            for (int mi = 0; mi < 4; mi++) {
                uint32_t addr = ab + (warp_m * 64 + mi * 16 + lmrow) * (LDSH * 2) + kk * 32 + lmbyte;
                ldmatrix_x4(af[mi][0], af[mi][1], af[mi][2], af[mi][3], addr);
            }
            uint32_t bf[4][2];
#pragma unroll
            for (int t = 0; t < 2; t++) {
                uint32_t addr = bb + (warp_n * 32 + t * 16 + lmrow) * (LDSH * 2) + kk * 32 + lmbyte;
                uint32_t r0, r1, r2, r3;
                ldmatrix_x4(r0, r1, r2, r3, addr);
                bf[t * 2 + 0][0] = r0; bf[t * 2 + 0][1] = r2;
                bf[t * 2 + 1][0] = r1; bf[t * 2 + 1][1] = r3;
            }
#pragma unroll
            for (int mi = 0; mi < 4; mi++)
#pragma unroll
                for (int nj = 0; nj < 4; nj++)
                    mma_bf16(acc[mi][nj], af[mi], bf[nj]);
        }

        loadb = cons;
        cons += STAGEB;
        if (cons == sb + NSTAGE * STAGEB) cons = sb;
    }

    // per-CTA routing for OQKV (whole 128-tile lies in one 512-col block)
    const bool isQ = OQKV && (n0 < 1024);
    const int c2b = n0 - 1024;
    const bool isK = OQKV && !isQ && (((c2b >> 9) & 1) == 0);
    const int colkb = OQKV && !isQ ? (((c2b >> 10) << 9) + (c2b & 511)) : 0;

    const int er = lane >> 2;
    const int ec = (lane & 3) * 2;
#pragma unroll
    for (int mi = 0; mi < 4; mi++) {
#pragma unroll
        for (int half = 0; half < 2; half++) {
            int row = m0 + warp_m * 64 + mi * 16 + half * 8 + er;
            if (row >= M) continue;
#pragma unroll
            for (int nj = 0; nj < 4; nj++) {
                int col = n0 + warp_n * 32 + nj * 8 + ec;
                float2 v;
                v.x = acc[mi][nj][half * 2 + 0] + bias[col + 0];
                v.y = acc[mi][nj][half * 2 + 1] + bias[col + 1];
                if (RESID) {
                    const float2 rv = *(const float2*)(R + (size_t)row * N + col);
                    v.x += rv.x; v.y += rv.y;
                }
                if (RELU) { v.x = fmaxf(v.x, 0.f); v.y = fmaxf(v.y, 0.f); }
                if (OQKV) {
                    int intile = col - n0;                 // 0..127
                    if (isQ) {
                        __nv_bfloat162 h2;
                        h2.x = __float2bfloat16_rn(v.x);
                        h2.y = __float2bfloat16_rn(v.y);
                        *(__nv_bfloat162*)(Cb + (size_t)row * 1024 + col) = h2;
                    } else if (isK) {
                        int colk = colkb + (c2b & 127) * 0 + ((col - 1024) & 511);
                        // (col-1024)&511 == (c2b&511) + intile, both consistent
                        (void)intile;
                        __nv_bfloat162 h2;
                        h2.x = __float2bfloat16_rn(v.x);
                        h2.y = __float2bfloat16_rn(v.y);
                        colk = ((c2b >> 10) << 9) + ((col - 1024) & 511);
                        *(__nv_bfloat162*)(Cb2 + (size_t)row * 1024 + colk) = h2;
                    } else {
                        int colk = ((c2b >> 10) << 9) + ((col - 1024) & 511);
                        *(float2*)(C + (size_t)row * 1024 + colk) = v;
                    }
                } else {
                    if (OF32)
                        *(float2*)(C + (size_t)row * N + col) = v;
                    if (OBF16) {
                        __nv_bfloat162 h2;
                        h2.x = __float2bfloat16_rn(v.x);
                        h2.y = __float2bfloat16_rn(v.y);
                        *(__nv_bfloat162*)(Cb + (size_t)row * N + col) = h2;
                    }
                }
            }
        }
    }
}

// ================= LN1 (z-batched, f32 + bf16 out) =================
__global__ __launch_bounds__(128) void ln1_kernel(
    const float* __restrict__ X, size_t xStr, ulong4 gq, ulong4 bq,
    float* __restrict__ out, size_t oStr, __nv_bfloat16* __restrict__ outb, size_t obStr)
{
    int row = blockIdx.x;
    int e = blockIdx.y;
    int tid = threadIdx.x;
    X += (size_t)e * xStr;
    out += (size_t)e * oStr;
    const float* g = (const float*)q_at(gq, e);
    const float* b = (const float*)q_at(bq, e);

    float4 v = ((const float4*)(X + (size_t)row * DM))[tid];
    __shared__ float sbuf[8];
    int wid = tid >> 5, lane = tid & 31;

    float s = v.x + v.y + v.z + v.w;
#pragma unroll
    for (int o = 16; o > 0; o >>= 1) s += __shfl_xor_sync(0xffffffffu, s, o);
    if (lane == 0) sbuf[wid] = s;
    __syncthreads();
    float mean = (sbuf[0] + sbuf[1] + sbuf[2] + sbuf[3]) * (1.0f / DM);
    __syncthreads();

    float dx0 = v.x - mean, dx1 = v.y - mean, dx2 = v.z - mean, dx3 = v.w - mean;
    float sq = dx0 * dx0 + dx1 * dx1 + dx2 * dx2 + dx3 * dx3;
#pragma unroll
    for (int o = 16; o > 0; o >>= 1) sq += __shfl_xor_sync(0xffffffffu, sq, o);
    if (lane == 0) sbuf[wid] = sq;
    __syncthreads();
    float var = (sbuf[0] + sbuf[1] + sbuf[2] + sbuf[3]) * (1.0f / DM);
    float rstd = rsqrtf(var + LNEPS);

    float4 gg = ((const float4*)g)[tid];
    float4 bb = ((const float4*)b)[tid];
    float4 y;
    y.x = dx0 * rstd * gg.x + bb.x;
    y.y = dx1 * rstd * gg.y + bb.y;
    y.z = dx2 * rstd * gg.z + bb.z;
    y.w = dx3 * rstd * gg.w + bb.w;

    ((float4*)(out + (size_t)row * DM))[tid] = y;
    __nv_bfloat16* ob = outb + (size_t)e * obStr + (size_t)row * DM;
    __nv_bfloat162 a, c;
    a.x = __float2bfloat16_rn(y.x); a.y = __float2bfloat16_rn(y.y);
    c.x = __float2bfloat16_rn(y.z); c.y = __float2bfloat16_rn(y.w);
    ((__nv_bfloat162*)ob)[tid * 2 + 0] = a;
    ((__nv_bfloat162*)ob)[tid * 2 + 1] = c;
}

// ============ LN2 pair + sum: out[p] = LN(T14[2p]) + LN(T14[2p+1]) ============
__global__ __launch_bounds__(128) void ln2_pair_kernel(
    const float* __restrict__ X, size_t xStr, ulong4 gq, ulong4 bq, float* __restrict__ out)
{
    int row = blockIdx.x;
    int p = blockIdx.y;
    int tid = threadIdx.x;
    int wid = tid >> 5, lane = tid & 31;

    const float* X0 = X + (size_t)(2 * p) * xStr + (size_t)row * DM;
    const float* X1 = X + (size_t)(2 * p + 1) * xStr + (size_t)row * DM;
    float4 v0 = ((const float4*)X0)[tid];
    float4 v1 = ((const float4*)X1)[tid];

    __shared__ float sbuf[16];
    float s0 = v0.x + v0.y + v0.z + v0.w;
    float s1 = v1.x + v1.y + v1.z + v1.w;
#pragma unroll
    for (int o = 16; o > 0; o >>= 1) {
        s0 += __shfl_xor_sync(0xffffffffu, s0, o);
        s1 += __shfl_xor_sync(0xffffffffu, s1, o);
    }
    if (lane == 0) { sbuf[wid] = s0; sbuf[8 + wid] = s1; }
    __syncthreads();
    float mean0 = (sbuf[0] + sbuf[1] + sbuf[2] + sbuf[3]) * (1.0f / DM);
    float mean1 = (sbuf[8] + sbuf[9] + sbuf[10] + sbuf[11]) * (1.0f / DM);
    __syncthreads();

    float a0 = v0.x - mean0, a1 = v0.y - mean0, a2 = v0.z - mean0, a3 = v0.w - mean0;
    float c0 = v1.x - mean1, c1 = v1.y - mean1, c2 = v1.z - mean1, c3 = v1.w - mean1;
    float q0 = a0 * a0 + a1 * a1 + a2 * a2 + a3 * a3;
    float q1 = c0 * c0 + c1 * c1 + c2 * c2 + c3 * c3;
#pragma unroll
    for (int o = 16; o > 0; o >>= 1) {
        q0 += __shfl_xor_sync(0xffffffffu, q0, o);
        q1 += __shfl_xor_sync(0xffffffffu, q1, o);
    }
    if (lane == 0) { sbuf[wid] = q0; sbuf[8 + wid] = q1; }
    __syncthreads();
    float rstd0 = rsqrtf((sbuf[0] + sbuf[1] + sbuf[2] + sbuf[3]) * (1.0f / DM) + LNEPS);
    float rstd1 = rsqrtf((sbuf[8] + sbuf[9] + sbuf[10] + sbuf[11]) * (1.0f / DM) + LNEPS);

    const float* g0 = (const float*)q_at(gq, 2 * p);
    const float* b0 = (const float*)q_at(bq, 2 * p);
    const float* g1 = (const float*)q_at(gq, 2 * p + 1);
    const float* b1 = (const float*)q_at(bq, 2 * p + 1);
    float4 gg0 = ((const float4*)g0)[tid], bb0 = ((const float4*)b0)[tid];
    float4 gg1 = ((const float4*)g1)[tid], bb1 = ((const float4*)b1)[tid];

    float4 y;
    y.x = (a0 * rstd0 * gg0.x + bb0.x) + (c0 * rstd1 * gg1.x + bb1.x);
    y.y = (a1 * rstd0 * gg0.y + bb0.y) + (c1 * rstd1 * gg1.y + bb1.y);
    y.z = (a2 * rstd0 * gg0.z + bb0.z) + (c2 * rstd1 * gg1.z + bb1.z);
    y.w = (a3 * rstd0 * gg0.w + bb0.w) + (c3 * rstd1 * gg1.w + bb1.w);

    ((float4*)(out + (size_t)p * NTOK * DM + (size_t)row * DM))[tid] = y;
}

// ================= segment attention (bf16 Q/K, fp32 V, scalar FMA) =================
__global__ __launch_bounds__(96) void attn_kernel()
{
    int s = blockIdx.x;
    int h = blockIdx.y;
    int e = blockIdx.z;
    int off = g_offs[s];
    int L = g_offs[s + 1] - off;

    const int srcQ = e >> 1, halfQ = e & 1;
    const int srcKV_t[4]  = {0, 1, 1, 0};
    const int halfKV_t[4] = {0, 0, 1, 1};
    const int srcKV = srcKV_t[e], halfKV = halfKV_t[e];

    const __nv_bfloat16* Qb = g_Qb4 + (size_t)srcQ  * NTOK * NQ + halfQ  * 512 + h * DKH;
    const __nv_bfloat16* Kb = g_KB4 + (size_t)srcKV * NTOK * NQ + halfKV * 512 + h * DKH;
    const float*         Vf = g_VF4 + (size_t)srcKV * NTOK * NQ + halfKV * 512 + h * DKH;

    __shared__ __align__(16) float Ks[95 * DKH];
    __shared__ __align__(16) float Vs[95 * DKH];
    for (int idx = threadIdx.x; idx < L * 16; idx += 96) {
        int j = idx >> 4, d4 = idx & 15;
        ((float4*)Vs)[j * 16 + d4] = ((const float4*)(Vf + (size_t)(off + j) * NQ))[d4];
    }
    for (int idx = threadIdx.x; idx < L * 8; idx += 96) {
        int j = idx >> 3, c = idx & 7;
        uint4 u = ((const uint4*)(Kb + (size_t)(off + j) * NQ))[c];
        bf8_to_f8(u, &Ks[j * DKH + c * 8]);
    }
    __syncthreads();

    int i = threadIdx.x;
    if (i >= L) return;

    float q[DKH];
    {
        const uint4* qp = (const uint4*)(Qb + (size_t)(off + i) * NQ);
#pragma unroll
        for (int t = 0; t < 8; t++) {
            uint4 u = qp[t];
            bf8_to_f8(u, &q[t * 8]);
        }
    }

    float m = -INFINITY, l = 0.f;
    float acc[DKH];
#pragma unroll
    for (int d = 0; d < DKH; d++) acc[d] = 0.f;

    for (int j0 = 0; j0 < L; j0 += 8) {
        int nj = L - j0; if (nj > 8) nj = 8;
        float sc[8];
#pragma unroll
        for (int jj = 0; jj < 8; jj++) {
            if (jj < nj) {
                const float4* kr = (const float4*)&Ks[(j0 + jj) * DKH];
                float sd = 0.f;
#pragma unroll
                for (int t = 0; t < 16; t++) {
                    float4 kv = kr[t];
                    sd = fmaf(q[4 * t + 0], kv.x, sd);
                    sd = fmaf(q[4 * t + 1], kv.y, sd);
                    sd = fmaf(q[4 * t + 2], kv.z, sd);
                    sd = fmaf(q[4 * t + 3], kv.w, sd);
                }
                sc[jj] = sd * 0.125f;
            } else sc[jj] = -INFINITY;
        }
        float cm = sc[0];
#pragma unroll
        for (int jj = 1; jj < 8; jj++) cm = fmaxf(cm, sc[jj]);
        float mn = fmaxf(m, cm);
        float corr = __expf(m - mn);
        l *= corr;
#pragma unroll
        for (int d = 0; d < DKH; d++) acc[d] *= corr;
#pragma unroll
        for (int jj = 0; jj < 8; jj++) {
            if (jj < nj) {
                float p = __expf(sc[jj] - mn);
                l += p;
                const float4* vr = (const float4*)&Vs[(j0 + jj) * DKH];
#pragma unroll
                for (int t = 0; t < 16; t++) {
                    float4 vv = vr[t];
                    acc[4 * t + 0] = fmaf(p, vv.x, acc[4 * t + 0]);
                    acc[4 * t + 1] = fmaf(p, vv.y, acc[4 * t + 1]);
                    acc[4 * t + 2] = fmaf(p, vv.z, acc[4 * t + 2]);
                    acc[4 * t + 3] = fmaf(p, vv.w, acc[4 * t + 3]);
                }
            }
        }
        m = mn;
    }

    float inv = 1.0f / l;
    __nv_bfloat162* o = (__nv_bfloat162*)(g_ctxb4 + (size_t)e * NTOK * DM + (size_t)(off + i) * DM + h * DKH);
#pragma unroll
    for (int t = 0; t < 32; t++) {
        __nv_bfloat162 h2;
        h2.x = __float2bfloat16_rn(acc[2 * t + 0] * inv);
        h2.y = __float2bfloat16_rn(acc[2 * t + 1] * inv);
        o[t] = h2;
    }
}

// ================= host =================
extern "C" void kernel_launch(void* const* d_in, const int* in_sizes, int n_in,
                              void* d_out, int out_size)
{
    const float* vis  = (const float*)d_in[0];
    const float* txt  = (const float*)d_in[1];
    const float* Wq   = (const float*)d_in[2];
    const float* bq   = (const float*)d_in[3];
    const float* Wk   = (const float*)d_in[4];
    const float* bk   = (const float*)d_in[5];
    const float* Wv   = (const float*)d_in[6];
    const float* bv   = (const float*)d_in[7];
    const float* Wo   = (const float*)d_in[8];
    const float* bo   = (const float*)d_in[9];
    const float* g1   = (const float*)d_in[10];
    const float* be1  = (const float*)d_in[11];
    const float* W1   = (const float*)d_in[12];
    const float* b1   = (const float*)d_in[13];
    const float* W2   = (const float*)d_in[14];
    const float* b2   = (const float*)d_in[15];
    const float* g2   = (const float*)d_in[16];
    const float* be2  = (const float*)d_in[17];
    const int*   nobj = (const int*)d_in[18];
    float* out = (float*)d_out;

    float *T14, *OUT14, *BQKV, *VF4;
    __nv_bfloat16 *QB4, *KB4, *VISB, *TXTB, *CTXB4, *OUT1B4, *HB4;
    __nv_bfloat16 *WqkvT4, *WoT, *W1T, *W2T;
    cudaGetSymbolAddress((void**)&T14, g_t14);
    cudaGetSymbolAddress((void**)&OUT14, g_out14);
    cudaGetSymbolAddress((void**)&BQKV, g_bqkv);
    cudaGetSymbolAddress((void**)&QB4, g_Qb4);
    cudaGetSymbolAddress((void**)&KB4, g_KB4);
    cudaGetSymbolAddress((void**)&VF4, g_VF4);
    cudaGetSymbolAddress((void**)&VISB, g_visb);
    cudaGetSymbolAddress((void**)&TXTB, g_txtb);
    cudaGetSymbolAddress((void**)&CTXB4, g_ctxb4);
    cudaGetSymbolAddress((void**)&OUT1B4, g_out1b4);
    cudaGetSymbolAddress((void**)&HB4, g_hb4);
    cudaGetSymbolAddress((void**)&WqkvT4, g_WqkvT4);
    cudaGetSymbolAddress((void**)&WoT, g_WoT);
    cudaGetSymbolAddress((void**)&W1T, g_W1T);
    cudaGetSymbolAddress((void**)&W2T, g_W2T);

    cudaFuncSetAttribute(gemm_bf16_k<false, false, false, false, true >, cudaFuncAttributeMaxDynamicSharedMemorySize, GEMM_SMEM);
    cudaFuncSetAttribute(gemm_bf16_k<false, true,  true,  false, false>, cudaFuncAttributeMaxDynamicSharedMemorySize, GEMM_SMEM);
    cudaFuncSetAttribute(gemm_bf16_k<true,  false, false, true,  false>, cudaFuncAttributeMaxDynamicSharedMemorySize, GEMM_SMEM);

    auto U4 = [](const void* a, const void* b, const void* c, const void* d) {
        ulong4 u; u.x = (u64)a; u.y = (u64)b; u.z = (u64)c; u.w = (u64)d; return u;
    };

    // 0: mega prepass (cvt + bias + offsets + all 24 transposes)
    {
        TT tt;
        const size_t BLK = (size_t)DM * DM;        // 262144
        // fused weight layout per src: rows [0,1024) Q halves, [1024,3072) KV
        // offset = src*6BLK + (Q: half*BLK) | (KV: 2BLK + half*2BLK + part*BLK)
        const u64 qoff[4] = {0, 6 * BLK, 1 * BLK, 7 * BLK};        // p -> (src,half): p0(0,0) p1(1,0) p2(0,1) p3(1,1)
        const u64 koff[4] = {2 * BLK, 10 * BLK, 8 * BLK, 4 * BLK}; // src: p0->0,h0 ; p1->1,h1 ; p2->1,h0 ; p3->0,h1
        const u64 voff[4] = {3 * BLK, 11 * BLK, 9 * BLK, 5 * BLK};
        for (int p = 0; p < 4; p++) {
            tt.src[p]      = (u64)(Wq + (size_t)p * BLK); tt.dst[p]      = (u64)(WqkvT4 + qoff[p]);
            tt.src[4 + p]  = (u64)(Wk + (size_t)p * BLK); tt.dst[4 + p]  = (u64)(WqkvT4 + koff[p]);
            tt.src[8 + p]  = (u64)(Wv + (size_t)p * BLK); tt.dst[8 + p]  = (u64)(WqkvT4 + voff[p]);
            tt.src[12 + p] = (u64)(Wo + (size_t)p * BLK); tt.dst[12 + p] = (u64)(WoT + (size_t)p * BLK);
            tt.src[16 + p] = (u64)(W1 + (size_t)p * DM * DI); tt.dst[16 + p] = (u64)(W1T + (size_t)p * DI * DM);
            tt.src[20 + p] = (u64)(W2 + (size_t)p * DI * DM); tt.dst[20 + p] = (u64)(W2T + (size_t)p * DM * DI);
        }
        megaprep_kernel<<<25633, 256>>>(tt, vis, txt, bq, bk, bv, nobj);
    }

    const int MT = (NTOK + 127) / 128;    // 105
    const size_t SL = (size_t)NTOK * DM;
    const int perm[4] = {0, 2, 1, 3};
    ulong4 nullq; nullq.x = nullq.y = nullq.z = nullq.w = 0;

    // 1: fused QKV GEMM (N=3072; Q bf16 / K bf16 / V f32 routed per CTA)
    {
        ulong4 Aq = U4(VISB, TXTB, nullptr, nullptr);
        ulong4 Bq = U4(WqkvT4, WqkvT4 + (size_t)NQKV * DM, nullptr, nullptr);
        ulong4 bq_ = U4(BQKV, BQKV + NQKV, nullptr, nullptr);
        gemm_bf16_k<false, false, false, false, true><<<dim3(NQKV / 128, MT, 2), 256, GEMM_SMEM>>>(
            Aq, Bq, bq_, nullq, VF4, (size_t)NTOK * NQ, QB4, (size_t)NTOK * NQ, KB4, NTOK, DM, NQKV);
    }

    // 2: attention
    attn_kernel<<<dim3(BATCH, NH, 4), 96>>>();

    // 3: proj + residual
    {
        const size_t BLK = (size_t)DM * DM;
        ulong4 Aq = U4(CTXB4, CTXB4 + SL, CTXB4 + 2 * SL, CTXB4 + 3 * SL);
        ulong4 Bq = U4(WoT + perm[0] * BLK, WoT + perm[1] * BLK, WoT + perm[2] * BLK, WoT + perm[3] * BLK);
        ulong4 bq_ = U4(bo + perm[0] * DM, bo + perm[1] * DM, bo + perm[2] * DM, bo + perm[3] * DM);
        ulong4 Rq = U4(vis, vis, txt, txt);
        gemm_bf16_k<false, true, true, false, false><<<dim3(DM / 128, MT, 4), 256, GEMM_SMEM>>>(
            Aq, Bq, bq_, Rq, T14, SL, nullptr, 0, nullptr, NTOK, DM, DM);
    }
    // 4: LN1
    {
        ulong4 gq = U4(g1 + perm[0] * DM, g1 + perm[1] * DM, g1 + perm[2] * DM, g1 + perm[3] * DM);
        ulong4 bq_ = U4(be1 + perm[0] * DM, be1 + perm[1] * DM, be1 + perm[2] * DM, be1 + perm[3] * DM);
        ln1_kernel<<<dim3(NTOK, 4), 128>>>(T14, SL, gq, bq_, OUT14, SL, OUT1B4, SL);
    }
    // 5: FFN1
    {
        ulong4 Aq = U4(OUT1B4, OUT1B4 + SL, OUT1B4 + 2 * SL, OUT1B4 + 3 * SL);
        const size_t WB = (size_t)DI * DM;
        ulong4 Bq = U4(W1T + perm[0] * WB, W1T + perm[1] * WB, W1T + perm[2] * WB, W1T + perm[3] * WB);
        ulong4 bq_ = U4(b1 + perm[0] * DI, b1 + perm[1] * DI, b1 + perm[2] * DI, b1 + perm[3] * DI);
        gemm_bf16_k<true, false, false, true, false><<<dim3(DI / 128, MT, 4), 256, GEMM_SMEM>>>(
            Aq, Bq, bq_, nullq, nullptr, 0, HB4, (size_t)NTOK * DI, nullptr, NTOK, DM, DI);
    }
    // 6: FFN2 + residual
    {
        const size_t HL = (size_t)NTOK * DI;
        ulong4 Aq = U4(HB4, HB4 + HL, HB4 + 2 * HL, HB4 + 3 * HL);
        const size_t WB = (size_t)DM * DI;
        ulong4 Bq = U4(W2T + perm[0] * WB, W2T + perm[1] * WB, W2T + perm[2] * WB, W2T + perm[3] * WB);
        ulong4 bq_ = U4(b2 + perm[0] * DM, b2 + perm[1] * DM, b2 + perm[2] * DM, b2 + perm[3] * DM);
        ulong4 Rq = U4(OUT14, OUT14 + SL, OUT14 + 2 * SL, OUT14 + 3 * SL);
        gemm_bf16_k<false, true, true, false, false><<<dim3(DM / 128, MT, 4), 256, GEMM_SMEM>>>(
            Aq, Bq, bq_, Rq, T14, SL, nullptr, 0, nullptr, NTOK, DI, DM);
    }
    // 7: LN2 + sum -> d_out
    {
        ulong4 gq = U4(g2 + perm[0] * DM, g2 + perm[1] * DM, g2 + perm[2] * DM, g2 + perm[3] * DM);
        ulong4 bq_ = U4(be2 + perm[0] * DM, be2 + perm[1] * DM, be2 + perm[2] * DM, be2 + perm[3] * DM);
        ln2_pair_kernel<<<dim3(NTOK, 2), 128>>>(T14, SL, gq, bq_, out);
    }
}

// round 13
// speedup vs baseline: 1.3429x; 1.2254x over previous
#include <cuda_runtime.h>
#include <cuda_bf16.h>
#include <math.h>
#include <stdint.h>

#define NTOK 13320
#define BATCH 240
#define DM 512
#define DI 2048
#define NH 8
#define DKH 64
#define LNEPS 1e-5f
#define NQ 1024
#define NKV 2048
#define NQKV 3072

typedef unsigned long long u64;

// ================= scratch (static device globals; no allocation) =================
__device__ float g_t14  [4 * NTOK * DM];
__device__ float g_out14[4 * NTOK * DM];
__device__ int   g_offs[BATCH + 1];
__device__ float g_bqkv[2 * NQKV];

__device__ __nv_bfloat16 g_Qb4[2 * NTOK * NQ];     // bf16 Q, row stride 1024
__device__ __nv_bfloat16 g_KB4[2 * NTOK * NQ];     // bf16 K, [src][row][half*512+sub]
__device__ __nv_bfloat16 g_Vb4[2 * NTOK * NQ];     // bf16 V, same layout

__device__ __nv_bfloat16 g_visb  [NTOK * DM];
__device__ __nv_bfloat16 g_txtb  [NTOK * DM];
__device__ __nv_bfloat16 g_ctxb4 [4 * NTOK * DM];
__device__ __nv_bfloat16 g_out1b4[4 * NTOK * DM];
__device__ __nv_bfloat16 g_hb4   [4 * NTOK * DI];

__device__ __nv_bfloat16 g_WqkvT4[2 * NQKV * DM];
__device__ __nv_bfloat16 g_WoT  [4 * DM * DM];
__device__ __nv_bfloat16 g_W1T  [4 * DI * DM];
__device__ __nv_bfloat16 g_W2T  [4 * DM * DI];

// ================= helpers =================
__device__ __forceinline__ uint32_t smem_u32(const void* p) {
    uint32_t a;
    asm("{ .reg .u64 t; cvta.to.shared.u64 t, %1; cvt.u32.u64 %0, t; }" : "=r"(a) : "l"(p));
    return a;
}
__device__ __forceinline__ void cp_async16(uint32_t dst, const void* src) {
    asm volatile("cp.async.cg.shared.global [%0], [%1], 16;" :: "r"(dst), "l"(src));
}
#define CP_COMMIT() asm volatile("cp.async.commit_group;" ::: "memory")
#define CP_WAIT(n)  asm volatile("cp.async.wait_group %0;" :: "n"(n) : "memory")

__device__ __forceinline__ void ldmatrix_x4(uint32_t& r0, uint32_t& r1, uint32_t& r2, uint32_t& r3, uint32_t addr) {
    asm volatile("ldmatrix.sync.aligned.m8n8.x4.shared.b16 {%0,%1,%2,%3}, [%4];"
        : "=r"(r0), "=r"(r1), "=r"(r2), "=r"(r3) : "r"(addr));
}
__device__ __forceinline__ void ldmatrix_x4_t(uint32_t& r0, uint32_t& r1, uint32_t& r2, uint32_t& r3, uint32_t addr) {
    asm volatile("ldmatrix.sync.aligned.m8n8.x4.trans.shared.b16 {%0,%1,%2,%3}, [%4];"
        : "=r"(r0), "=r"(r1), "=r"(r2), "=r"(r3) : "r"(addr));
}
__device__ __forceinline__ void mma_bf16(float* d, const uint32_t* a, const uint32_t* b) {
    asm volatile("mma.sync.aligned.m16n8k16.row.col.f32.bf16.bf16.f32 "
        "{%0,%1,%2,%3}, {%4,%5,%6,%7}, {%8,%9}, {%0,%1,%2,%3};"
        : "+f"(d[0]), "+f"(d[1]), "+f"(d[2]), "+f"(d[3])
        : "r"(a[0]), "r"(a[1]), "r"(a[2]), "r"(a[3]), "r"(b[0]), "r"(b[1]));
}
__device__ __forceinline__ u64 q_at(const ulong4& q, int z) {
    u64 v;
    switch (z) { case 0: v = q.x; break; case 1: v = q.y; break;
                 case 2: v = q.z; break; default: v = q.w; }
    return v;
}

// ========== fused mega-prepass: cvt(vis,txt) + bias concat + offsets + 24 transposes ==========
#define NC4 (NTOK * DM / 4)
struct TT { u64 src[24]; u64 dst[24]; };

__global__ __launch_bounds__(256) void megaprep_kernel(
    TT tt,
    const float* __restrict__ Vsrc, const float* __restrict__ Tsrc,
    const float* __restrict__ bq, const float* __restrict__ bk, const float* __restrict__ bv,
    const int* __restrict__ nobj)
{
    int bid = blockIdx.x;
    int tid = threadIdx.x;
    if (bid < 13320) {
        int i = bid * 256 + tid;
        const float* X; __nv_bfloat16* Y; int j;
        if (i < NC4) { X = Vsrc; Y = g_visb; j = i; }
        else { X = Tsrc; Y = g_txtb; j = i - NC4; }
        float4 v = ((const float4*)X)[j];
        __nv_bfloat162 a, b;
        a.x = __float2bfloat16_rn(v.x); a.y = __float2bfloat16_rn(v.y);
        b.x = __float2bfloat16_rn(v.z); b.y = __float2bfloat16_rn(v.w);
        ((__nv_bfloat162*)Y)[j * 2 + 0] = a;
        ((__nv_bfloat162*)Y)[j * 2 + 1] = b;
    } else if (bid < 13344) {
        int i = (bid - 13320) * 256 + tid;
        int src = i / NQKV, r = i % NQKV;
        float val;
        if (r < 1024) {
            int half = (r >> 9) & 1, j = r & 511;
            int p = src + 2 * half;
            val = bq[p * DM + j];
        } else {
            int rr = r - 1024;
            int half = rr >> 10, part = (rr >> 9) & 1, j = rr & 511;
            const int pt[2][2] = { {0, 3}, {2, 1} };
            int p = pt[src][half];
            val = (part ? bv : bk)[p * DM + j];
        }
        g_bqkv[i] = val;
    } else if (bid == 13344) {
        if (tid == 0) {
            int s = 0;
            for (int i = 0; i < BATCH; i++) { g_offs[i] = s; s += nobj[i]; }
            g_offs[BATCH] = s;
        }
    } else {
        int b2 = bid - 13345;
        int e, t, R, C;
        if (b2 < 4096)      { e = b2 >> 8;               t = b2 & 255;            R = 512;  C = 512;  }
        else if (b2 < 8192) { e = 16 + ((b2 - 4096) >> 10); t = (b2 - 4096) & 1023; R = 512;  C = 2048; }
        else                { e = 20 + ((b2 - 8192) >> 10); t = (b2 - 8192) & 1023; R = 2048; C = 512;  }
        const float* Sp = (const float*)tt.src[e];
        __nv_bfloat16* Dp = (__nv_bfloat16*)tt.dst[e];
        int tpr = C >> 5;
        int bx = (t % tpr) * 32, by = (t / tpr) * 32;
        int tx = tid & 31, ty = tid >> 5;

        __shared__ float tile[32][33];
        int x = bx + tx;
#pragma unroll
        for (int yy = ty; yy < 32; yy += 8)
            tile[yy][tx] = Sp[(size_t)(by + yy) * C + x];
        __syncthreads();
        int x2 = by + tx;
#pragma unroll
        for (int yy = ty; yy < 32; yy += 8)
            Dp[(size_t)(bx + yy) * R + x2] = __float2bfloat16_rn(tile[tx][yy]);
    }
}

// ======== bf16 mma.sync GEMM, 128x128 tile (8 warps of 64x32), BK=64, 3-stage ========
#define LDSH 72
#define TILEB (128 * LDSH * 2)
#define STAGEB (2 * TILEB)
#define NSTAGE 3
#define GEMM_SMEM (NSTAGE * STAGEB)        // 110592

template <bool RELU, bool RESID, bool OF32, bool OBF16, bool OQKV>
__global__ __launch_bounds__(256, 2) void gemm_bf16_k(
    ulong4 Aq, ulong4 Btq, ulong4 biasq, ulong4 Rq,
    float* __restrict__ C, size_t cStr, __nv_bfloat16* __restrict__ Cb, size_t cbStr,
    __nv_bfloat16* __restrict__ Cb2,
    int M, int K, int N)
{
    extern __shared__ char smem[];
    const uint32_t sb = smem_u32(smem);
    const int tid = threadIdx.x;
    const int lane = tid & 31;
    const int wid = tid >> 5;
    const int z = blockIdx.z;
    const int m0 = blockIdx.y * 128;
    const int n0 = blockIdx.x * 128;
    const int warp_m = wid & 1;
    const int warp_n = wid >> 1;

    const __nv_bfloat16* A  = (const __nv_bfloat16*)q_at(Aq, z);
    const __nv_bfloat16* Bt = (const __nv_bfloat16*)q_at(Btq, z);
    const float* bias = (const float*)q_at(biasq, z);
    const float* R = RESID ? (const float*)q_at(Rq, z) : nullptr;
    if (OF32)  C  += (size_t)z * cStr;
    __nv_bfloat16* Vb2 = OQKV ? ((__nv_bfloat16*)C) + (size_t)z * cbStr : nullptr;
    if (OBF16 || OQKV) Cb  += (size_t)z * cbStr;
    __nv_bfloat16* Kb2 = OQKV ? Cb2 + (size_t)z * cbStr : nullptr;

    float acc[4][4][4];
#pragma unroll
    for (int i = 0; i < 4; i++)
#pragma unroll
        for (int j = 0; j < 4; j++)
#pragma unroll
            for (int r = 0; r < 4; r++) acc[i][j][r] = 0.f;

    const __nv_bfloat16* aptr[4];
    const __nv_bfloat16* bptr[4];
    uint32_t adst[4], bdst[4];
#pragma unroll
    for (int i = 0; i < 4; i++) {
        int c = tid + i * 256;
        int row = c >> 3, c16 = c & 7;
        int gr = m0 + row; gr = gr < M ? gr : M - 1;
        aptr[i] = A + (size_t)gr * K + c16 * 8;
        bptr[i] = Bt + (size_t)(n0 + row) * K + c16 * 8;
        adst[i] = row * (LDSH * 2) + c16 * 16;
        bdst[i] = TILEB + row * (LDSH * 2) + c16 * 16;
    }

    const int lmrow  = lane & 15;
    const int lmbyte = (lane >> 4) * 16;
    const int KT = K >> 6;

    auto load_stage_at = [&](uint32_t base, int k0) {
#pragma unroll
        for (int i = 0; i < 4; i++)
            cp_async16(base + adst[i], aptr[i] + k0);
#pragma unroll
        for (int i = 0; i < 4; i++)
            cp_async16(base + bdst[i], bptr[i] + k0);
        CP_COMMIT();
    };

    load_stage_at(sb, 0);
    load_stage_at(sb + STAGEB, 64);

    uint32_t cons = sb;
    uint32_t loadb = sb + 2 * STAGEB;

#pragma unroll 1
    for (int it = 0; it < KT; it++) {
        CP_WAIT(NSTAGE - 2);
        __syncthreads();
        int nk = it + NSTAGE - 1;
        if (nk < KT) load_stage_at(loadb, nk << 6);
        else CP_COMMIT();

        const uint32_t ab = cons;
        const uint32_t bb = cons + TILEB;

#pragma unroll
        for (int kk = 0; kk < 4; kk++) {
            uint32_t af[4][4];
#pragma unroll
            for (int mi = 0; mi < 4; mi++) {
                uint32_t addr = ab + (warp_m * 64 + mi * 16 + lmrow) * (LDSH * 2) + kk * 32 + lmbyte;
                ldmatrix_x4(af[mi][0], af[mi][1], af[mi][2], af[mi][3], addr);
            }
            uint32_t bf[4][2];
#pragma unroll
            for (int t = 0; t < 2; t++) {
                uint32_t addr = bb + (warp_n * 32 + t * 16 + lmrow) * (LDSH * 2) + kk * 32 + lmbyte;
                uint32_t r0, r1, r2, r3;
                ldmatrix_x4(r0, r1, r2, r3, addr);
                bf[t * 2 + 0][0] = r0; bf[t * 2 + 0][1] = r2;
                bf[t * 2 + 1][0] = r1; bf[t * 2 + 1][1] = r3;
            }
#pragma unroll
            for (int mi = 0; mi < 4; mi++)
#pragma unroll
                for (int nj = 0; nj < 4; nj++)
                    mma_bf16(acc[mi][nj], af[mi], bf[nj]);
        }

        loadb = cons;
        cons += STAGEB;
        if (cons == sb + NSTAGE * STAGEB) cons = sb;
    }

    const bool isQ = OQKV && (n0 < 1024);
    const int c2b = n0 - 1024;
    const bool isK = OQKV && !isQ && (((c2b >> 9) & 1) == 0);

    const int er = lane >> 2;
    const int ec = (lane & 3) * 2;
#pragma unroll
    for (int mi = 0; mi < 4; mi++) {
#pragma unroll
        for (int half = 0; half < 2; half++) {
            int row = m0 + warp_m * 64 + mi * 16 + half * 8 + er;
            if (row >= M) continue;
#pragma unroll
            for (int nj = 0; nj < 4; nj++) {
                int col = n0 + warp_n * 32 + nj * 8 + ec;
                float2 v;
                v.x = acc[mi][nj][half * 2 + 0] + bias[col + 0];
                v.y = acc[mi][nj][half * 2 + 1] + bias[col + 1];
                if (RESID) {
                    const float2 rv = *(const float2*)(R + (size_t)row * N + col);
                    v.x += rv.x; v.y += rv.y;
                }
                if (RELU) { v.x = fmaxf(v.x, 0.f); v.y = fmaxf(v.y, 0.f); }
                if (OQKV) {
                    __nv_bfloat162 h2;
                    h2.x = __float2bfloat16_rn(v.x);
                    h2.y = __float2bfloat16_rn(v.y);
                    if (isQ) {
                        *(__nv_bfloat162*)(Cb + (size_t)row * 1024 + col) = h2;
                    } else {
                        int colk = ((c2b >> 10) << 9) + ((col - 1024) & 511);
                        if (isK)
                            *(__nv_bfloat162*)(Kb2 + (size_t)row * 1024 + colk) = h2;
                        else
                            *(__nv_bfloat162*)(Vb2 + (size_t)row * 1024 + colk) = h2;
                    }
                } else {
                    if (OF32)
                        *(float2*)(C + (size_t)row * N + col) = v;
                    if (OBF16) {
                        __nv_bfloat162 h2;
                        h2.x = __float2bfloat16_rn(v.x);
                        h2.y = __float2bfloat16_rn(v.y);
                        *(__nv_bfloat162*)(Cb + (size_t)row * N + col) = h2;
                    }
                }
            }
        }
    }
}

// ================= LN1 (z-batched, f32 + bf16 out) =================
__global__ __launch_bounds__(128) void ln1_kernel(
    const float* __restrict__ X, size_t xStr, ulong4 gq, ulong4 bq,
    float* __restrict__ out, size_t oStr, __nv_bfloat16* __restrict__ outb, size_t obStr)
{
    int row = blockIdx.x;
    int e = blockIdx.y;
    int tid = threadIdx.x;
    X += (size_t)e * xStr;
    out += (size_t)e * oStr;
    const float* g = (const float*)q_at(gq, e);
    const float* b = (const float*)q_at(bq, e);

    float4 v = ((const float4*)(X + (size_t)row * DM))[tid];
    __shared__ float sbuf[8];
    int wid = tid >> 5, lane = tid & 31;

    float s = v.x + v.y + v.z + v.w;
#pragma unroll
    for (int o = 16; o > 0; o >>= 1) s += __shfl_xor_sync(0xffffffffu, s, o);
    if (lane == 0) sbuf[wid] = s;
    __syncthreads();
    float mean = (sbuf[0] + sbuf[1] + sbuf[2] + sbuf[3]) * (1.0f / DM);
    __syncthreads();

    float dx0 = v.x - mean, dx1 = v.y - mean, dx2 = v.z - mean, dx3 = v.w - mean;
    float sq = dx0 * dx0 + dx1 * dx1 + dx2 * dx2 + dx3 * dx3;
#pragma unroll
    for (int o = 16; o > 0; o >>= 1) sq += __shfl_xor_sync(0xffffffffu, sq, o);
    if (lane == 0) sbuf[wid] = sq;
    __syncthreads();
    float var = (sbuf[0] + sbuf[1] + sbuf[2] + sbuf[3]) * (1.0f / DM);
    float rstd = rsqrtf(var + LNEPS);

    float4 gg = ((const float4*)g)[tid];
    float4 bb = ((const float4*)b)[tid];
    float4 y;
    y.x = dx0 * rstd * gg.x + bb.x;
    y.y = dx1 * rstd * gg.y + bb.y;
    y.z = dx2 * rstd * gg.z + bb.z;
    y.w = dx3 * rstd * gg.w + bb.w;

    ((float4*)(out + (size_t)row * DM))[tid] = y;
    __nv_bfloat16* ob = outb + (size_t)e * obStr + (size_t)row * DM;
    __nv_bfloat162 a, c;
    a.x = __float2bfloat16_rn(y.x); a.y = __float2bfloat16_rn(y.y);
    c.x = __float2bfloat16_rn(y.z); c.y = __float2bfloat16_rn(y.w);
    ((__nv_bfloat162*)ob)[tid * 2 + 0] = a;
    ((__nv_bfloat162*)ob)[tid * 2 + 1] = c;
}

// ============ LN2 pair + sum ============
__global__ __launch_bounds__(128) void ln2_pair_kernel(
    const float* __restrict__ X, size_t xStr, ulong4 gq, ulong4 bq, float* __restrict__ out)
{
    int row = blockIdx.x;
    int p = blockIdx.y;
    int tid = threadIdx.x;
    int wid = tid >> 5, lane = tid & 31;

    const float* X0 = X + (size_t)(2 * p) * xStr + (size_t)row * DM;
    const float* X1 = X + (size_t)(2 * p + 1) * xStr + (size_t)row * DM;
    float4 v0 = ((const float4*)X0)[tid];
    float4 v1 = ((const float4*)X1)[tid];

    __shared__ float sbuf[16];
    float s0 = v0.x + v0.y + v0.z + v0.w;
    float s1 = v1.x + v1.y + v1.z + v1.w;
#pragma unroll
    for (int o = 16; o > 0; o >>= 1) {
        s0 += __shfl_xor_sync(0xffffffffu, s0, o);
        s1 += __shfl_xor_sync(0xffffffffu, s1, o);
    }
    if (lane == 0) { sbuf[wid] = s0; sbuf[8 + wid] = s1; }
    __syncthreads();
    float mean0 = (sbuf[0] + sbuf[1] + sbuf[2] + sbuf[3]) * (1.0f / DM);
    float mean1 = (sbuf[8] + sbuf[9] + sbuf[10] + sbuf[11]) * (1.0f / DM);
    __syncthreads();

    float a0 = v0.x - mean0, a1 = v0.y - mean0, a2 = v0.z - mean0, a3 = v0.w - mean0;
    float c0 = v1.x - mean1, c1 = v1.y - mean1, c2 = v1.z - mean1, c3 = v1.w - mean1;
    float q0 = a0 * a0 + a1 * a1 + a2 * a2 + a3 * a3;
    float q1 = c0 * c0 + c1 * c1 + c2 * c2 + c3 * c3;
#pragma unroll
    for (int o = 16; o > 0; o >>= 1) {
        q0 += __shfl_xor_sync(0xffffffffu, q0, o);
        q1 += __shfl_xor_sync(0xffffffffu, q1, o);
    }
    if (lane == 0) { sbuf[wid] = q0; sbuf[8 + wid] = q1; }
    __syncthreads();
    float rstd0 = rsqrtf((sbuf[0] + sbuf[1] + sbuf[2] + sbuf[3]) * (1.0f / DM) + LNEPS);
    float rstd1 = rsqrtf((sbuf[8] + sbuf[9] + sbuf[10] + sbuf[11]) * (1.0f / DM) + LNEPS);

    const float* g0 = (const float*)q_at(gq, 2 * p);
    const float* b0 = (const float*)q_at(bq, 2 * p);
    const float* g1 = (const float*)q_at(gq, 2 * p + 1);
    const float* b1 = (const float*)q_at(bq, 2 * p + 1);
    float4 gg0 = ((const float4*)g0)[tid], bb0 = ((const float4*)b0)[tid];
    float4 gg1 = ((const float4*)g1)[tid], bb1 = ((const float4*)b1)[tid];

    float4 y;
    y.x = (a0 * rstd0 * gg0.x + bb0.x) + (c0 * rstd1 * gg1.x + bb1.x);
    y.y = (a1 * rstd0 * gg0.y + bb0.y) + (c1 * rstd1 * gg1.y + bb1.y);
    y.z = (a2 * rstd0 * gg0.z + bb0.z) + (c2 * rstd1 * gg1.z + bb1.z);
    y.w = (a3 * rstd0 * gg0.w + bb0.w) + (c3 * rstd1 * gg1.w + bb1.w);

    ((float4*)(out + (size_t)p * NTOK * DM + (size_t)row * DM))[tid] = y;
}

// ================= tensor-core segment attention: 1 warp per (seg, head, enc) =================
__global__ __launch_bounds__(32) void attn_tc_kernel()
{
    int s = blockIdx.x;
    int h = blockIdx.y;
    int e = blockIdx.z;
    int off = g_offs[s];
    int L = g_offs[s + 1] - off;
    int L16 = (L + 15) & ~15;
    int npairs = L16 >> 4;                 // 16-key groups (== PV k-tiles)

    const int srcQ = e >> 1, halfQ = e & 1;
    const int srcKV_t[4]  = {0, 1, 1, 0};
    const int halfKV_t[4] = {0, 0, 1, 1};
    const int srcKV = srcKV_t[e], halfKV = halfKV_t[e];

    const __nv_bfloat16* Qb = g_Qb4 + (size_t)srcQ  * NTOK * NQ + halfQ  * 512 + h * DKH;
    const __nv_bfloat16* Kb = g_KB4 + (size_t)srcKV * NTOK * NQ + halfKV * 512 + h * DKH;
    const __nv_bfloat16* Vb = g_Vb4 + (size_t)srcKV * NTOK * NQ + halfKV * 512 + h * DKH;

    __shared__ __align__(16) __nv_bfloat16 Ks[96 * 72];
    __shared__ __align__(16) __nv_bfloat16 Vs[96 * 72];
    int lane = threadIdx.x;
    uint4 zz; zz.x = zz.y = zz.z = zz.w = 0u;
    for (int idx = lane; idx < L16 * 8; idx += 32) {
        int j = idx >> 3, c = idx & 7;
        uint4 uk = zz, uv = zz;
        if (j < L) {
            uk = ((const uint4*)(Kb + (size_t)(off + j) * 1024))[c];
            uv = ((const uint4*)(Vb + (size_t)(off + j) * 1024))[c];
        }
        *(uint4*)&Ks[j * 72 + c * 8] = uk;
        *(uint4*)&Vs[j * 72 + c * 8] = uv;
    }
    __syncwarp();

    const uint32_t uK = smem_u32(Ks);
    const uint32_t uV = smem_u32(Vs);
    const int r0 = lane >> 2;
    const int cq = (lane & 3) * 2;
    const int lmrow = lane & 15;
    const int lmhalf = lane >> 4;

    for (int m0 = 0; m0 < L; m0 += 16) {
        // --- Q fragments (direct global bf162 loads) ---
        uint32_t qa[4][4];
        int row1 = off + min(m0 + r0, L - 1);
        int row2 = off + min(m0 + r0 + 8, L - 1);
#pragma unroll
        for (int kf = 0; kf < 4; kf++) {
            qa[kf][0] = *(const uint32_t*)(Qb + (size_t)row1 * 1024 + kf * 16 + cq);
            qa[kf][1] = *(const uint32_t*)(Qb + (size_t)row2 * 1024 + kf * 16 + cq);
            qa[kf][2] = *(const uint32_t*)(Qb + (size_t)row1 * 1024 + kf * 16 + cq + 8);
            qa[kf][3] = *(const uint32_t*)(Qb + (size_t)row2 * 1024 + kf * 16 + cq + 8);
        }

        // --- S = Q K^T ---
        float S[12][4];
#pragma unroll
        for (int t = 0; t < 12; t++) { S[t][0] = S[t][1] = S[t][2] = S[t][3] = 0.f; }
#pragma unroll
        for (int np = 0; np < 6; np++) {
            if (np < npairs) {
#pragma unroll
                for (int kf = 0; kf < 4; kf++) {
                    uint32_t addr = uK + ((np * 16 + lmrow) * 72 + kf * 16 + lmhalf * 8) * 2;
                    uint32_t r0_, r1_, r2_, r3_;
                    ldmatrix_x4(r0_, r1_, r2_, r3_, addr);
                    uint32_t b0[2] = { r0_, r2_ };
                    uint32_t b1[2] = { r1_, r3_ };
                    mma_bf16(S[2 * np + 0], qa[kf], b0);
                    mma_bf16(S[2 * np + 1], qa[kf], b1);
                }
            }
        }

        // --- mask + scale ---
#pragma unroll
        for (int t = 0; t < 12; t++) {
            int c = t * 8 + cq;
            S[t][0] = (c     < L) ? S[t][0] * 0.125f : -INFINITY;
            S[t][1] = (c + 1 < L) ? S[t][1] * 0.125f : -INFINITY;
            S[t][2] = (c     < L) ? S[t][2] * 0.125f : -INFINITY;
            S[t][3] = (c + 1 < L) ? S[t][3] * 0.125f : -INFINITY;
        }

        // --- row max (rows r0 and r0+8) ---
        float mx1 = -INFINITY, mx2 = -INFINITY;
#pragma unroll
        for (int t = 0; t < 12; t++) {
            mx1 = fmaxf(mx1, fmaxf(S[t][0], S[t][1]));
            mx2 = fmaxf(mx2, fmaxf(S[t][2], S[t][3]));
        }
        mx1 = fmaxf(mx1, __shfl_xor_sync(0xffffffffu, mx1, 1));
        mx1 = fmaxf(mx1, __shfl_xor_sync(0xffffffffu, mx1, 2));
        mx2 = fmaxf(mx2, __shfl_xor_sync(0xffffffffu, mx2, 1));
        mx2 = fmaxf(mx2, __shfl_xor_sync(0xffffffffu, mx2, 2));

        // --- exp + row sums ---
        float l1 = 0.f, l2 = 0.f;
#pragma unroll
        for (int t = 0; t < 12; t++) {
            S[t][0] = __expf(S[t][0] - mx1);
            S[t][1] = __expf(S[t][1] - mx1);
            S[t][2] = __expf(S[t][2] - mx2);
            S[t][3] = __expf(S[t][3] - mx2);
            l1 += S[t][0] + S[t][1];
            l2 += S[t][2] + S[t][3];
        }
        l1 += __shfl_xor_sync(0xffffffffu, l1, 1);
        l1 += __shfl_xor_sync(0xffffffffu, l1, 2);
        l2 += __shfl_xor_sync(0xffffffffu, l2, 1);
        l2 += __shfl_xor_sync(0xffffffffu, l2, 2);

        // --- pack P to bf16 A-fragments ---
        uint32_t pf[6][4];
#pragma unroll
        for (int np = 0; np < 6; np++) {
            __nv_bfloat162 h2;
            h2.x = __float2bfloat16_rn(S[2 * np + 0][0]); h2.y = __float2bfloat16_rn(S[2 * np + 0][1]);
            pf[np][0] = *(uint32_t*)&h2;
            h2.x = __float2bfloat16_rn(S[2 * np + 0][2]); h2.y = __float2bfloat16_rn(S[2 * np + 0][3]);
            pf[np][1] = *(uint32_t*)&h2;
            h2.x = __float2bfloat16_rn(S[2 * np + 1][0]); h2.y = __float2bfloat16_rn(S[2 * np + 1][1]);
            pf[np][2] = *(uint32_t*)&h2;
            h2.x = __float2bfloat16_rn(S[2 * np + 1][2]); h2.y = __float2bfloat16_rn(S[2 * np + 1][3]);
            pf[np][3] = *(uint32_t*)&h2;
        }

        // --- O = P V ---
        float O[8][4];
#pragma unroll
        for (int nt = 0; nt < 8; nt++) { O[nt][0] = O[nt][1] = O[nt][2] = O[nt][3] = 0.f; }
#pragma unroll
        for (int kt = 0; kt < 6; kt++) {
            if (kt < npairs) {
#pragma unroll
                for (int nt = 0; nt < 8; nt += 2) {
                    uint32_t addr = uV + ((kt * 16 + lmrow) * 72 + nt * 8 + lmhalf * 8) * 2;
                    uint32_t r0_, r1_, r2_, r3_;
                    ldmatrix_x4_t(r0_, r1_, r2_, r3_, addr);
                    uint32_t b0[2] = { r0_, r1_ };
                    uint32_t b1[2] = { r2_, r3_ };
                    mma_bf16(O[nt + 0], pf[kt], b0);
                    mma_bf16(O[nt + 1], pf[kt], b1);
                }
            }
        }

        // --- write ctx (bf16) ---
        float il1 = 1.0f / l1, il2 = 1.0f / l2;
        int gr1 = m0 + r0, gr2 = gr1 + 8;
        __nv_bfloat16* obase = g_ctxb4 + (size_t)e * NTOK * DM + h * DKH;
        if (gr1 < L) {
            __nv_bfloat16* o1 = obase + (size_t)(off + gr1) * DM;
#pragma unroll
            for (int nt = 0; nt < 8; nt++) {
                __nv_bfloat162 h2;
                h2.x = __float2bfloat16_rn(O[nt][0] * il1);
                h2.y = __float2bfloat16_rn(O[nt][1] * il1);
                *(__nv_bfloat162*)(o1 + nt * 8 + cq) = h2;
            }
        }
        if (gr2 < L) {
            __nv_bfloat16* o2 = obase + (size_t)(off + gr2) * DM;
#pragma unroll
            for (int nt = 0; nt < 8; nt++) {
                __nv_bfloat162 h2;
                h2.x = __float2bfloat16_rn(O[nt][2] * il2);
                h2.y = __float2bfloat16_rn(O[nt][3] * il2);
                *(__nv_bfloat162*)(o2 + nt * 8 + cq) = h2;
            }
        }
    }
}

// ================= host =================
extern "C" void kernel_launch(void* const* d_in, const int* in_sizes, int n_in,
                              void* d_out, int out_size)
{
    const float* vis  = (const float*)d_in[0];
    const float* txt  = (const float*)d_in[1];
    const float* Wq   = (const float*)d_in[2];
    const float* bq   = (const float*)d_in[3];
    const float* Wk   = (const float*)d_in[4];
    const float* bk   = (const float*)d_in[5];
    const float* Wv   = (const float*)d_in[6];
    const float* bv   = (const float*)d_in[7];
    const float* Wo   = (const float*)d_in[8];
    const float* bo   = (const float*)d_in[9];
    const float* g1   = (const float*)d_in[10];
    const float* be1  = (const float*)d_in[11];
    const float* W1   = (const float*)d_in[12];
    const float* b1   = (const float*)d_in[13];
    const float* W2   = (const float*)d_in[14];
    const float* b2   = (const float*)d_in[15];
    const float* g2   = (const float*)d_in[16];
    const float* be2  = (const float*)d_in[17];
    const int*   nobj = (const int*)d_in[18];
    float* out = (float*)d_out;

    float *T14, *OUT14, *BQKV;
    __nv_bfloat16 *QB4, *KB4, *VB4, *VISB, *TXTB, *CTXB4, *OUT1B4, *HB4;
    __nv_bfloat16 *WqkvT4, *WoT, *W1T, *W2T;
    cudaGetSymbolAddress((void**)&T14, g_t14);
    cudaGetSymbolAddress((void**)&OUT14, g_out14);
    cudaGetSymbolAddress((void**)&BQKV, g_bqkv);
    cudaGetSymbolAddress((void**)&QB4, g_Qb4);
    cudaGetSymbolAddress((void**)&KB4, g_KB4);
    cudaGetSymbolAddress((void**)&VB4, g_Vb4);
    cudaGetSymbolAddress((void**)&VISB, g_visb);
    cudaGetSymbolAddress((void**)&TXTB, g_txtb);
    cudaGetSymbolAddress((void**)&CTXB4, g_ctxb4);
    cudaGetSymbolAddress((void**)&OUT1B4, g_out1b4);
    cudaGetSymbolAddress((void**)&HB4, g_hb4);
    cudaGetSymbolAddress((void**)&WqkvT4, g_WqkvT4);
    cudaGetSymbolAddress((void**)&WoT, g_WoT);
    cudaGetSymbolAddress((void**)&W1T, g_W1T);
    cudaGetSymbolAddress((void**)&W2T, g_W2T);

    cudaFuncSetAttribute(gemm_bf16_k<false, false, false, false, true >, cudaFuncAttributeMaxDynamicSharedMemorySize, GEMM_SMEM);
    cudaFuncSetAttribute(gemm_bf16_k<false, true,  true,  false, false>, cudaFuncAttributeMaxDynamicSharedMemorySize, GEMM_SMEM);
    cudaFuncSetAttribute(gemm_bf16_k<true,  false, false, true,  false>, cudaFuncAttributeMaxDynamicSharedMemorySize, GEMM_SMEM);

    auto U4 = [](const void* a, const void* b, const void* c, const void* d) {
        ulong4 u; u.x = (u64)a; u.y = (u64)b; u.z = (u64)c; u.w = (u64)d; return u;
    };

    // 0: mega prepass
    {
        TT tt;
        const size_t BLK = (size_t)DM * DM;
        const u64 qoff[4] = {0, 6 * BLK, 1 * BLK, 7 * BLK};
        const u64 koff[4] = {2 * BLK, 10 * BLK, 8 * BLK, 4 * BLK};
        const u64 voff[4] = {3 * BLK, 11 * BLK, 9 * BLK, 5 * BLK};
        for (int p = 0; p < 4; p++) {
            tt.src[p]      = (u64)(Wq + (size_t)p * BLK); tt.dst[p]      = (u64)(WqkvT4 + qoff[p]);
            tt.src[4 + p]  = (u64)(Wk + (size_t)p * BLK); tt.dst[4 + p]  = (u64)(WqkvT4 + koff[p]);
            tt.src[8 + p]  = (u64)(Wv + (size_t)p * BLK); tt.dst[8 + p]  = (u64)(WqkvT4 + voff[p]);
            tt.src[12 + p] = (u64)(Wo + (size_t)p * BLK); tt.dst[12 + p] = (u64)(WoT + (size_t)p * BLK);
            tt.src[16 + p] = (u64)(W1 + (size_t)p * DM * DI); tt.dst[16 + p] = (u64)(W1T + (size_t)p * DI * DM);
            tt.src[20 + p] = (u64)(W2 + (size_t)p * DI * DM); tt.dst[20 + p] = (u64)(W2T + (size_t)p * DM * DI);
        }
        megaprep_kernel<<<25633, 256>>>(tt, vis, txt, bq, bk, bv, nobj);
    }

    const int MT = (NTOK + 127) / 128;
    const size_t SL = (size_t)NTOK * DM;
    const int perm[4] = {0, 2, 1, 3};
    ulong4 nullq; nullq.x = nullq.y = nullq.z = nullq.w = 0;

    // 1: fused QKV GEMM (Q bf16 / K bf16 / V bf16 routed per CTA)
    {
        ulong4 Aq = U4(VISB, TXTB, nullptr, nullptr);
        ulong4 Bq = U4(WqkvT4, WqkvT4 + (size_t)NQKV * DM, nullptr, nullptr);
        ulong4 bq_ = U4(BQKV, BQKV + NQKV, nullptr, nullptr);
        gemm_bf16_k<false, false, false, false, true><<<dim3(NQKV / 128, MT, 2), 256, GEMM_SMEM>>>(
            Aq, Bq, bq_, nullq, (float*)VB4, 0, QB4, (size_t)NTOK * NQ, KB4, NTOK, DM, NQKV);
    }

    // 2: tensor-core attention
    attn_tc_kernel<<<dim3(BATCH, NH, 4), 32>>>();

    // 3: proj + residual
    {
        const size_t BLK = (size_t)DM * DM;
        ulong4 Aq = U4(CTXB4, CTXB4 + SL, CTXB4 + 2 * SL, CTXB4 + 3 * SL);
        ulong4 Bq = U4(WoT + perm[0] * BLK, WoT + perm[1] * BLK, WoT + perm[2] * BLK, WoT + perm[3] * BLK);
        ulong4 bq_ = U4(bo + perm[0] * DM, bo + perm[1] * DM, bo + perm[2] * DM, bo + perm[3] * DM);
        ulong4 Rq = U4(vis, vis, txt, txt);
        gemm_bf16_k<false, true, true, false, false><<<dim3(DM / 128, MT, 4), 256, GEMM_SMEM>>>(
            Aq, Bq, bq_, Rq, T14, SL, nullptr, 0, nullptr, NTOK, DM, DM);
    }
    // 4: LN1
    {
        ulong4 gq = U4(g1 + perm[0] * DM, g1 + perm[1] * DM, g1 + perm[2] * DM, g1 + perm[3] * DM);
        ulong4 bq_ = U4(be1 + perm[0] * DM, be1 + perm[1] * DM, be1 + perm[2] * DM, be1 + perm[3] * DM);
        ln1_kernel<<<dim3(NTOK, 4), 128>>>(T14, SL, gq, bq_, OUT14, SL, OUT1B4, SL);
    }
    // 5: FFN1
    {
        ulong4 Aq = U4(OUT1B4, OUT1B4 + SL, OUT1B4 + 2 * SL, OUT1B4 + 3 * SL);
        const size_t WB = (size_t)DI * DM;
        ulong4 Bq = U4(W1T + perm[0] * WB, W1T + perm[1] * WB, W1T + perm[2] * WB, W1T + perm[3] * WB);
        ulong4 bq_ = U4(b1 + perm[0] * DI, b1 + perm[1] * DI, b1 + perm[2] * DI, b1 + perm[3] * DI);
        gemm_bf16_k<true, false, false, true, false><<<dim3(DI / 128, MT, 4), 256, GEMM_SMEM>>>(
            Aq, Bq, bq_, nullq, nullptr, 0, HB4, (size_t)NTOK * DI, nullptr, NTOK, DM, DI);
    }
    // 6: FFN2 + residual
    {
        const size_t HL = (size_t)NTOK * DI;
        ulong4 Aq = U4(HB4, HB4 + HL, HB4 + 2 * HL, HB4 + 3 * HL);
        const size_t WB = (size_t)DM * DI;
        ulong4 Bq = U4(W2T + perm[0] * WB, W2T + perm[1] * WB, W2T + perm[2] * WB, W2T + perm[3] * WB);
        ulong4 bq_ = U4(b2 + perm[0] * DM, b2 + perm[1] * DM, b2 + perm[2] * DM, b2 + perm[3] * DM);
        ulong4 Rq = U4(OUT14, OUT14 + SL, OUT14 + 2 * SL, OUT14 + 3 * SL);
        gemm_bf16_k<false, true, true, false, false><<<dim3(DM / 128, MT, 4), 256, GEMM_SMEM>>>(
            Aq, Bq, bq_, Rq, T14, SL, nullptr, 0, nullptr, NTOK, DI, DM);
    }
    // 7: LN2 + sum -> d_out
    {
        ulong4 gq = U4(g2 + perm[0] * DM, g2 + perm[1] * DM, g2 + perm[2] * DM, g2 + perm[3] * DM);
        ulong4 bq_ = U4(be2 + perm[0] * DM, be2 + perm[1] * DM, be2 + perm[2] * DM, be2 + perm[3] * DM);
        ln2_pair_kernel<<<dim3(NTOK, 2), 128>>>(T14, SL, gq, bq_, out);
    }
}

// round 14
// speedup vs baseline: 1.3445x; 1.0012x over previous
#include <cuda_runtime.h>
#include <cuda_bf16.h>
#include <math.h>
#include <stdint.h>

#define NTOK 13320
#define BATCH 240
#define DM 512
#define DI 2048
#define NH 8
#define DKH 64
#define LNEPS 1e-5f
#define NQ 1024
#define NKV 2048
#define NQKV 3072

typedef unsigned long long u64;

// ================= scratch (static device globals; no allocation) =================
__device__ float g_t14  [4 * NTOK * DM];
__device__ float g_out14[4 * NTOK * DM];
__device__ int   g_offs[BATCH + 1];
__device__ float g_bqkv[2 * NQKV];

__device__ __nv_bfloat16 g_Qb4[2 * NTOK * NQ];
__device__ __nv_bfloat16 g_KB4[2 * NTOK * NQ];
__device__ __nv_bfloat16 g_Vb4[2 * NTOK * NQ];

__device__ __nv_bfloat16 g_visb  [NTOK * DM];
__device__ __nv_bfloat16 g_txtb  [NTOK * DM];
__device__ __nv_bfloat16 g_ctxb4 [4 * NTOK * DM];
__device__ __nv_bfloat16 g_out1b4[4 * NTOK * DM];
__device__ __nv_bfloat16 g_hb4   [4 * NTOK * DI];

__device__ __nv_bfloat16 g_WqkvT4[2 * NQKV * DM];
__device__ __nv_bfloat16 g_WoT  [4 * DM * DM];
__device__ __nv_bfloat16 g_W1T  [4 * DI * DM];
__device__ __nv_bfloat16 g_W2T  [4 * DM * DI];

// ================= helpers =================
__device__ __forceinline__ uint32_t smem_u32(const void* p) {
    uint32_t a;
    asm("{ .reg .u64 t; cvta.to.shared.u64 t, %1; cvt.u32.u64 %0, t; }" : "=r"(a) : "l"(p));
    return a;
}
__device__ __forceinline__ void cp_async16(uint32_t dst, const void* src) {
    asm volatile("cp.async.cg.shared.global [%0], [%1], 16;" :: "r"(dst), "l"(src));
}
#define CP_COMMIT() asm volatile("cp.async.commit_group;" ::: "memory")
#define CP_WAIT(n)  asm volatile("cp.async.wait_group %0;" :: "n"(n) : "memory")

__device__ __forceinline__ void ldmatrix_x4(uint32_t& r0, uint32_t& r1, uint32_t& r2, uint32_t& r3, uint32_t addr) {
    asm volatile("ldmatrix.sync.aligned.m8n8.x4.shared.b16 {%0,%1,%2,%3}, [%4];"
        : "=r"(r0), "=r"(r1), "=r"(r2), "=r"(r3) : "r"(addr));
}
__device__ __forceinline__ void ldmatrix_x4_t(uint32_t& r0, uint32_t& r1, uint32_t& r2, uint32_t& r3, uint32_t addr) {
    asm volatile("ldmatrix.sync.aligned.m8n8.x4.trans.shared.b16 {%0,%1,%2,%3}, [%4];"
        : "=r"(r0), "=r"(r1), "=r"(r2), "=r"(r3) : "r"(addr));
}
__device__ __forceinline__ void mma_bf16(float* d, const uint32_t* a, const uint32_t* b) {
    asm volatile("mma.sync.aligned.m16n8k16.row.col.f32.bf16.bf16.f32 "
        "{%0,%1,%2,%3}, {%4,%5,%6,%7}, {%8,%9}, {%0,%1,%2,%3};"
        : "+f"(d[0]), "+f"(d[1]), "+f"(d[2]), "+f"(d[3])
        : "r"(a[0]), "r"(a[1]), "r"(a[2]), "r"(a[3]), "r"(b[0]), "r"(b[1]));
}
__device__ __forceinline__ u64 q_at(const ulong4& q, int z) {
    u64 v;
    switch (z) { case 0: v = q.x; break; case 1: v = q.y; break;
                 case 2: v = q.z; break; default: v = q.w; }
    return v;
}

// ========== fused mega-prepass ==========
#define NC4 (NTOK * DM / 4)
struct TT { u64 src[24]; u64 dst[24]; };

__global__ __launch_bounds__(256) void megaprep_kernel(
    TT tt,
    const float* __restrict__ Vsrc, const float* __restrict__ Tsrc,
    const float* __restrict__ bq, const float* __restrict__ bk, const float* __restrict__ bv,
    const int* __restrict__ nobj)
{
    int bid = blockIdx.x;
    int tid = threadIdx.x;
    if (bid < 13320) {
        int i = bid * 256 + tid;
        const float* X; __nv_bfloat16* Y; int j;
        if (i < NC4) { X = Vsrc; Y = g_visb; j = i; }
        else { X = Tsrc; Y = g_txtb; j = i - NC4; }
        float4 v = ((const float4*)X)[j];
        __nv_bfloat162 a, b;
        a.x = __float2bfloat16_rn(v.x); a.y = __float2bfloat16_rn(v.y);
        b.x = __float2bfloat16_rn(v.z); b.y = __float2bfloat16_rn(v.w);
        ((__nv_bfloat162*)Y)[j * 2 + 0] = a;
        ((__nv_bfloat162*)Y)[j * 2 + 1] = b;
    } else if (bid < 13344) {
        int i = (bid - 13320) * 256 + tid;
        int src = i / NQKV, r = i % NQKV;
        float val;
        if (r < 1024) {
            int half = (r >> 9) & 1, j = r & 511;
            int p = src + 2 * half;
            val = bq[p * DM + j];
        } else {
            int rr = r - 1024;
            int half = rr >> 10, part = (rr >> 9) & 1, j = rr & 511;
            const int pt[2][2] = { {0, 3}, {2, 1} };
            int p = pt[src][half];
            val = (part ? bv : bk)[p * DM + j];
        }
        g_bqkv[i] = val;
    } else if (bid == 13344) {
        if (tid == 0) {
            int s = 0;
            for (int i = 0; i < BATCH; i++) { g_offs[i] = s; s += nobj[i]; }
            g_offs[BATCH] = s;
        }
    } else {
        int b2 = bid - 13345;
        int e, t, R, C;
        if (b2 < 4096)      { e = b2 >> 8;               t = b2 & 255;            R = 512;  C = 512;  }
        else if (b2 < 8192) { e = 16 + ((b2 - 4096) >> 10); t = (b2 - 4096) & 1023; R = 512;  C = 2048; }
        else                { e = 20 + ((b2 - 8192) >> 10); t = (b2 - 8192) & 1023; R = 2048; C = 512;  }
        const float* Sp = (const float*)tt.src[e];
        __nv_bfloat16* Dp = (__nv_bfloat16*)tt.dst[e];
        int tpr = C >> 5;
        int bx = (t % tpr) * 32, by = (t / tpr) * 32;
        int tx = tid & 31, ty = tid >> 5;

        __shared__ float tile[32][33];
        int x = bx + tx;
#pragma unroll
        for (int yy = ty; yy < 32; yy += 8)
            tile[yy][tx] = Sp[(size_t)(by + yy) * C + x];
        __syncthreads();
        int x2 = by + tx;
#pragma unroll
        for (int yy = ty; yy < 32; yy += 8)
            Dp[(size_t)(bx + yy) * R + x2] = __float2bfloat16_rn(tile[tx][yy]);
    }
}

// ======== bf16 mma.sync GEMM, 128x128 tile (8 warps of 64x32), BK=64, 3-stage ========
#define LDSH 72
#define TILEB (128 * LDSH * 2)
#define STAGEB (2 * TILEB)
#define NSTAGE 3
#define GEMM_SMEM (NSTAGE * STAGEB)        // 110592

template <bool RELU, bool RESID, bool OF32, bool OBF16, bool OQKV>
__global__ __launch_bounds__(256, 2) void gemm_bf16_k(
    ulong4 Aq, ulong4 Btq, ulong4 biasq, ulong4 Rq,
    float* __restrict__ C, size_t cStr, __nv_bfloat16* __restrict__ Cb, size_t cbStr,
    __nv_bfloat16* __restrict__ Cb2,
    int M, int K, int N)
{
    extern __shared__ char smem[];
    const uint32_t sb = smem_u32(smem);
    const int tid = threadIdx.x;
    const int lane = tid & 31;
    const int wid = tid >> 5;
    const int z = blockIdx.z;
    const int m0 = blockIdx.y * 128;
    const int n0 = blockIdx.x * 128;
    const int warp_m = wid & 1;
    const int warp_n = wid >> 1;

    const __nv_bfloat16* A  = (const __nv_bfloat16*)q_at(Aq, z);
    const __nv_bfloat16* Bt = (const __nv_bfloat16*)q_at(Btq, z);
    const float* bias = (const float*)q_at(biasq, z);
    const float* R = RESID ? (const float*)q_at(Rq, z) : nullptr;
    if (OF32)  C  += (size_t)z * cStr;
    __nv_bfloat16* Vb2 = OQKV ? ((__nv_bfloat16*)C) + (size_t)z * cbStr : nullptr;
    if (OBF16 || OQKV) Cb  += (size_t)z * cbStr;
    __nv_bfloat16* Kb2 = OQKV ? Cb2 + (size_t)z * cbStr : nullptr;

    float acc[4][4][4];
#pragma unroll
    for (int i = 0; i < 4; i++)
#pragma unroll
        for (int j = 0; j < 4; j++)
#pragma unroll
            for (int r = 0; r < 4; r++) acc[i][j][r] = 0.f;

    const __nv_bfloat16* aptr[4];
    const __nv_bfloat16* bptr[4];
    uint32_t adst[4], bdst[4];
#pragma unroll
    for (int i = 0; i < 4; i++) {
        int c = tid + i * 256;
        int row = c >> 3, c16 = c & 7;
        int gr = m0 + row; gr = gr < M ? gr : M - 1;
        aptr[i] = A + (size_t)gr * K + c16 * 8;
        bptr[i] = Bt + (size_t)(n0 + row) * K + c16 * 8;
        adst[i] = row * (LDSH * 2) + c16 * 16;
        bdst[i] = TILEB + row * (LDSH * 2) + c16 * 16;
    }

    const int lmrow  = lane & 15;
    const int lmbyte = (lane >> 4) * 16;
    const int KT = K >> 6;

    auto load_stage_at = [&](uint32_t base, int k0) {
#pragma unroll
        for (int i = 0; i < 4; i++)
            cp_async16(base + adst[i], aptr[i] + k0);
#pragma unroll
        for (int i = 0; i < 4; i++)
            cp_async16(base + bdst[i], bptr[i] + k0);
        CP_COMMIT();
    };

    load_stage_at(sb, 0);
    load_stage_at(sb + STAGEB, 64);

    uint32_t cons = sb;
    uint32_t loadb = sb + 2 * STAGEB;

#pragma unroll 1
    for (int it = 0; it < KT; it++) {
        CP_WAIT(NSTAGE - 2);
        __syncthreads();
        int nk = it + NSTAGE - 1;
        if (nk < KT) load_stage_at(loadb, nk << 6);
        else CP_COMMIT();

        const uint32_t ab = cons;
        const uint32_t bb = cons + TILEB;

#pragma unroll
        for (int kk = 0; kk < 4; kk++) {
            uint32_t af[4][4];
#pragma unroll
            for (int mi = 0; mi < 4; mi++) {
                uint32_t addr = ab + (warp_m * 64 + mi * 16 + lmrow) * (LDSH * 2) + kk * 32 + lmbyte;
                ldmatrix_x4(af[mi][0], af[mi][1], af[mi][2], af[mi][3], addr);
            }
            uint32_t bf[4][2];
#pragma unroll
            for (int t = 0; t < 2; t++) {
                uint32_t addr = bb + (warp_n * 32 + t * 16 + lmrow) * (LDSH * 2) + kk * 32 + lmbyte;
                uint32_t r0, r1, r2, r3;
                ldmatrix_x4(r0, r1, r2, r3, addr);
                bf[t * 2 + 0][0] = r0; bf[t * 2 + 0][1] = r2;
                bf[t * 2 + 1][0] = r1; bf[t * 2 + 1][1] = r3;
            }
#pragma unroll
            for (int mi = 0; mi < 4; mi++)
#pragma unroll
                for (int nj = 0; nj < 4; nj++)
                    mma_bf16(acc[mi][nj], af[mi], bf[nj]);
        }

        loadb = cons;
        cons += STAGEB;
        if (cons == sb + NSTAGE * STAGEB) cons = sb;
    }

    const bool isQ = OQKV && (n0 < 1024);
    const int c2b = n0 - 1024;
    const bool isK = OQKV && !isQ && (((c2b >> 9) & 1) == 0);

    const int er = lane >> 2;
    const int ec = (lane & 3) * 2;
#pragma unroll
    for (int mi = 0; mi < 4; mi++) {
#pragma unroll
        for (int half = 0; half < 2; half++) {
            int row = m0 + warp_m * 64 + mi * 16 + half * 8 + er;
            if (row >= M) continue;
#pragma unroll
            for (int nj = 0; nj < 4; nj++) {
                int col = n0 + warp_n * 32 + nj * 8 + ec;
                float2 v;
                v.x = acc[mi][nj][half * 2 + 0] + bias[col + 0];
                v.y = acc[mi][nj][half * 2 + 1] + bias[col + 1];
                if (RESID) {
                    const float2 rv = *(const float2*)(R + (size_t)row * N + col);
                    v.x += rv.x; v.y += rv.y;
                }
                if (RELU) { v.x = fmaxf(v.x, 0.f); v.y = fmaxf(v.y, 0.f); }
                if (OQKV) {
                    __nv_bfloat162 h2;
                    h2.x = __float2bfloat16_rn(v.x);
                    h2.y = __float2bfloat16_rn(v.y);
                    if (isQ) {
                        *(__nv_bfloat162*)(Cb + (size_t)row * 1024 + col) = h2;
                    } else {
                        int colk = ((c2b >> 10) << 9) + ((col - 1024) & 511);
                        if (isK)
                            *(__nv_bfloat162*)(Kb2 + (size_t)row * 1024 + colk) = h2;
                        else
                            *(__nv_bfloat162*)(Vb2 + (size_t)row * 1024 + colk) = h2;
                    }
                } else {
                    if (OF32)
                        *(float2*)(C + (size_t)row * N + col) = v;
                    if (OBF16) {
                        __nv_bfloat162 h2;
                        h2.x = __float2bfloat16_rn(v.x);
                        h2.y = __float2bfloat16_rn(v.y);
                        *(__nv_bfloat162*)(Cb + (size_t)row * N + col) = h2;
                    }
                }
            }
        }
    }
}

// ================= LN1: warp-per-row (8 rows / 256-thr block) =================
__global__ __launch_bounds__(256) void ln1_kernel(
    const float* __restrict__ X, size_t xStr, ulong4 gq, ulong4 bq,
    float* __restrict__ out, size_t oStr, __nv_bfloat16* __restrict__ outb, size_t obStr)
{
    int wid = threadIdx.x >> 5;
    int lane = threadIdx.x & 31;
    int row = blockIdx.x * 8 + wid;
    int e = blockIdx.y;
    const float* Xr = X + (size_t)e * xStr + (size_t)row * DM;
    const float* g = (const float*)q_at(gq, e);
    const float* b = (const float*)q_at(bq, e);

    float4 v[4];
#pragma unroll
    for (int k = 0; k < 4; k++) v[k] = ((const float4*)Xr)[lane + 32 * k];

    float s = 0.f;
#pragma unroll
    for (int k = 0; k < 4; k++) s += (v[k].x + v[k].y) + (v[k].z + v[k].w);
#pragma unroll
    for (int o = 16; o > 0; o >>= 1) s += __shfl_xor_sync(0xffffffffu, s, o);
    float mean = s * (1.0f / DM);

    float sq = 0.f;
#pragma unroll
    for (int k = 0; k < 4; k++) {
        v[k].x -= mean; v[k].y -= mean; v[k].z -= mean; v[k].w -= mean;
        sq += v[k].x * v[k].x + v[k].y * v[k].y + v[k].z * v[k].z + v[k].w * v[k].w;
    }
#pragma unroll
    for (int o = 16; o > 0; o >>= 1) sq += __shfl_xor_sync(0xffffffffu, sq, o);
    float rstd = rsqrtf(sq * (1.0f / DM) + LNEPS);

    float* outr = out + (size_t)e * oStr + (size_t)row * DM;
    __nv_bfloat16* ob = outb + (size_t)e * obStr + (size_t)row * DM;
#pragma unroll
    for (int k = 0; k < 4; k++) {
        float4 gg = ((const float4*)g)[lane + 32 * k];
        float4 bb = ((const float4*)b)[lane + 32 * k];
        float4 y;
        y.x = v[k].x * rstd * gg.x + bb.x;
        y.y = v[k].y * rstd * gg.y + bb.y;
        y.z = v[k].z * rstd * gg.z + bb.z;
        y.w = v[k].w * rstd * gg.w + bb.w;
        ((float4*)outr)[lane + 32 * k] = y;
        __nv_bfloat162 a, c;
        a.x = __float2bfloat16_rn(y.x); a.y = __float2bfloat16_rn(y.y);
        c.x = __float2bfloat16_rn(y.z); c.y = __float2bfloat16_rn(y.w);
        ((__nv_bfloat162*)ob)[(lane + 32 * k) * 2 + 0] = a;
        ((__nv_bfloat162*)ob)[(lane + 32 * k) * 2 + 1] = c;
    }
}

// ============ LN2 pair + sum: warp-per-row ============
__global__ __launch_bounds__(256) void ln2_pair_kernel(
    const float* __restrict__ X, size_t xStr, ulong4 gq, ulong4 bq, float* __restrict__ out)
{
    int wid = threadIdx.x >> 5;
    int lane = threadIdx.x & 31;
    int row = blockIdx.x * 8 + wid;
    int p = blockIdx.y;

    const float* X0 = X + (size_t)(2 * p) * xStr + (size_t)row * DM;
    const float* X1 = X + (size_t)(2 * p + 1) * xStr + (size_t)row * DM;
    float4 v0[4], v1[4];
#pragma unroll
    for (int k = 0; k < 4; k++) {
        v0[k] = ((const float4*)X0)[lane + 32 * k];
        v1[k] = ((const float4*)X1)[lane + 32 * k];
    }

    float s0 = 0.f, s1 = 0.f;
#pragma unroll
    for (int k = 0; k < 4; k++) {
        s0 += (v0[k].x + v0[k].y) + (v0[k].z + v0[k].w);
        s1 += (v1[k].x + v1[k].y) + (v1[k].z + v1[k].w);
    }
#pragma unroll
    for (int o = 16; o > 0; o >>= 1) {
        s0 += __shfl_xor_sync(0xffffffffu, s0, o);
        s1 += __shfl_xor_sync(0xffffffffu, s1, o);
    }
    float mean0 = s0 * (1.0f / DM);
    float mean1 = s1 * (1.0f / DM);

    float q0 = 0.f, q1 = 0.f;
#pragma unroll
    for (int k = 0; k < 4; k++) {
        v0[k].x -= mean0; v0[k].y -= mean0; v0[k].z -= mean0; v0[k].w -= mean0;
        v1[k].x -= mean1; v1[k].y -= mean1; v1[k].z -= mean1; v1[k].w -= mean1;
        q0 += v0[k].x * v0[k].x + v0[k].y * v0[k].y + v0[k].z * v0[k].z + v0[k].w * v0[k].w;
        q1 += v1[k].x * v1[k].x + v1[k].y * v1[k].y + v1[k].z * v1[k].z + v1[k].w * v1[k].w;
    }
#pragma unroll
    for (int o = 16; o > 0; o >>= 1) {
        q0 += __shfl_xor_sync(0xffffffffu, q0, o);
        q1 += __shfl_xor_sync(0xffffffffu, q1, o);
    }
    float rstd0 = rsqrtf(q0 * (1.0f / DM) + LNEPS);
    float rstd1 = rsqrtf(q1 * (1.0f / DM) + LNEPS);

    const float* g0 = (const float*)q_at(gq, 2 * p);
    const float* b0 = (const float*)q_at(bq, 2 * p);
    const float* g1 = (const float*)q_at(gq, 2 * p + 1);
    const float* b1 = (const float*)q_at(bq, 2 * p + 1);

    float* outr = out + (size_t)p * NTOK * DM + (size_t)row * DM;
#pragma unroll
    for (int k = 0; k < 4; k++) {
        float4 gg0 = ((const float4*)g0)[lane + 32 * k], bb0 = ((const float4*)b0)[lane + 32 * k];
        float4 gg1 = ((const float4*)g1)[lane + 32 * k], bb1 = ((const float4*)b1)[lane + 32 * k];
        float4 y;
        y.x = (v0[k].x * rstd0 * gg0.x + bb0.x) + (v1[k].x * rstd1 * gg1.x + bb1.x);
        y.y = (v0[k].y * rstd0 * gg0.y + bb0.y) + (v1[k].y * rstd1 * gg1.y + bb1.y);
        y.z = (v0[k].z * rstd0 * gg0.z + bb0.z) + (v1[k].z * rstd1 * gg1.z + bb1.z);
        y.w = (v0[k].w * rstd0 * gg0.w + bb0.w) + (v1[k].w * rstd1 * gg1.w + bb1.w);
        ((float4*)outr)[lane + 32 * k] = y;
    }
}

// ================= tensor-core segment attention: 1 warp per (seg, head, enc) =================
__global__ __launch_bounds__(32) void attn_tc_kernel()
{
    int s = blockIdx.x;
    int h = blockIdx.y;
    int e = blockIdx.z;
    int off = g_offs[s];
    int L = g_offs[s + 1] - off;
    int L16 = (L + 15) & ~15;
    int npairs = L16 >> 4;

    const int srcQ = e >> 1, halfQ = e & 1;
    const int srcKV_t[4]  = {0, 1, 1, 0};
    const int halfKV_t[4] = {0, 0, 1, 1};
    const int srcKV = srcKV_t[e], halfKV = halfKV_t[e];

    const __nv_bfloat16* Qb = g_Qb4 + (size_t)srcQ  * NTOK * NQ + halfQ  * 512 + h * DKH;
    const __nv_bfloat16* Kb = g_KB4 + (size_t)srcKV * NTOK * NQ + halfKV * 512 + h * DKH;
    const __nv_bfloat16* Vb = g_Vb4 + (size_t)srcKV * NTOK * NQ + halfKV * 512 + h * DKH;

    __shared__ __align__(16) __nv_bfloat16 Ks[96 * 72];
    __shared__ __align__(16) __nv_bfloat16 Vs[96 * 72];
    int lane = threadIdx.x;
    uint4 zz; zz.x = zz.y = zz.z = zz.w = 0u;
    for (int idx = lane; idx < L16 * 8; idx += 32) {
        int j = idx >> 3, c = idx & 7;
        uint4 uk = zz, uv = zz;
        if (j < L) {
            uk = ((const uint4*)(Kb + (size_t)(off + j) * 1024))[c];
            uv = ((const uint4*)(Vb + (size_t)(off + j) * 1024))[c];
        }
        *(uint4*)&Ks[j * 72 + c * 8] = uk;
        *(uint4*)&Vs[j * 72 + c * 8] = uv;
    }
    __syncwarp();

    const uint32_t uK = smem_u32(Ks);
    const uint32_t uV = smem_u32(Vs);
    const int r0 = lane >> 2;
    const int cq = (lane & 3) * 2;
    const int lmrow = lane & 15;
    const int lmhalf = lane >> 4;

    for (int m0 = 0; m0 < L; m0 += 16) {
        uint32_t qa[4][4];
        int row1 = off + min(m0 + r0, L - 1);
        int row2 = off + min(m0 + r0 + 8, L - 1);
#pragma unroll
        for (int kf = 0; kf < 4; kf++) {
            qa[kf][0] = *(const uint32_t*)(Qb + (size_t)row1 * 1024 + kf * 16 + cq);
            qa[kf][1] = *(const uint32_t*)(Qb + (size_t)row2 * 1024 + kf * 16 + cq);
            qa[kf][2] = *(const uint32_t*)(Qb + (size_t)row1 * 1024 + kf * 16 + cq + 8);
            qa[kf][3] = *(const uint32_t*)(Qb + (size_t)row2 * 1024 + kf * 16 + cq + 8);
        }

        float S[12][4];
#pragma unroll
        for (int t = 0; t < 12; t++) { S[t][0] = S[t][1] = S[t][2] = S[t][3] = 0.f; }
#pragma unroll
        for (int np = 0; np < 6; np++) {
            if (np < npairs) {
#pragma unroll
                for (int kf = 0; kf < 4; kf++) {
                    uint32_t addr = uK + ((np * 16 + lmrow) * 72 + kf * 16 + lmhalf * 8) * 2;
                    uint32_t r0_, r1_, r2_, r3_;
                    ldmatrix_x4(r0_, r1_, r2_, r3_, addr);
                    uint32_t b0[2] = { r0_, r2_ };
                    uint32_t b1[2] = { r1_, r3_ };
                    mma_bf16(S[2 * np + 0], qa[kf], b0);
                    mma_bf16(S[2 * np + 1], qa[kf], b1);
                }
            }
        }

#pragma unroll
        for (int t = 0; t < 12; t++) {
            int c = t * 8 + cq;
            S[t][0] = (c     < L) ? S[t][0] * 0.125f : -INFINITY;
            S[t][1] = (c + 1 < L) ? S[t][1] * 0.125f : -INFINITY;
            S[t][2] = (c     < L) ? S[t][2] * 0.125f : -INFINITY;
            S[t][3] = (c + 1 < L) ? S[t][3] * 0.125f : -INFINITY;
        }

        float mx1 = -INFINITY, mx2 = -INFINITY;
#pragma unroll
        for (int t = 0; t < 12; t++) {
            mx1 = fmaxf(mx1, fmaxf(S[t][0], S[t][1]));
            mx2 = fmaxf(mx2, fmaxf(S[t][2], S[t][3]));
        }
        mx1 = fmaxf(mx1, __shfl_xor_sync(0xffffffffu, mx1, 1));
        mx1 = fmaxf(mx1, __shfl_xor_sync(0xffffffffu, mx1, 2));
        mx2 = fmaxf(mx2, __shfl_xor_sync(0xffffffffu, mx2, 1));
        mx2 = fmaxf(mx2, __shfl_xor_sync(0xffffffffu, mx2, 2));

        float l1 = 0.f, l2 = 0.f;
#pragma unroll
        for (int t = 0; t < 12; t++) {
            S[t][0] = __expf(S[t][0] - mx1);
            S[t][1] = __expf(S[t][1] - mx1);
            S[t][2] = __expf(S[t][2] - mx2);
            S[t][3] = __expf(S[t][3] - mx2);
            l1 += S[t][0] + S[t][1];
            l2 += S[t][2] + S[t][3];
        }
        l1 += __shfl_xor_sync(0xffffffffu, l1, 1);
        l1 += __shfl_xor_sync(0xffffffffu, l1, 2);
        l2 += __shfl_xor_sync(0xffffffffu, l2, 1);
        l2 += __shfl_xor_sync(0xffffffffu, l2, 2);

        uint32_t pf[6][4];
#pragma unroll
        for (int np = 0; np < 6; np++) {
            __nv_bfloat162 h2;
            h2.x = __float2bfloat16_rn(S[2 * np + 0][0]); h2.y = __float2bfloat16_rn(S[2 * np + 0][1]);
            pf[np][0] = *(uint32_t*)&h2;
            h2.x = __float2bfloat16_rn(S[2 * np + 0][2]); h2.y = __float2bfloat16_rn(S[2 * np + 0][3]);
            pf[np][1] = *(uint32_t*)&h2;
            h2.x = __float2bfloat16_rn(S[2 * np + 1][0]); h2.y = __float2bfloat16_rn(S[2 * np + 1][1]);
            pf[np][2] = *(uint32_t*)&h2;
            h2.x = __float2bfloat16_rn(S[2 * np + 1][2]); h2.y = __float2bfloat16_rn(S[2 * np + 1][3]);
            pf[np][3] = *(uint32_t*)&h2;
        }

        float O[8][4];
#pragma unroll
        for (int nt = 0; nt < 8; nt++) { O[nt][0] = O[nt][1] = O[nt][2] = O[nt][3] = 0.f; }
#pragma unroll
        for (int kt = 0; kt < 6; kt++) {
            if (kt < npairs) {
#pragma unroll
                for (int nt = 0; nt < 8; nt += 2) {
                    uint32_t addr = uV + ((kt * 16 + lmrow) * 72 + nt * 8 + lmhalf * 8) * 2;
                    uint32_t r0_, r1_, r2_, r3_;
                    ldmatrix_x4_t(r0_, r1_, r2_, r3_, addr);
                    uint32_t b0[2] = { r0_, r1_ };
                    uint32_t b1[2] = { r2_, r3_ };
                    mma_bf16(O[nt + 0], pf[kt], b0);
                    mma_bf16(O[nt + 1], pf[kt], b1);
                }
            }
        }

        float il1 = 1.0f / l1, il2 = 1.0f / l2;
        int gr1 = m0 + r0, gr2 = gr1 + 8;
        __nv_bfloat16* obase = g_ctxb4 + (size_t)e * NTOK * DM + h * DKH;
        if (gr1 < L) {
            __nv_bfloat16* o1 = obase + (size_t)(off + gr1) * DM;
#pragma unroll
            for (int nt = 0; nt < 8; nt++) {
                __nv_bfloat162 h2;
                h2.x = __float2bfloat16_rn(O[nt][0] * il1);
                h2.y = __float2bfloat16_rn(O[nt][1] * il1);
                *(__nv_bfloat162*)(o1 + nt * 8 + cq) = h2;
            }
        }
        if (gr2 < L) {
            __nv_bfloat16* o2 = obase + (size_t)(off + gr2) * DM;
#pragma unroll
            for (int nt = 0; nt < 8; nt++) {
                __nv_bfloat162 h2;
                h2.x = __float2bfloat16_rn(O[nt][2] * il2);
                h2.y = __float2bfloat16_rn(O[nt][3] * il2);
                *(__nv_bfloat162*)(o2 + nt * 8 + cq) = h2;
            }
        }
    }
}

// ================= host =================
extern "C" void kernel_launch(void* const* d_in, const int* in_sizes, int n_in,
                              void* d_out, int out_size)
{
    const float* vis  = (const float*)d_in[0];
    const float* txt  = (const float*)d_in[1];
    const float* Wq   = (const float*)d_in[2];
    const float* bq   = (const float*)d_in[3];
    const float* Wk   = (const float*)d_in[4];
    const float* bk   = (const float*)d_in[5];
    const float* Wv   = (const float*)d_in[6];
    const float* bv   = (const float*)d_in[7];
    const float* Wo   = (const float*)d_in[8];
    const float* bo   = (const float*)d_in[9];
    const float* g1   = (const float*)d_in[10];
    const float* be1  = (const float*)d_in[11];
    const float* W1   = (const float*)d_in[12];
    const float* b1   = (const float*)d_in[13];
    const float* W2   = (const float*)d_in[14];
    const float* b2   = (const float*)d_in[15];
    const float* g2   = (const float*)d_in[16];
    const float* be2  = (const float*)d_in[17];
    const int*   nobj = (const int*)d_in[18];
    float* out = (float*)d_out;

    float *T14, *OUT14, *BQKV;
    __nv_bfloat16 *QB4, *KB4, *VB4, *VISB, *TXTB, *CTXB4, *OUT1B4, *HB4;
    __nv_bfloat16 *WqkvT4, *WoT, *W1T, *W2T;
    cudaGetSymbolAddress((void**)&T14, g_t14);
    cudaGetSymbolAddress((void**)&OUT14, g_out14);
    cudaGetSymbolAddress((void**)&BQKV, g_bqkv);
    cudaGetSymbolAddress((void**)&QB4, g_Qb4);
    cudaGetSymbolAddress((void**)&KB4, g_KB4);
    cudaGetSymbolAddress((void**)&VB4, g_Vb4);
    cudaGetSymbolAddress((void**)&VISB, g_visb);
    cudaGetSymbolAddress((void**)&TXTB, g_txtb);
    cudaGetSymbolAddress((void**)&CTXB4, g_ctxb4);
    cudaGetSymbolAddress((void**)&OUT1B4, g_out1b4);
    cudaGetSymbolAddress((void**)&HB4, g_hb4);
    cudaGetSymbolAddress((void**)&WqkvT4, g_WqkvT4);
    cudaGetSymbolAddress((void**)&WoT, g_WoT);
    cudaGetSymbolAddress((void**)&W1T, g_W1T);
    cudaGetSymbolAddress((void**)&W2T, g_W2T);

    cudaFuncSetAttribute(gemm_bf16_k<false, false, false, false, true >, cudaFuncAttributeMaxDynamicSharedMemorySize, GEMM_SMEM);
    cudaFuncSetAttribute(gemm_bf16_k<false, true,  true,  false, false>, cudaFuncAttributeMaxDynamicSharedMemorySize, GEMM_SMEM);
    cudaFuncSetAttribute(gemm_bf16_k<true,  false, false, true,  false>, cudaFuncAttributeMaxDynamicSharedMemorySize, GEMM_SMEM);

    auto U4 = [](const void* a, const void* b, const void* c, const void* d) {
        ulong4 u; u.x = (u64)a; u.y = (u64)b; u.z = (u64)c; u.w = (u64)d; return u;
    };

    // 0: mega prepass
    {
        TT tt;
        const size_t BLK = (size_t)DM * DM;
        const u64 qoff[4] = {0, 6 * BLK, 1 * BLK, 7 * BLK};
        const u64 koff[4] = {2 * BLK, 10 * BLK, 8 * BLK, 4 * BLK};
        const u64 voff[4] = {3 * BLK, 11 * BLK, 9 * BLK, 5 * BLK};
        for (int p = 0; p < 4; p++) {
            tt.src[p]      = (u64)(Wq + (size_t)p * BLK); tt.dst[p]      = (u64)(WqkvT4 + qoff[p]);
            tt.src[4 + p]  = (u64)(Wk + (size_t)p * BLK); tt.dst[4 + p]  = (u64)(WqkvT4 + koff[p]);
            tt.src[8 + p]  = (u64)(Wv + (size_t)p * BLK); tt.dst[8 + p]  = (u64)(WqkvT4 + voff[p]);
            tt.src[12 + p] = (u64)(Wo + (size_t)p * BLK); tt.dst[12 + p] = (u64)(WoT + (size_t)p * BLK);
            tt.src[16 + p] = (u64)(W1 + (size_t)p * DM * DI); tt.dst[16 + p] = (u64)(W1T + (size_t)p * DI * DM);
            tt.src[20 + p] = (u64)(W2 + (size_t)p * DI * DM); tt.dst[20 + p] = (u64)(W2T + (size_t)p * DM * DI);
        }
        megaprep_kernel<<<25633, 256>>>(tt, vis, txt, bq, bk, bv, nobj);
    }

    const int MT = (NTOK + 127) / 128;
    const size_t SL = (size_t)NTOK * DM;
    const int perm[4] = {0, 2, 1, 3};
    ulong4 nullq; nullq.x = nullq.y = nullq.z = nullq.w = 0;

    // 1: fused QKV GEMM
    {
        ulong4 Aq = U4(VISB, TXTB, nullptr, nullptr);
        ulong4 Bq = U4(WqkvT4, WqkvT4 + (size_t)NQKV * DM, nullptr, nullptr);
        ulong4 bq_ = U4(BQKV, BQKV + NQKV, nullptr, nullptr);
        gemm_bf16_k<false, false, false, false, true><<<dim3(NQKV / 128, MT, 2), 256, GEMM_SMEM>>>(
            Aq, Bq, bq_, nullq, (float*)VB4, 0, QB4, (size_t)NTOK * NQ, KB4, NTOK, DM, NQKV);
    }

    // 2: tensor-core attention
    attn_tc_kernel<<<dim3(BATCH, NH, 4), 32>>>();

    // 3: proj + residual
    {
        const size_t BLK = (size_t)DM * DM;
        ulong4 Aq = U4(CTXB4, CTXB4 + SL, CTXB4 + 2 * SL, CTXB4 + 3 * SL);
        ulong4 Bq = U4(WoT + perm[0] * BLK, WoT + perm[1] * BLK, WoT + perm[2] * BLK, WoT + perm[3] * BLK);
        ulong4 bq_ = U4(bo + perm[0] * DM, bo + perm[1] * DM, bo + perm[2] * DM, bo + perm[3] * DM);
        ulong4 Rq = U4(vis, vis, txt, txt);
        gemm_bf16_k<false, true, true, false, false><<<dim3(DM / 128, MT, 4), 256, GEMM_SMEM>>>(
            Aq, Bq, bq_, Rq, T14, SL, nullptr, 0, nullptr, NTOK, DM, DM);
    }
    // 4: LN1 (warp-per-row)
    {
        ulong4 gq = U4(g1 + perm[0] * DM, g1 + perm[1] * DM, g1 + perm[2] * DM, g1 + perm[3] * DM);
        ulong4 bq_ = U4(be1 + perm[0] * DM, be1 + perm[1] * DM, be1 + perm[2] * DM, be1 + perm[3] * DM);
        ln1_kernel<<<dim3(NTOK / 8, 4), 256>>>(T14, SL, gq, bq_, OUT14, SL, OUT1B4, SL);
    }
    // 5: FFN1
    {
        ulong4 Aq = U4(OUT1B4, OUT1B4 + SL, OUT1B4 + 2 * SL, OUT1B4 + 3 * SL);
        const size_t WB = (size_t)DI * DM;
        ulong4 Bq = U4(W1T + perm[0] * WB, W1T + perm[1] * WB, W1T + perm[2] * WB, W1T + perm[3] * WB);
        ulong4 bq_ = U4(b1 + perm[0] * DI, b1 + perm[1] * DI, b1 + perm[2] * DI, b1 + perm[3] * DI);
        gemm_bf16_k<true, false, false, true, false><<<dim3(DI / 128, MT, 4), 256, GEMM_SMEM>>>(
            Aq, Bq, bq_, nullq, nullptr, 0, HB4, (size_t)NTOK * DI, nullptr, NTOK, DM, DI);
    }
    // 6: FFN2 + residual
    {
        const size_t HL = (size_t)NTOK * DI;
        ulong4 Aq = U4(HB4, HB4 + HL, HB4 + 2 * HL, HB4 + 3 * HL);
        const size_t WB = (size_t)DM * DI;
        ulong4 Bq = U4(W2T + perm[0] * WB, W2T + perm[1] * WB, W2T + perm[2] * WB, W2T + perm[3] * WB);
        ulong4 bq_ = U4(b2 + perm[0] * DM, b2 + perm[1] * DM, b2 + perm[2] * DM, b2 + perm[3] * DM);
        ulong4 Rq = U4(OUT14, OUT14 + SL, OUT14 + 2 * SL, OUT14 + 3 * SL);
        gemm_bf16_k<false, true, true, false, false><<<dim3(DM / 128, MT, 4), 256, GEMM_SMEM>>>(
            Aq, Bq, bq_, Rq, T14, SL, nullptr, 0, nullptr, NTOK, DI, DM);
    }
    // 7: LN2 + sum -> d_out (warp-per-row)
    {
        ulong4 gq = U4(g2 + perm[0] * DM, g2 + perm[1] * DM, g2 + perm[2] * DM, g2 + perm[3] * DM);
        ulong4 bq_ = U4(be2 + perm[0] * DM, be2 + perm[1] * DM, be2 + perm[2] * DM, be2 + perm[3] * DM);
        ln2_pair_kernel<<<dim3(NTOK / 8, 2), 256>>>(T14, SL, gq, bq_, out);
    }
}

// round 16
// speedup vs baseline: 1.3615x; 1.0126x over previous
#include <cuda_runtime.h>
#include <cuda_bf16.h>
#include <math.h>
#include <stdint.h>

#define NTOK 13320
#define BATCH 240
#define DM 512
#define DI 2048
#define NH 8
#define DKH 64
#define LNEPS 1e-5f
#define NQ 1024
#define NKV 2048
#define NQKV 3072

typedef unsigned long long u64;

// ================= scratch (static device globals; no allocation) =================
__device__ float g_t14  [4 * NTOK * DM];
__device__ float g_out14[4 * NTOK * DM];
__device__ int   g_offs[BATCH + 1];
__device__ float g_bqkv[2 * NQKV];

__device__ __nv_bfloat16 g_Qb4[2 * NTOK * NQ];
__device__ __nv_bfloat16 g_KB4[2 * NTOK * NQ];
__device__ __nv_bfloat16 g_Vb4[2 * NTOK * NQ];

__device__ __nv_bfloat16 g_visb  [NTOK * DM];
__device__ __nv_bfloat16 g_txtb  [NTOK * DM];
__device__ __nv_bfloat16 g_ctxb4 [4 * NTOK * DM];
__device__ __nv_bfloat16 g_out1b4[4 * NTOK * DM];
__device__ __nv_bfloat16 g_hb4   [4 * NTOK * DI];

__device__ __nv_bfloat16 g_WqkvT4[2 * NQKV * DM];
__device__ __nv_bfloat16 g_WoT  [4 * DM * DM];
__device__ __nv_bfloat16 g_W1T  [4 * DI * DM];
__device__ __nv_bfloat16 g_W2T  [4 * DM * DI];

// ================= helpers =================
__device__ __forceinline__ uint32_t smem_u32(const void* p) {
    uint32_t a;
    asm("{ .reg .u64 t; cvta.to.shared.u64 t, %1; cvt.u32.u64 %0, t; }" : "=r"(a) : "l"(p));
    return a;
}
__device__ __forceinline__ void cp_async16(uint32_t dst, const void* src) {
    asm volatile("cp.async.cg.shared.global [%0], [%1], 16;" :: "r"(dst), "l"(src));
}
#define CP_COMMIT() asm volatile("cp.async.commit_group;" ::: "memory")
#define CP_WAIT(n)  asm volatile("cp.async.wait_group %0;" :: "n"(n) : "memory")

__device__ __forceinline__ void ldmatrix_x4(uint32_t& r0, uint32_t& r1, uint32_t& r2, uint32_t& r3, uint32_t addr) {
    asm volatile("ldmatrix.sync.aligned.m8n8.x4.shared.b16 {%0,%1,%2,%3}, [%4];"
        : "=r"(r0), "=r"(r1), "=r"(r2), "=r"(r3) : "r"(addr));
}
__device__ __forceinline__ void ldmatrix_x4_t(uint32_t& r0, uint32_t& r1, uint32_t& r2, uint32_t& r3, uint32_t addr) {
    asm volatile("ldmatrix.sync.aligned.m8n8.x4.trans.shared.b16 {%0,%1,%2,%3}, [%4];"
        : "=r"(r0), "=r"(r1), "=r"(r2), "=r"(r3) : "r"(addr));
}
__device__ __forceinline__ void mma_bf16(float* d, const uint32_t* a, const uint32_t* b) {
    asm volatile("mma.sync.aligned.m16n8k16.row.col.f32.bf16.bf16.f32 "
        "{%0,%1,%2,%3}, {%4,%5,%6,%7}, {%8,%9}, {%0,%1,%2,%3};"
        : "+f"(d[0]), "+f"(d[1]), "+f"(d[2]), "+f"(d[3])
        : "r"(a[0]), "r"(a[1]), "r"(a[2]), "r"(a[3]), "r"(b[0]), "r"(b[1]));
}
__device__ __forceinline__ u64 q_at(const ulong4& q, int z) {
    u64 v;
    switch (z) { case 0: v = q.x; break; case 1: v = q.y; break;
                 case 2: v = q.z; break; default: v = q.w; }
    return v;
}

// ========== fused mega-prepass ==========
#define NC4 (NTOK * DM / 4)
struct TT { u64 src[24]; u64 dst[24]; };

__global__ __launch_bounds__(256) void megaprep_kernel(
    TT tt,
    const float* __restrict__ Vsrc, const float* __restrict__ Tsrc,
    const float* __restrict__ bq, const float* __restrict__ bk, const float* __restrict__ bv,
    const int* __restrict__ nobj)
{
    int bid = blockIdx.x;
    int tid = threadIdx.x;
    if (bid < 13320) {
        int i = bid * 256 + tid;
        const float* X; __nv_bfloat16* Y; int j;
        if (i < NC4) { X = Vsrc; Y = g_visb; j = i; }
        else { X = Tsrc; Y = g_txtb; j = i - NC4; }
        float4 v = ((const float4*)X)[j];
        __nv_bfloat162 a, b;
        a.x = __float2bfloat16_rn(v.x); a.y = __float2bfloat16_rn(v.y);
        b.x = __float2bfloat16_rn(v.z); b.y = __float2bfloat16_rn(v.w);
        ((__nv_bfloat162*)Y)[j * 2 + 0] = a;
        ((__nv_bfloat162*)Y)[j * 2 + 1] = b;
    } else if (bid < 13344) {
        int i = (bid - 13320) * 256 + tid;
        int src = i / NQKV, r = i % NQKV;
        float val;
        if (r < 1024) {
            int half = (r >> 9) & 1, j = r & 511;
            int p = src + 2 * half;
            val = bq[p * DM + j];
        } else {
            int rr = r - 1024;
            int half = rr >> 10, part = (rr >> 9) & 1, j = rr & 511;
            const int pt[2][2] = { {0, 3}, {2, 1} };
            int p = pt[src][half];
            val = (part ? bv : bk)[p * DM + j];
        }
        g_bqkv[i] = val;
    } else if (bid == 13344) {
        if (tid == 0) {
            int s = 0;
            for (int i = 0; i < BATCH; i++) { g_offs[i] = s; s += nobj[i]; }
            g_offs[BATCH] = s;
        }
    } else {
        int b2 = bid - 13345;
        int e, t, R, C;
        if (b2 < 4096)      { e = b2 >> 8;               t = b2 & 255;            R = 512;  C = 512;  }
        else if (b2 < 8192) { e = 16 + ((b2 - 4096) >> 10); t = (b2 - 4096) & 1023; R = 512;  C = 2048; }
        else                { e = 20 + ((b2 - 8192) >> 10); t = (b2 - 8192) & 1023; R = 2048; C = 512;  }
        const float* Sp = (const float*)tt.src[e];
        __nv_bfloat16* Dp = (__nv_bfloat16*)tt.dst[e];
        int tpr = C >> 5;
        int bx = (t % tpr) * 32, by = (t / tpr) * 32;
        int tx = tid & 31, ty = tid >> 5;

        __shared__ float tile[32][33];
        int x = bx + tx;
#pragma unroll
        for (int yy = ty; yy < 32; yy += 8)
            tile[yy][tx] = Sp[(size_t)(by + yy) * C + x];
        __syncthreads();
        int x2 = by + tx;
#pragma unroll
        for (int yy = ty; yy < 32; yy += 8)
            Dp[(size_t)(bx + yy) * R + x2] = __float2bfloat16_rn(tile[tx][yy]);
    }
}

// ======== bf16 mma.sync GEMM, 128x128 tile (8 warps of 64x32), BK=64, 3-stage ========
#define LDSH 72
#define TILEB (128 * LDSH * 2)
#define STAGEB (2 * TILEB)
#define NSTAGE 3
#define GEMM_SMEM (NSTAGE * STAGEB)        // 110592

template <bool RELU, bool RESID, bool OF32, bool OBF16, bool OQKV>
__global__ __launch_bounds__(256, 2) void gemm_bf16_k(
    ulong4 Aq, ulong4 Btq, ulong4 biasq, ulong4 Rq,
    float* __restrict__ C, size_t cStr, __nv_bfloat16* __restrict__ Cb, size_t cbStr,
    __nv_bfloat16* __restrict__ Cb2,
    int M, int K, int N)
{
    extern __shared__ char smem[];
    const uint32_t sb = smem_u32(smem);
    const int tid = threadIdx.x;
    const int lane = tid & 31;
    const int wid = tid >> 5;
    const int z = blockIdx.z;
    const int m0 = blockIdx.y * 128;
    const int n0 = blockIdx.x * 128;
    const int warp_m = wid & 1;
    const int warp_n = wid >> 1;

    const __nv_bfloat16* A  = (const __nv_bfloat16*)q_at(Aq, z);
    const __nv_bfloat16* Bt = (const __nv_bfloat16*)q_at(Btq, z);
    const float* bias = (const float*)q_at(biasq, z);
    const float* R = RESID ? (const float*)q_at(Rq, z) : nullptr;
    if (OF32)  C  += (size_t)z * cStr;
    __nv_bfloat16* Vb2 = OQKV ? ((__nv_bfloat16*)C) + (size_t)z * cbStr : nullptr;
    if (OBF16 || OQKV) Cb  += (size_t)z * cbStr;
    __nv_bfloat16* Kb2 = OQKV ? Cb2 + (size_t)z * cbStr : nullptr;

    float acc[4][4][4];
#pragma unroll
    for (int i = 0; i < 4; i++)
#pragma unroll
        for (int j = 0; j < 4; j++)
#pragma unroll
            for (int r = 0; r < 4; r++) acc[i][j][r] = 0.f;

    const __nv_bfloat16* aptr[4];
    const __nv_bfloat16* bptr[4];
    uint32_t adst[4], bdst[4];
#pragma unroll
    for (int i = 0; i < 4; i++) {
        int c = tid + i * 256;
        int row = c >> 3, c16 = c & 7;
        int gr = m0 + row; gr = gr < M ? gr : M - 1;
        aptr[i] = A + (size_t)gr * K + c16 * 8;
        bptr[i] = Bt + (size_t)(n0 + row) * K + c16 * 8;
        adst[i] = row * (LDSH * 2) + c16 * 16;
        bdst[i] = TILEB + row * (LDSH * 2) + c16 * 16;
    }

    const int lmrow  = lane & 15;
    const int lmbyte = (lane >> 4) * 16;
    const int KT = K >> 6;

    auto load_stage_at = [&](uint32_t base, int k0) {
#pragma unroll
        for (int i = 0; i < 4; i++)
            cp_async16(base + adst[i], aptr[i] + k0);
#pragma unroll
        for (int i = 0; i < 4; i++)
            cp_async16(base + bdst[i], bptr[i] + k0);
        CP_COMMIT();
    };

    load_stage_at(sb, 0);
    load_stage_at(sb + STAGEB, 64);

    uint32_t cons = sb;
    uint32_t loadb = sb + 2 * STAGEB;

#pragma unroll 1
    for (int it = 0; it < KT; it++) {
        CP_WAIT(NSTAGE - 2);
        __syncthreads();
        int nk = it + NSTAGE - 1;
        if (nk < KT) load_stage_at(loadb, nk << 6);
        else CP_COMMIT();

        const uint32_t ab = cons;
        const uint32_t bb = cons + TILEB;

#pragma unroll
        for (int kk = 0; kk < 4; kk++) {
            uint32_t af[4][4];
#pragma unroll
            for (int mi = 0; mi < 4; mi++) {
                uint32_t addr = ab + (warp_m * 64 + mi * 16 + lmrow) * (LDSH * 2) + kk * 32 + lmbyte;
                ldmatrix_x4(af[mi][0], af[mi][1], af[mi][2], af[mi][3], addr);
            }
            uint32_t bf[4][2];
#pragma unroll
            for (int t = 0; t < 2; t++) {
                uint32_t addr = bb + (warp_n * 32 + t * 16 + lmrow) * (LDSH * 2) + kk * 32 + lmbyte;
                uint32_t r0, r1, r2, r3;
                ldmatrix_x4(r0, r1, r2, r3, addr);
                bf[t * 2 + 0][0] = r0; bf[t * 2 + 0][1] = r2;
                bf[t * 2 + 1][0] = r1; bf[t * 2 + 1][1] = r3;
            }
#pragma unroll
            for (int mi = 0; mi < 4; mi++)
#pragma unroll
                for (int nj = 0; nj < 4; nj++)
                    mma_bf16(acc[mi][nj], af[mi], bf[nj]);
        }

        loadb = cons;
        cons += STAGEB;
        if (cons == sb + NSTAGE * STAGEB) cons = sb;
    }

    const bool isQ = OQKV && (n0 < 1024);
    const int c2b = n0 - 1024;
    const bool isK = OQKV && !isQ && (((c2b >> 9) & 1) == 0);

    const int er = lane >> 2;
    const int ec = (lane & 3) * 2;
#pragma unroll
    for (int mi = 0; mi < 4; mi++) {
#pragma unroll
        for (int half = 0; half < 2; half++) {
            int row = m0 + warp_m * 64 + mi * 16 + half * 8 + er;
            if (row >= M) continue;
#pragma unroll
            for (int nj = 0; nj < 4; nj++) {
                int col = n0 + warp_n * 32 + nj * 8 + ec;
                float2 v;
                v.x = acc[mi][nj][half * 2 + 0] + bias[col + 0];
                v.y = acc[mi][nj][half * 2 + 1] + bias[col + 1];
                if (RESID) {
                    const float2 rv = *(const float2*)(R + (size_t)row * N + col);
                    v.x += rv.x; v.y += rv.y;
                }
                if (RELU) { v.x = fmaxf(v.x, 0.f); v.y = fmaxf(v.y, 0.f); }
                if (OQKV) {
                    __nv_bfloat162 h2;
                    h2.x = __float2bfloat16_rn(v.x);
                    h2.y = __float2bfloat16_rn(v.y);
                    if (isQ) {
                        *(__nv_bfloat162*)(Cb + (size_t)row * 1024 + col) = h2;
                    } else {
                        int colk = ((c2b >> 10) << 9) + ((col - 1024) & 511);
                        if (isK)
                            *(__nv_bfloat162*)(Kb2 + (size_t)row * 1024 + colk) = h2;
                        else
                            *(__nv_bfloat162*)(Vb2 + (size_t)row * 1024 + colk) = h2;
                    }
                } else {
                    if (OF32)
                        *(float2*)(C + (size_t)row * N + col) = v;
                    if (OBF16) {
                        __nv_bfloat162 h2;
                        h2.x = __float2bfloat16_rn(v.x);
                        h2.y = __float2bfloat16_rn(v.y);
                        *(__nv_bfloat162*)(Cb + (size_t)row * N + col) = h2;
                    }
                }
            }
        }
    }
}

// ================= LN1: warp-per-row (8 rows / 256-thr block) =================
__global__ __launch_bounds__(256) void ln1_kernel(
    const float* __restrict__ X, size_t xStr, ulong4 gq, ulong4 bq,
    float* __restrict__ out, size_t oStr, __nv_bfloat16* __restrict__ outb, size_t obStr)
{
    int wid = threadIdx.x >> 5;
    int lane = threadIdx.x & 31;
    int row = blockIdx.x * 8 + wid;
    int e = blockIdx.y;
    const float* Xr = X + (size_t)e * xStr + (size_t)row * DM;
    const float* g = (const float*)q_at(gq, e);
    const float* b = (const float*)q_at(bq, e);

    float4 v[4];
#pragma unroll
    for (int k = 0; k < 4; k++) v[k] = ((const float4*)Xr)[lane + 32 * k];

    float s = 0.f;
#pragma unroll
    for (int k = 0; k < 4; k++) s += (v[k].x + v[k].y) + (v[k].z + v[k].w);
#pragma unroll
    for (int o = 16; o > 0; o >>= 1) s += __shfl_xor_sync(0xffffffffu, s, o);
    float mean = s * (1.0f / DM);

    float sq = 0.f;
#pragma unroll
    for (int k = 0; k < 4; k++) {
        v[k].x -= mean; v[k].y -= mean; v[k].z -= mean; v[k].w -= mean;
        sq += v[k].x * v[k].x + v[k].y * v[k].y + v[k].z * v[k].z + v[k].w * v[k].w;
    }
#pragma unroll
    for (int o = 16; o > 0; o >>= 1) sq += __shfl_xor_sync(0xffffffffu, sq, o);
    float rstd = rsqrtf(sq * (1.0f / DM) + LNEPS);

    float* outr = out + (size_t)e * oStr + (size_t)row * DM;
    __nv_bfloat16* ob = outb + (size_t)e * obStr + (size_t)row * DM;
#pragma unroll
    for (int k = 0; k < 4; k++) {
        float4 gg = ((const float4*)g)[lane + 32 * k];
        float4 bb = ((const float4*)b)[lane + 32 * k];
        float4 y;
        y.x = v[k].x * rstd * gg.x + bb.x;
        y.y = v[k].y * rstd * gg.y + bb.y;
        y.z = v[k].z * rstd * gg.z + bb.z;
        y.w = v[k].w * rstd * gg.w + bb.w;
        ((float4*)outr)[lane + 32 * k] = y;
        __nv_bfloat162 a, c;
        a.x = __float2bfloat16_rn(y.x); a.y = __float2bfloat16_rn(y.y);
        c.x = __float2bfloat16_rn(y.z); c.y = __float2bfloat16_rn(y.w);
        ((__nv_bfloat162*)ob)[(lane + 32 * k) * 2 + 0] = a;
        ((__nv_bfloat162*)ob)[(lane + 32 * k) * 2 + 1] = c;
    }
}

// ============ LN2 pair + sum: warp-per-row ============
__global__ __launch_bounds__(256) void ln2_pair_kernel(
    const float* __restrict__ X, size_t xStr, ulong4 gq, ulong4 bq, float* __restrict__ out)
{
    int wid = threadIdx.x >> 5;
    int lane = threadIdx.x & 31;
    int row = blockIdx.x * 8 + wid;
    int p = blockIdx.y;

    const float* X0 = X + (size_t)(2 * p) * xStr + (size_t)row * DM;
    const float* X1 = X + (size_t)(2 * p + 1) * xStr + (size_t)row * DM;
    float4 v0[4], v1[4];
#pragma unroll
    for (int k = 0; k < 4; k++) {
        v0[k] = ((const float4*)X0)[lane + 32 * k];
        v1[k] = ((const float4*)X1)[lane + 32 * k];
    }

    float s0 = 0.f, s1 = 0.f;
#pragma unroll
    for (int k = 0; k < 4; k++) {
        s0 += (v0[k].x + v0[k].y) + (v0[k].z + v0[k].w);
        s1 += (v1[k].x + v1[k].y) + (v1[k].z + v1[k].w);
    }
#pragma unroll
    for (int o = 16; o > 0; o >>= 1) {
        s0 += __shfl_xor_sync(0xffffffffu, s0, o);
        s1 += __shfl_xor_sync(0xffffffffu, s1, o);
    }
    float mean0 = s0 * (1.0f / DM);
    float mean1 = s1 * (1.0f / DM);

    float q0 = 0.f, q1 = 0.f;
#pragma unroll
    for (int k = 0; k < 4; k++) {
        v0[k].x -= mean0; v0[k].y -= mean0; v0[k].z -= mean0; v0[k].w -= mean0;
        v1[k].x -= mean1; v1[k].y -= mean1; v1[k].z -= mean1; v1[k].w -= mean1;
        q0 += v0[k].x * v0[k].x + v0[k].y * v0[k].y + v0[k].z * v0[k].z + v0[k].w * v0[k].w;
        q1 += v1[k].x * v1[k].x + v1[k].y * v1[k].y + v1[k].z * v1[k].z + v1[k].w * v1[k].w;
    }
#pragma unroll
    for (int o = 16; o > 0; o >>= 1) {
        q0 += __shfl_xor_sync(0xffffffffu, q0, o);
        q1 += __shfl_xor_sync(0xffffffffu, q1, o);
    }
    float rstd0 = rsqrtf(q0 * (1.0f / DM) + LNEPS);
    float rstd1 = rsqrtf(q1 * (1.0f / DM) + LNEPS);

    const float* g0 = (const float*)q_at(gq, 2 * p);
    const float* b0 = (const float*)q_at(bq, 2 * p);
    const float* g1 = (const float*)q_at(gq, 2 * p + 1);
    const float* b1 = (const float*)q_at(bq, 2 * p + 1);

    float* outr = out + (size_t)p * NTOK * DM + (size_t)row * DM;
#pragma unroll
    for (int k = 0; k < 4; k++) {
        float4 gg0 = ((const float4*)g0)[lane + 32 * k], bb0 = ((const float4*)b0)[lane + 32 * k];
        float4 gg1 = ((const float4*)g1)[lane + 32 * k], bb1 = ((const float4*)b1)[lane + 32 * k];
        float4 y;
        y.x = (v0[k].x * rstd0 * gg0.x + bb0.x) + (v1[k].x * rstd1 * gg1.x + bb1.x);
        y.y = (v0[k].y * rstd0 * gg0.y + bb0.y) + (v1[k].y * rstd1 * gg1.y + bb1.y);
        y.z = (v0[k].z * rstd0 * gg0.z + bb0.z) + (v1[k].z * rstd1 * gg1.z + bb1.z);
        y.w = (v0[k].w * rstd0 * gg0.w + bb0.w) + (v1[k].w * rstd1 * gg1.w + bb1.w);
        ((float4*)outr)[lane + 32 * k] = y;
    }
}

// ========== tensor-core segment attention: 4 warps per (seg, head, enc), m-strided ==========
__global__ __launch_bounds__(128) void attn_tc_kernel()
{
    int s = blockIdx.x;
    int h = blockIdx.y;
    int e = blockIdx.z;
    int off = g_offs[s];
    int L = g_offs[s + 1] - off;
    int L16 = (L + 15) & ~15;
    int npairs = L16 >> 4;

    const int srcQ = e >> 1, halfQ = e & 1;
    const int srcKV_t[4]  = {0, 1, 1, 0};
    const int halfKV_t[4] = {0, 0, 1, 1};
    const int srcKV = srcKV_t[e], halfKV = halfKV_t[e];

    const __nv_bfloat16* Qb = g_Qb4 + (size_t)srcQ  * NTOK * NQ + halfQ  * 512 + h * DKH;
    const __nv_bfloat16* Kb = g_KB4 + (size_t)srcKV * NTOK * NQ + halfKV * 512 + h * DKH;
    const __nv_bfloat16* Vb = g_Vb4 + (size_t)srcKV * NTOK * NQ + halfKV * 512 + h * DKH;

    __shared__ __align__(16) __nv_bfloat16 Ks[96 * 72];
    __shared__ __align__(16) __nv_bfloat16 Vs[96 * 72];
    int tid = threadIdx.x;
    int lane = tid & 31;
    int wid = tid >> 5;
    uint4 zz; zz.x = zz.y = zz.z = zz.w = 0u;
    // cooperative K/V staging with all 128 threads
    for (int idx = tid; idx < L16 * 8; idx += 128) {
        int j = idx >> 3, c = idx & 7;
        uint4 uk = zz, uv = zz;
        if (j < L) {
            uk = ((const uint4*)(Kb + (size_t)(off + j) * 1024))[c];
            uv = ((const uint4*)(Vb + (size_t)(off + j) * 1024))[c];
        }
        *(uint4*)&Ks[j * 72 + c * 8] = uk;
        *(uint4*)&Vs[j * 72 + c * 8] = uv;
    }
    __syncthreads();

    const uint32_t uK = smem_u32(Ks);
    const uint32_t uV = smem_u32(Vs);
    const int r0 = lane >> 2;
    const int cq = (lane & 3) * 2;
    const int lmrow = lane & 15;
    const int lmhalf = lane >> 4;

    // warps take m-tiles strided by 64 rows
    for (int m0 = wid * 16; m0 < L; m0 += 64) {
        uint32_t qa[4][4];
        int row1 = off + min(m0 + r0, L - 1);
        int row2 = off + min(m0 + r0 + 8, L - 1);
#pragma unroll
        for (int kf = 0; kf < 4; kf++) {
            qa[kf][0] = *(const uint32_t*)(Qb + (size_t)row1 * 1024 + kf * 16 + cq);
            qa[kf][1] = *(const uint32_t*)(Qb + (size_t)row2 * 1024 + kf * 16 + cq);
            qa[kf][2] = *(const uint32_t*)(Qb + (size_t)row1 * 1024 + kf * 16 + cq + 8);
            qa[kf][3] = *(const uint32_t*)(Qb + (size_t)row2 * 1024 + kf * 16 + cq + 8);
        }

        float S[12][4];
#pragma unroll
        for (int t = 0; t < 12; t++) { S[t][0] = S[t][1] = S[t][2] = S[t][3] = 0.f; }
#pragma unroll
        for (int np = 0; np < 6; np++) {
            if (np < npairs) {
#pragma unroll
                for (int kf = 0; kf < 4; kf++) {
                    uint32_t addr = uK + ((np * 16 + lmrow) * 72 + kf * 16 + lmhalf * 8) * 2;
                    uint32_t r0_, r1_, r2_, r3_;
                    ldmatrix_x4(r0_, r1_, r2_, r3_, addr);
                    uint32_t b0[2] = { r0_, r2_ };
                    uint32_t b1[2] = { r1_, r3_ };
                    mma_bf16(S[2 * np + 0], qa[kf], b0);
                    mma_bf16(S[2 * np + 1], qa[kf], b1);
                }
            }
        }

#pragma unroll
        for (int t = 0; t < 12; t++) {
            int c = t * 8 + cq;
            S[t][0] = (c     < L) ? S[t][0] * 0.125f : -INFINITY;
            S[t][1] = (c + 1 < L) ? S[t][1] * 0.125f : -INFINITY;
            S[t][2] = (c     < L) ? S[t][2] * 0.125f : -INFINITY;
            S[t][3] = (c + 1 < L) ? S[t][3] * 0.125f : -INFINITY;
        }

        float mx1 = -INFINITY, mx2 = -INFINITY;
#pragma unroll
        for (int t = 0; t < 12; t++) {
            mx1 = fmaxf(mx1, fmaxf(S[t][0], S[t][1]));
            mx2 = fmaxf(mx2, fmaxf(S[t][2], S[t][3]));
        }
        mx1 = fmaxf(mx1, __shfl_xor_sync(0xffffffffu, mx1, 1));
        mx1 = fmaxf(mx1, __shfl_xor_sync(0xffffffffu, mx1, 2));
        mx2 = fmaxf(mx2, __shfl_xor_sync(0xffffffffu, mx2, 1));
        mx2 = fmaxf(mx2, __shfl_xor_sync(0xffffffffu, mx2, 2));

        float l1 = 0.f, l2 = 0.f;
#pragma unroll
        for (int t = 0; t < 12; t++) {
            S[t][0] = __expf(S[t][0] - mx1);
            S[t][1] = __expf(S[t][1] - mx1);
            S[t][2] = __expf(S[t][2] - mx2);
            S[t][3] = __expf(S[t][3] - mx2);
            l1 += S[t][0] + S[t][1];
            l2 += S[t][2] + S[t][3];
        }
        l1 += __shfl_xor_sync(0xffffffffu, l1, 1);
        l1 += __shfl_xor_sync(0xffffffffu, l1, 2);
        l2 += __shfl_xor_sync(0xffffffffu, l2, 1);
        l2 += __shfl_xor_sync(0xffffffffu, l2, 2);

        uint32_t pf[6][4];
#pragma unroll
        for (int np = 0; np < 6; np++) {
            __nv_bfloat162 h2;
            h2.x = __float2bfloat16_rn(S[2 * np + 0][0]); h2.y = __float2bfloat16_rn(S[2 * np + 0][1]);
            pf[np][0] = *(uint32_t*)&h2;
            h2.x = __float2bfloat16_rn(S[2 * np + 0][2]); h2.y = __float2bfloat16_rn(S[2 * np + 0][3]);
            pf[np][1] = *(uint32_t*)&h2;
            h2.x = __float2bfloat16_rn(S[2 * np + 1][0]); h2.y = __float2bfloat16_rn(S[2 * np + 1][1]);
            pf[np][2] = *(uint32_t*)&h2;
            h2.x = __float2bfloat16_rn(S[2 * np + 1][2]); h2.y = __float2bfloat16_rn(S[2 * np + 1][3]);
            pf[np][3] = *(uint32_t*)&h2;
        }

        float O[8][4];
#pragma unroll
        for (int nt = 0; nt < 8; nt++) { O[nt][0] = O[nt][1] = O[nt][2] = O[nt][3] = 0.f; }
#pragma unroll
        for (int kt = 0; kt < 6; kt++) {
            if (kt < npairs) {
#pragma unroll
                for (int nt = 0; nt < 8; nt += 2) {
                    uint32_t addr = uV + ((kt * 16 + lmrow) * 72 + nt * 8 + lmhalf * 8) * 2;
                    uint32_t r0_, r1_, r2_, r3_;
                    ldmatrix_x4_t(r0_, r1_, r2_, r3_, addr);
                    uint32_t b0[2] = { r0_, r1_ };
                    uint32_t b1[2] = { r2_, r3_ };
                    mma_bf16(O[nt + 0], pf[kt], b0);
                    mma_bf16(O[nt + 1], pf[kt], b1);
                }
            }
        }

        float il1 = 1.0f / l1, il2 = 1.0f / l2;
        int gr1 = m0 + r0, gr2 = gr1 + 8;
        __nv_bfloat16* obase = g_ctxb4 + (size_t)e * NTOK * DM + h * DKH;
        if (gr1 < L) {
            __nv_bfloat16* o1 = obase + (size_t)(off + gr1) * DM;
#pragma unroll
            for (int nt = 0; nt < 8; nt++) {
                __nv_bfloat162 h2;
                h2.x = __float2bfloat16_rn(O[nt][0] * il1);
                h2.y = __float2bfloat16_rn(O[nt][1] * il1);
                *(__nv_bfloat162*)(o1 + nt * 8 + cq) = h2;
            }
        }
        if (gr2 < L) {
            __nv_bfloat16* o2 = obase + (size_t)(off + gr2) * DM;
#pragma unroll
            for (int nt = 0; nt < 8; nt++) {
                __nv_bfloat162 h2;
                h2.x = __float2bfloat16_rn(O[nt][2] * il2);
                h2.y = __float2bfloat16_rn(O[nt][3] * il2);
                *(__nv_bfloat162*)(o2 + nt * 8 + cq) = h2;
            }
        }
    }
}

// ================= host =================
extern "C" void kernel_launch(void* const* d_in, const int* in_sizes, int n_in,
                              void* d_out, int out_size)
{
    const float* vis  = (const float*)d_in[0];
    const float* txt  = (const float*)d_in[1];
    const float* Wq   = (const float*)d_in[2];
    const float* bq   = (const float*)d_in[3];
    const float* Wk   = (const float*)d_in[4];
    const float* bk   = (const float*)d_in[5];
    const float* Wv   = (const float*)d_in[6];
    const float* bv   = (const float*)d_in[7];
    const float* Wo   = (const float*)d_in[8];
    const float* bo   = (const float*)d_in[9];
    const float* g1   = (const float*)d_in[10];
    const float* be1  = (const float*)d_in[11];
    const float* W1   = (const float*)d_in[12];
    const float* b1   = (const float*)d_in[13];
    const float* W2   = (const float*)d_in[14];
    const float* b2   = (const float*)d_in[15];
    const float* g2   = (const float*)d_in[16];
    const float* be2  = (const float*)d_in[17];
    const int*   nobj = (const int*)d_in[18];
    float* out = (float*)d_out;

    float *T14, *OUT14, *BQKV;
    __nv_bfloat16 *QB4, *KB4, *VB4, *VISB, *TXTB, *CTXB4, *OUT1B4, *HB4;
    __nv_bfloat16 *WqkvT4, *WoT, *W1T, *W2T;
    cudaGetSymbolAddress((void**)&T14, g_t14);
    cudaGetSymbolAddress((void**)&OUT14, g_out14);
    cudaGetSymbolAddress((void**)&BQKV, g_bqkv);
    cudaGetSymbolAddress((void**)&QB4, g_Qb4);
    cudaGetSymbolAddress((void**)&KB4, g_KB4);
    cudaGetSymbolAddress((void**)&VB4, g_Vb4);
    cudaGetSymbolAddress((void**)&VISB, g_visb);
    cudaGetSymbolAddress((void**)&TXTB, g_txtb);
    cudaGetSymbolAddress((void**)&CTXB4, g_ctxb4);
    cudaGetSymbolAddress((void**)&OUT1B4, g_out1b4);
    cudaGetSymbolAddress((void**)&HB4, g_hb4);
    cudaGetSymbolAddress((void**)&WqkvT4, g_WqkvT4);
    cudaGetSymbolAddress((void**)&WoT, g_WoT);
    cudaGetSymbolAddress((void**)&W1T, g_W1T);
    cudaGetSymbolAddress((void**)&W2T, g_W2T);

    cudaFuncSetAttribute(gemm_bf16_k<false, false, false, false, true >, cudaFuncAttributeMaxDynamicSharedMemorySize, GEMM_SMEM);
    cudaFuncSetAttribute(gemm_bf16_k<false, true,  true,  false, false>, cudaFuncAttributeMaxDynamicSharedMemorySize, GEMM_SMEM);
    cudaFuncSetAttribute(gemm_bf16_k<true,  false, false, true,  false>, cudaFuncAttributeMaxDynamicSharedMemorySize, GEMM_SMEM);

    auto U4 = [](const void* a, const void* b, const void* c, const void* d) {
        ulong4 u; u.x = (u64)a; u.y = (u64)b; u.z = (u64)c; u.w = (u64)d; return u;
    };

    // 0: mega prepass
    {
        TT tt;
        const size_t BLK = (size_t)DM * DM;
        const u64 qoff[4] = {0, 6 * BLK, 1 * BLK, 7 * BLK};
        const u64 koff[4] = {2 * BLK, 10 * BLK, 8 * BLK, 4 * BLK};
        const u64 voff[4] = {3 * BLK, 11 * BLK, 9 * BLK, 5 * BLK};
        for (int p = 0; p < 4; p++) {
            tt.src[p]      = (u64)(Wq + (size_t)p * BLK); tt.dst[p]      = (u64)(WqkvT4 + qoff[p]);
            tt.src[4 + p]  = (u64)(Wk + (size_t)p * BLK); tt.dst[4 + p]  = (u64)(WqkvT4 + koff[p]);
            tt.src[8 + p]  = (u64)(Wv + (size_t)p * BLK); tt.dst[8 + p]  = (u64)(WqkvT4 + voff[p]);
            tt.src[12 + p] = (u64)(Wo + (size_t)p * BLK); tt.dst[12 + p] = (u64)(WoT + (size_t)p * BLK);
            tt.src[16 + p] = (u64)(W1 + (size_t)p * DM * DI); tt.dst[16 + p] = (u64)(W1T + (size_t)p * DI * DM);
            tt.src[20 + p] = (u64)(W2 + (size_t)p * DI * DM); tt.dst[20 + p] = (u64)(W2T + (size_t)p * DM * DI);
        }
        megaprep_kernel<<<25633, 256>>>(tt, vis, txt, bq, bk, bv, nobj);
    }

    const int MT = (NTOK + 127) / 128;
    const size_t SL = (size_t)NTOK * DM;
    const int perm[4] = {0, 2, 1, 3};
    ulong4 nullq; nullq.x = nullq.y = nullq.z = nullq.w = 0;

    // 1: fused QKV GEMM
    {
        ulong4 Aq = U4(VISB, TXTB, nullptr, nullptr);
        ulong4 Bq = U4(WqkvT4, WqkvT4 + (size_t)NQKV * DM, nullptr, nullptr);
        ulong4 bq_ = U4(BQKV, BQKV + NQKV, nullptr, nullptr);
        gemm_bf16_k<false, false, false, false, true><<<dim3(NQKV / 128, MT, 2), 256, GEMM_SMEM>>>(
            Aq, Bq, bq_, nullq, (float*)VB4, 0, QB4, (size_t)NTOK * NQ, KB4, NTOK, DM, NQKV);
    }

    // 2: tensor-core attention (4 warps / block)
    attn_tc_kernel<<<dim3(BATCH, NH, 4), 128>>>();

    // 3: proj + residual
    {
        const size_t BLK = (size_t)DM * DM;
        ulong4 Aq = U4(CTXB4, CTXB4 + SL, CTXB4 + 2 * SL, CTXB4 + 3 * SL);
        ulong4 Bq = U4(WoT + perm[0] * BLK, WoT + perm[1] * BLK, WoT + perm[2] * BLK, WoT + perm[3] * BLK);
        ulong4 bq_ = U4(bo + perm[0] * DM, bo + perm[1] * DM, bo + perm[2] * DM, bo + perm[3] * DM);
        ulong4 Rq = U4(vis, vis, txt, txt);
        gemm_bf16_k<false, true, true, false, false><<<dim3(DM / 128, MT, 4), 256, GEMM_SMEM>>>(
            Aq, Bq, bq_, Rq, T14, SL, nullptr, 0, nullptr, NTOK, DM, DM);
    }
    // 4: LN1 (warp-per-row)
    {
        ulong4 gq = U4(g1 + perm[0] * DM, g1 + perm[1] * DM, g1 + perm[2] * DM, g1 + perm[3] * DM);
        ulong4 bq_ = U4(be1 + perm[0] * DM, be1 + perm[1] * DM, be1 + perm[2] * DM, be1 + perm[3] * DM);
        ln1_kernel<<<dim3(NTOK / 8, 4), 256>>>(T14, SL, gq, bq_, OUT14, SL, OUT1B4, SL);
    }
    // 5: FFN1
    {
        ulong4 Aq = U4(OUT1B4, OUT1B4 + SL, OUT1B4 + 2 * SL, OUT1B4 + 3 * SL);
        const size_t WB = (size_t)DI * DM;
        ulong4 Bq = U4(W1T + perm[0] * WB, W1T + perm[1] * WB, W1T + perm[2] * WB, W1T + perm[3] * WB);
        ulong4 bq_ = U4(b1 + perm[0] * DI, b1 + perm[1] * DI, b1 + perm[2] * DI, b1 + perm[3] * DI);
        gemm_bf16_k<true, false, false, true, false><<<dim3(DI / 128, MT, 4), 256, GEMM_SMEM>>>(
            Aq, Bq, bq_, nullq, nullptr, 0, HB4, (size_t)NTOK * DI, nullptr, NTOK, DM, DI);
    }
    // 6: FFN2 + residual
    {
        const size_t HL = (size_t)NTOK * DI;
        ulong4 Aq = U4(HB4, HB4 + HL, HB4 + 2 * HL, HB4 + 3 * HL);
        const size_t WB = (size_t)DM * DI;
        ulong4 Bq = U4(W2T + perm[0] * WB, W2T + perm[1] * WB, W2T + perm[2] * WB, W2T + perm[3] * WB);
        ulong4 bq_ = U4(b2 + perm[0] * DM, b2 + perm[1] * DM, b2 + perm[2] * DM, b2 + perm[3] * DM);
        ulong4 Rq = U4(OUT14, OUT14 + SL, OUT14 + 2 * SL, OUT14 + 3 * SL);
        gemm_bf16_k<false, true, true, false, false><<<dim3(DM / 128, MT, 4), 256, GEMM_SMEM>>>(
            Aq, Bq, bq_, Rq, T14, SL, nullptr, 0, nullptr, NTOK, DI, DM);
    }
    // 7: LN2 + sum -> d_out (warp-per-row)
    {
        ulong4 gq = U4(g2 + perm[0] * DM, g2 + perm[1] * DM, g2 + perm[2] * DM, g2 + perm[3] * DM);
        ulong4 bq_ = U4(be2 + perm[0] * DM, be2 + perm[1] * DM, be2 + perm[2] * DM, be2 + perm[3] * DM);
        ln2_pair_kernel<<<dim3(NTOK / 8, 2), 256>>>(T14, SL, gq, bq_, out);
    }
}

// round 17
// speedup vs baseline: 1.3625x; 1.0008x over previous
#include <cuda_runtime.h>
#include <cuda_bf16.h>
#include <math.h>
#include <stdint.h>

#define NTOK 13320
#define BATCH 240
#define DM 512
#define DI 2048
#define NH 8
#define DKH 64
#define LNEPS 1e-5f
#define NQ 1024
#define NKV 2048
#define NQKV 3072

typedef unsigned long long u64;

// ================= scratch (static device globals; no allocation) =================
__device__ float g_t14  [4 * NTOK * DM];
__device__ float g_out14[4 * NTOK * DM];
__device__ int   g_offs[BATCH + 1];
__device__ float g_bqkv[2 * NQKV];

__device__ __nv_bfloat16 g_Qb4[2 * NTOK * NQ];
__device__ __nv_bfloat16 g_KB4[2 * NTOK * NQ];
__device__ __nv_bfloat16 g_Vb4[2 * NTOK * NQ];

__device__ __nv_bfloat16 g_visb  [NTOK * DM];
__device__ __nv_bfloat16 g_txtb  [NTOK * DM];
__device__ __nv_bfloat16 g_ctxb4 [4 * NTOK * DM];
__device__ __nv_bfloat16 g_out1b4[4 * NTOK * DM];
__device__ __nv_bfloat16 g_hb4   [4 * NTOK * DI];

__device__ __nv_bfloat16 g_WqkvT4[2 * NQKV * DM];
__device__ __nv_bfloat16 g_WoT  [4 * DM * DM];
__device__ __nv_bfloat16 g_W1T  [4 * DI * DM];
__device__ __nv_bfloat16 g_W2T  [4 * DM * DI];

// ================= helpers =================
__device__ __forceinline__ uint32_t smem_u32(const void* p) {
    uint32_t a;
    asm("{ .reg .u64 t; cvta.to.shared.u64 t, %1; cvt.u32.u64 %0, t; }" : "=r"(a) : "l"(p));
    return a;
}
__device__ __forceinline__ void cp_async16(uint32_t dst, const void* src) {
    asm volatile("cp.async.cg.shared.global [%0], [%1], 16;" :: "r"(dst), "l"(src));
}
#define CP_COMMIT() asm volatile("cp.async.commit_group;" ::: "memory")
#define CP_WAIT(n)  asm volatile("cp.async.wait_group %0;" :: "n"(n) : "memory")

__device__ __forceinline__ void ldmatrix_x4(uint32_t& r0, uint32_t& r1, uint32_t& r2, uint32_t& r3, uint32_t addr) {
    asm volatile("ldmatrix.sync.aligned.m8n8.x4.shared.b16 {%0,%1,%2,%3}, [%4];"
        : "=r"(r0), "=r"(r1), "=r"(r2), "=r"(r3) : "r"(addr));
}
__device__ __forceinline__ void ldmatrix_x4_t(uint32_t& r0, uint32_t& r1, uint32_t& r2, uint32_t& r3, uint32_t addr) {
    asm volatile("ldmatrix.sync.aligned.m8n8.x4.trans.shared.b16 {%0,%1,%2,%3}, [%4];"
        : "=r"(r0), "=r"(r1), "=r"(r2), "=r"(r3) : "r"(addr));
}
__device__ __forceinline__ void mma_bf16(float* d, const uint32_t* a, const uint32_t* b) {
    asm volatile("mma.sync.aligned.m16n8k16.row.col.f32.bf16.bf16.f32 "
        "{%0,%1,%2,%3}, {%4,%5,%6,%7}, {%8,%9}, {%0,%1,%2,%3};"
        : "+f"(d[0]), "+f"(d[1]), "+f"(d[2]), "+f"(d[3])
        : "r"(a[0]), "r"(a[1]), "r"(a[2]), "r"(a[3]), "r"(b[0]), "r"(b[1]));
}
__device__ __forceinline__ u64 q_at(const ulong4& q, int z) {
    u64 v;
    switch (z) { case 0: v = q.x; break; case 1: v = q.y; break;
                 case 2: v = q.z; break; default: v = q.w; }
    return v;
}

// ========== fused mega-prepass ==========
#define NC4 (NTOK * DM / 4)
struct TT { u64 src[24]; u64 dst[24]; };

__global__ __launch_bounds__(256) void megaprep_kernel(
    TT tt,
    const float* __restrict__ Vsrc, const float* __restrict__ Tsrc,
    const float* __restrict__ bq, const float* __restrict__ bk, const float* __restrict__ bv,
    const int* __restrict__ nobj)
{
    int bid = blockIdx.x;
    int tid = threadIdx.x;
    if (bid < 13320) {
        int i = bid * 256 + tid;
        const float* X; __nv_bfloat16* Y; int j;
        if (i < NC4) { X = Vsrc; Y = g_visb; j = i; }
        else { X = Tsrc; Y = g_txtb; j = i - NC4; }
        float4 v = ((const float4*)X)[j];
        __nv_bfloat162 a, b;
        a.x = __float2bfloat16_rn(v.x); a.y = __float2bfloat16_rn(v.y);
        b.x = __float2bfloat16_rn(v.z); b.y = __float2bfloat16_rn(v.w);
        ((__nv_bfloat162*)Y)[j * 2 + 0] = a;
        ((__nv_bfloat162*)Y)[j * 2 + 1] = b;
    } else if (bid < 13344) {
        int i = (bid - 13320) * 256 + tid;
        int src = i / NQKV, r = i % NQKV;
        float val;
        if (r < 1024) {
            int half = (r >> 9) & 1, j = r & 511;
            int p = src + 2 * half;
            val = bq[p * DM + j];
        } else {
            int rr = r - 1024;
            int half = rr >> 10, part = (rr >> 9) & 1, j = rr & 511;
            const int pt[2][2] = { {0, 3}, {2, 1} };
            int p = pt[src][half];
            val = (part ? bv : bk)[p * DM + j];
        }
        g_bqkv[i] = val;
    } else if (bid == 13344) {
        if (tid == 0) {
            int s = 0;
            for (int i = 0; i < BATCH; i++) { g_offs[i] = s; s += nobj[i]; }
            g_offs[BATCH] = s;
        }
    } else {
        int b2 = bid - 13345;
        int e, t, R, C;
        if (b2 < 4096)      { e = b2 >> 8;               t = b2 & 255;            R = 512;  C = 512;  }
        else if (b2 < 8192) { e = 16 + ((b2 - 4096) >> 10); t = (b2 - 4096) & 1023; R = 512;  C = 2048; }
        else                { e = 20 + ((b2 - 8192) >> 10); t = (b2 - 8192) & 1023; R = 2048; C = 512;  }
        const float* Sp = (const float*)tt.src[e];
        __nv_bfloat16* Dp = (__nv_bfloat16*)tt.dst[e];
        int tpr = C >> 5;
        int bx = (t % tpr) * 32, by = (t / tpr) * 32;
        int tx = tid & 31, ty = tid >> 5;

        __shared__ float tile[32][33];
        int x = bx + tx;
#pragma unroll
        for (int yy = ty; yy < 32; yy += 8)
            tile[yy][tx] = Sp[(size_t)(by + yy) * C + x];
        __syncthreads();
        int x2 = by + tx;
#pragma unroll
        for (int yy = ty; yy < 32; yy += 8)
            Dp[(size_t)(bx + yy) * R + x2] = __float2bfloat16_rn(tile[tx][yy]);
    }
}

// ======== bf16 mma.sync GEMM, 128x128 tile (8 warps of 64x32), BK=64, 3-stage ========
#define LDSH 72
#define TILEB (128 * LDSH * 2)
#define STAGEB (2 * TILEB)
#define NSTAGE 3
#define GEMM_SMEM (NSTAGE * STAGEB)        // 110592

template <bool RELU, bool RESID, bool OF32, bool OBF16, bool OQKV>
__global__ __launch_bounds__(256, 2) void gemm_bf16_k(
    ulong4 Aq, ulong4 Btq, ulong4 biasq, ulong4 Rq,
    float* __restrict__ C, size_t cStr, __nv_bfloat16* __restrict__ Cb, size_t cbStr,
    __nv_bfloat16* __restrict__ Cb2,
    int M, int K, int N)
{
    extern __shared__ char smem[];
    const uint32_t sb = smem_u32(smem);
    const int tid = threadIdx.x;
    const int lane = tid & 31;
    const int wid = tid >> 5;
    const int z = blockIdx.z;
    const int m0 = blockIdx.y * 128;
    const int n0 = blockIdx.x * 128;
    const int warp_m = wid & 1;
    const int warp_n = wid >> 1;

    const __nv_bfloat16* A  = (const __nv_bfloat16*)q_at(Aq, z);
    const __nv_bfloat16* Bt = (const __nv_bfloat16*)q_at(Btq, z);
    const float* bias = (const float*)q_at(biasq, z);
    const float* R = RESID ? (const float*)q_at(Rq, z) : nullptr;
    if (OF32)  C  += (size_t)z * cStr;
    __nv_bfloat16* Vb2 = OQKV ? ((__nv_bfloat16*)C) + (size_t)z * cbStr : nullptr;
    if (OBF16 || OQKV) Cb  += (size_t)z * cbStr;
    __nv_bfloat16* Kb2 = OQKV ? Cb2 + (size_t)z * cbStr : nullptr;

    float acc[4][4][4];
#pragma unroll
    for (int i = 0; i < 4; i++)
#pragma unroll
        for (int j = 0; j < 4; j++)
#pragma unroll
            for (int r = 0; r < 4; r++) acc[i][j][r] = 0.f;

    const __nv_bfloat16* aptr[4];
    const __nv_bfloat16* bptr[4];
    uint32_t adst[4], bdst[4];
#pragma unroll
    for (int i = 0; i < 4; i++) {
        int c = tid + i * 256;
        int row = c >> 3, c16 = c & 7;
        int gr = m0 + row; gr = gr < M ? gr : M - 1;
        aptr[i] = A + (size_t)gr * K + c16 * 8;
        bptr[i] = Bt + (size_t)(n0 + row) * K + c16 * 8;
        adst[i] = row * (LDSH * 2) + c16 * 16;
        bdst[i] = TILEB + row * (LDSH * 2) + c16 * 16;
    }

    const int lmrow  = lane & 15;
    const int lmbyte = (lane >> 4) * 16;
    const int KT = K >> 6;

    auto load_stage_at = [&](uint32_t base, int k0) {
#pragma unroll
        for (int i = 0; i < 4; i++)
            cp_async16(base + adst[i], aptr[i] + k0);
#pragma unroll
        for (int i = 0; i < 4; i++)
            cp_async16(base + bdst[i], bptr[i] + k0);
        CP_COMMIT();
    };

    load_stage_at(sb, 0);
    load_stage_at(sb + STAGEB, 64);

    uint32_t cons = sb;
    uint32_t loadb = sb + 2 * STAGEB;

#pragma unroll 1
    for (int it = 0; it < KT; it++) {
        CP_WAIT(NSTAGE - 2);
        __syncthreads();
        int nk = it + NSTAGE - 1;
        if (nk < KT) load_stage_at(loadb, nk << 6);
        else CP_COMMIT();

        const uint32_t ab = cons;
        const uint32_t bb = cons + TILEB;

#pragma unroll
        for (int kk = 0; kk < 4; kk++) {
            uint32_t af[4][4];
#pragma unroll
            for (int mi = 0; mi < 4; mi++) {
                uint32_t addr = ab + (warp_m * 64 + mi * 16 + lmrow) * (LDSH * 2) + kk * 32 + lmbyte;
                ldmatrix_x4(af[mi][0], af[mi][1], af[mi][2], af[mi][3], addr);
            }
            uint32_t bf[4][2];
#pragma unroll
            for (int t = 0; t < 2; t++) {
                uint32_t addr = bb + (warp_n * 32 + t * 16 + lmrow) * (LDSH * 2) + kk * 32 + lmbyte;
                uint32_t r0, r1, r2, r3;
                ldmatrix_x4(r0, r1, r2, r3, addr);
                bf[t * 2 + 0][0] = r0; bf[t * 2 + 0][1] = r2;
                bf[t * 2 + 1][0] = r1; bf[t * 2 + 1][1] = r3;
            }
#pragma unroll
            for (int mi = 0; mi < 4; mi++)
#pragma unroll
                for (int nj = 0; nj < 4; nj++)
                    mma_bf16(acc[mi][nj], af[mi], bf[nj]);
        }

        loadb = cons;
        cons += STAGEB;
        if (cons == sb + NSTAGE * STAGEB) cons = sb;
    }

    const bool isQ = OQKV && (n0 < 1024);
    const int c2b = n0 - 1024;
    const bool isK = OQKV && !isQ && (((c2b >> 9) & 1) == 0);

    const int er = lane >> 2;
    const int ec = (lane & 3) * 2;
#pragma unroll
    for (int mi = 0; mi < 4; mi++) {
#pragma unroll
        for (int half = 0; half < 2; half++) {
            int row = m0 + warp_m * 64 + mi * 16 + half * 8 + er;
            if (row >= M) continue;
#pragma unroll
            for (int nj = 0; nj < 4; nj++) {
                int col = n0 + warp_n * 32 + nj * 8 + ec;
                float2 v;
                v.x = acc[mi][nj][half * 2 + 0] + bias[col + 0];
                v.y = acc[mi][nj][half * 2 + 1] + bias[col + 1];
                if (RESID) {
                    const float2 rv = *(const float2*)(R + (size_t)row * N + col);
                    v.x += rv.x; v.y += rv.y;
                }
                if (RELU) { v.x = fmaxf(v.x, 0.f); v.y = fmaxf(v.y, 0.f); }
                if (OQKV) {
                    __nv_bfloat162 h2;
                    h2.x = __float2bfloat16_rn(v.x);
                    h2.y = __float2bfloat16_rn(v.y);
                    if (isQ) {
                        *(__nv_bfloat162*)(Cb + (size_t)row * 1024 + col) = h2;
                    } else {
                        int colk = ((c2b >> 10) << 9) + ((col - 1024) & 511);
                        if (isK)
                            *(__nv_bfloat162*)(Kb2 + (size_t)row * 1024 + colk) = h2;
                        else
                            *(__nv_bfloat162*)(Vb2 + (size_t)row * 1024 + colk) = h2;
                    }
                } else {
                    if (OF32)
                        *(float2*)(C + (size_t)row * N + col) = v;
                    if (OBF16) {
                        __nv_bfloat162 h2;
                        h2.x = __float2bfloat16_rn(v.x);
                        h2.y = __float2bfloat16_rn(v.y);
                        *(__nv_bfloat162*)(Cb + (size_t)row * N + col) = h2;
                    }
                }
            }
        }
    }
}

// ================= LN1: warp-per-row (8 rows / 256-thr block) =================
__global__ __launch_bounds__(256) void ln1_kernel(
    const float* __restrict__ X, size_t xStr, ulong4 gq, ulong4 bq,
    float* __restrict__ out, size_t oStr, __nv_bfloat16* __restrict__ outb, size_t obStr)
{
    int wid = threadIdx.x >> 5;
    int lane = threadIdx.x & 31;
    int row = blockIdx.x * 8 + wid;
    int e = blockIdx.y;
    const float* Xr = X + (size_t)e * xStr + (size_t)row * DM;
    const float* g = (const float*)q_at(gq, e);
    const float* b = (const float*)q_at(bq, e);

    float4 v[4];
#pragma unroll
    for (int k = 0; k < 4; k++) v[k] = ((const float4*)Xr)[lane + 32 * k];

    float s = 0.f;
#pragma unroll
    for (int k = 0; k < 4; k++) s += (v[k].x + v[k].y) + (v[k].z + v[k].w);
#pragma unroll
    for (int o = 16; o > 0; o >>= 1) s += __shfl_xor_sync(0xffffffffu, s, o);
    float mean = s * (1.0f / DM);

    float sq = 0.f;
#pragma unroll
    for (int k = 0; k < 4; k++) {
        v[k].x -= mean; v[k].y -= mean; v[k].z -= mean; v[k].w -= mean;
        sq += v[k].x * v[k].x + v[k].y * v[k].y + v[k].z * v[k].z + v[k].w * v[k].w;
    }
#pragma unroll
    for (int o = 16; o > 0; o >>= 1) sq += __shfl_xor_sync(0xffffffffu, sq, o);
    float rstd = rsqrtf(sq * (1.0f / DM) + LNEPS);

    float* outr = out + (size_t)e * oStr + (size_t)row * DM;
    __nv_bfloat16* ob = outb + (size_t)e * obStr + (size_t)row * DM;
#pragma unroll
    for (int k = 0; k < 4; k++) {
        float4 gg = ((const float4*)g)[lane + 32 * k];
        float4 bb = ((const float4*)b)[lane + 32 * k];
        float4 y;
        y.x = v[k].x * rstd * gg.x + bb.x;
        y.y = v[k].y * rstd * gg.y + bb.y;
        y.z = v[k].z * rstd * gg.z + bb.z;
        y.w = v[k].w * rstd * gg.w + bb.w;
        ((float4*)outr)[lane + 32 * k] = y;
        __nv_bfloat162 a, c;
        a.x = __float2bfloat16_rn(y.x); a.y = __float2bfloat16_rn(y.y);
        c.x = __float2bfloat16_rn(y.z); c.y = __float2bfloat16_rn(y.w);
        ((__nv_bfloat162*)ob)[(lane + 32 * k) * 2 + 0] = a;
        ((__nv_bfloat162*)ob)[(lane + 32 * k) * 2 + 1] = c;
    }
}

// ============ LN2 pair + sum: warp-per-row ============
__global__ __launch_bounds__(256) void ln2_pair_kernel(
    const float* __restrict__ X, size_t xStr, ulong4 gq, ulong4 bq, float* __restrict__ out)
{
    int wid = threadIdx.x >> 5;
    int lane = threadIdx.x & 31;
    int row = blockIdx.x * 8 + wid;
    int p = blockIdx.y;

    const float* X0 = X + (size_t)(2 * p) * xStr + (size_t)row * DM;
    const float* X1 = X + (size_t)(2 * p + 1) * xStr + (size_t)row * DM;
    float4 v0[4], v1[4];
#pragma unroll
    for (int k = 0; k < 4; k++) {
        v0[k] = ((const float4*)X0)[lane + 32 * k];
        v1[k] = ((const float4*)X1)[lane + 32 * k];
    }

    float s0 = 0.f, s1 = 0.f;
#pragma unroll
    for (int k = 0; k < 4; k++) {
        s0 += (v0[k].x + v0[k].y) + (v0[k].z + v0[k].w);
        s1 += (v1[k].x + v1[k].y) + (v1[k].z + v1[k].w);
    }
#pragma unroll
    for (int o = 16; o > 0; o >>= 1) {
        s0 += __shfl_xor_sync(0xffffffffu, s0, o);
        s1 += __shfl_xor_sync(0xffffffffu, s1, o);
    }
    float mean0 = s0 * (1.0f / DM);
    float mean1 = s1 * (1.0f / DM);

    float q0 = 0.f, q1 = 0.f;
#pragma unroll
    for (int k = 0; k < 4; k++) {
        v0[k].x -= mean0; v0[k].y -= mean0; v0[k].z -= mean0; v0[k].w -= mean0;
        v1[k].x -= mean1; v1[k].y -= mean1; v1[k].z -= mean1; v1[k].w -= mean1;
        q0 += v0[k].x * v0[k].x + v0[k].y * v0[k].y + v0[k].z * v0[k].z + v0[k].w * v0[k].w;
        q1 += v1[k].x * v1[k].x + v1[k].y * v1[k].y + v1[k].z * v1[k].z + v1[k].w * v1[k].w;
    }
#pragma unroll
    for (int o = 16; o > 0; o >>= 1) {
        q0 += __shfl_xor_sync(0xffffffffu, q0, o);
        q1 += __shfl_xor_sync(0xffffffffu, q1, o);
    }
    float rstd0 = rsqrtf(q0 * (1.0f / DM) + LNEPS);
    float rstd1 = rsqrtf(q1 * (1.0f / DM) + LNEPS);

    const float* g0 = (const float*)q_at(gq, 2 * p);
    const float* b0 = (const float*)q_at(bq, 2 * p);
    const float* g1 = (const float*)q_at(gq, 2 * p + 1);
    const float* b1 = (const float*)q_at(bq, 2 * p + 1);

    float* outr = out + (size_t)p * NTOK * DM + (size_t)row * DM;
#pragma unroll
    for (int k = 0; k < 4; k++) {
        float4 gg0 = ((const float4*)g0)[lane + 32 * k], bb0 = ((const float4*)b0)[lane + 32 * k];
        float4 gg1 = ((const float4*)g1)[lane + 32 * k], bb1 = ((const float4*)b1)[lane + 32 * k];
        float4 y;
        y.x = (v0[k].x * rstd0 * gg0.x + bb0.x) + (v1[k].x * rstd1 * gg1.x + bb1.x);
        y.y = (v0[k].y * rstd0 * gg0.y + bb0.y) + (v1[k].y * rstd1 * gg1.y + bb1.y);
        y.z = (v0[k].z * rstd0 * gg0.z + bb0.z) + (v1[k].z * rstd1 * gg1.z + bb1.z);
        y.w = (v0[k].w * rstd0 * gg0.w + bb0.w) + (v1[k].w * rstd1 * gg1.w + bb1.w);
        ((float4*)outr)[lane + 32 * k] = y;
    }
}

// ========== tensor-core segment attention: 4 warps per (seg, head, enc), m-strided ==========
__global__ __launch_bounds__(128) void attn_tc_kernel()
{
    int s = blockIdx.x;
    int h = blockIdx.y;
    int e = blockIdx.z;
    int off = g_offs[s];
    int L = g_offs[s + 1] - off;
    int L16 = (L + 15) & ~15;
    int npairs = L16 >> 4;

    const int srcQ = e >> 1, halfQ = e & 1;
    const int srcKV_t[4]  = {0, 1, 1, 0};
    const int halfKV_t[4] = {0, 0, 1, 1};
    const int srcKV = srcKV_t[e], halfKV = halfKV_t[e];

    const __nv_bfloat16* Qb = g_Qb4 + (size_t)srcQ  * NTOK * NQ + halfQ  * 512 + h * DKH;
    const __nv_bfloat16* Kb = g_KB4 + (size_t)srcKV * NTOK * NQ + halfKV * 512 + h * DKH;
    const __nv_bfloat16* Vb = g_Vb4 + (size_t)srcKV * NTOK * NQ + halfKV * 512 + h * DKH;

    __shared__ __align__(16) __nv_bfloat16 Ks[96 * 72];
    __shared__ __align__(16) __nv_bfloat16 Vs[96 * 72];
    int tid = threadIdx.x;
    int lane = tid & 31;
    int wid = tid >> 5;
    uint4 zz; zz.x = zz.y = zz.z = zz.w = 0u;
    // cooperative K/V staging with all 128 threads
    for (int idx = tid; idx < L16 * 8; idx += 128) {
        int j = idx >> 3, c = idx & 7;
        uint4 uk = zz, uv = zz;
        if (j < L) {
            uk = ((const uint4*)(Kb + (size_t)(off + j) * 1024))[c];
            uv = ((const uint4*)(Vb + (size_t)(off + j) * 1024))[c];
        }
        *(uint4*)&Ks[j * 72 + c * 8] = uk;
        *(uint4*)&Vs[j * 72 + c * 8] = uv;
    }
    __syncthreads();

    const uint32_t uK = smem_u32(Ks);
    const uint32_t uV = smem_u32(Vs);
    const int r0 = lane >> 2;
    const int cq = (lane & 3) * 2;
    const int lmrow = lane & 15;
    const int lmhalf = lane >> 4;

    // warps take m-tiles strided by 64 rows
    for (int m0 = wid * 16; m0 < L; m0 += 64) {
        uint32_t qa[4][4];
        int row1 = off + min(m0 + r0, L - 1);
        int row2 = off + min(m0 + r0 + 8, L - 1);
#pragma unroll
        for (int kf = 0; kf < 4; kf++) {
            qa[kf][0] = *(const uint32_t*)(Qb + (size_t)row1 * 1024 + kf * 16 + cq);
            qa[kf][1] = *(const uint32_t*)(Qb + (size_t)row2 * 1024 + kf * 16 + cq);
            qa[kf][2] = *(const uint32_t*)(Qb + (size_t)row1 * 1024 + kf * 16 + cq + 8);
            qa[kf][3] = *(const uint32_t*)(Qb + (size_t)row2 * 1024 + kf * 16 + cq + 8);
        }

        float S[12][4];
#pragma unroll
        for (int t = 0; t < 12; t++) { S[t][0] = S[t][1] = S[t][2] = S[t][3] = 0.f; }
#pragma unroll
        for (int np = 0; np < 6; np++) {
            if (np < npairs) {
#pragma unroll
                for (int kf = 0; kf < 4; kf++) {
                    uint32_t addr = uK + ((np * 16 + lmrow) * 72 + kf * 16 + lmhalf * 8) * 2;
                    uint32_t r0_, r1_, r2_, r3_;
                    ldmatrix_x4(r0_, r1_, r2_, r3_, addr);
                    uint32_t b0[2] = { r0_, r2_ };
                    uint32_t b1[2] = { r1_, r3_ };
                    mma_bf16(S[2 * np + 0], qa[kf], b0);
                    mma_bf16(S[2 * np + 1], qa[kf], b1);
                }
            }
        }

#pragma unroll
        for (int t = 0; t < 12; t++) {
            int c = t * 8 + cq;
            S[t][0] = (c     < L) ? S[t][0] * 0.125f : -INFINITY;
            S[t][1] = (c + 1 < L) ? S[t][1] * 0.125f : -INFINITY;
            S[t][2] = (c     < L) ? S[t][2] * 0.125f : -INFINITY;
            S[t][3] = (c + 1 < L) ? S[t][3] * 0.125f : -INFINITY;
        }

        float mx1 = -INFINITY, mx2 = -INFINITY;
#pragma unroll
        for (int t = 0; t < 12; t++) {
            mx1 = fmaxf(mx1, fmaxf(S[t][0], S[t][1]));
            mx2 = fmaxf(mx2, fmaxf(S[t][2], S[t][3]));
        }
        mx1 = fmaxf(mx1, __shfl_xor_sync(0xffffffffu, mx1, 1));
        mx1 = fmaxf(mx1, __shfl_xor_sync(0xffffffffu, mx1, 2));
        mx2 = fmaxf(mx2, __shfl_xor_sync(0xffffffffu, mx2, 1));
        mx2 = fmaxf(mx2, __shfl_xor_sync(0xffffffffu, mx2, 2));

        float l1 = 0.f, l2 = 0.f;
#pragma unroll
        for (int t = 0; t < 12; t++) {
            S[t][0] = __expf(S[t][0] - mx1);
            S[t][1] = __expf(S[t][1] - mx1);
            S[t][2] = __expf(S[t][2] - mx2);
            S[t][3] = __expf(S[t][3] - mx2);
            l1 += S[t][0] + S[t][1];
            l2 += S[t][2] + S[t][3];
        }
        l1 += __shfl_xor_sync(0xffffffffu, l1, 1);
        l1 += __shfl_xor_sync(0xffffffffu, l1, 2);
        l2 += __shfl_xor_sync(0xffffffffu, l2, 1);
        l2 += __shfl_xor_sync(0xffffffffu, l2, 2);

        uint32_t pf[6][4];
#pragma unroll
        for (int np = 0; np < 6; np++) {
            __nv_bfloat162 h2;
            h2.x = __float2bfloat16_rn(S[2 * np + 0][0]); h2.y = __float2bfloat16_rn(S[2 * np + 0][1]);
            pf[np][0] = *(uint32_t*)&h2;
            h2.x = __float2bfloat16_rn(S[2 * np + 0][2]); h2.y = __float2bfloat16_rn(S[2 * np + 0][3]);
            pf[np][1] = *(uint32_t*)&h2;
            h2.x = __float2bfloat16_rn(S[2 * np + 1][0]); h2.y = __float2bfloat16_rn(S[2 * np + 1][1]);
            pf[np][2] = *(uint32_t*)&h2;
            h2.x = __float2bfloat16_rn(S[2 * np + 1][2]); h2.y = __float2bfloat16_rn(S[2 * np + 1][3]);
            pf[np][3] = *(uint32_t*)&h2;
        }

        float O[8][4];
#pragma unroll
        for (int nt = 0; nt < 8; nt++) { O[nt][0] = O[nt][1] = O[nt][2] = O[nt][3] = 0.f; }
#pragma unroll
        for (int kt = 0; kt < 6; kt++) {
            if (kt < npairs) {
#pragma unroll
                for (int nt = 0; nt < 8; nt += 2) {
                    uint32_t addr = uV + ((kt * 16 + lmrow) * 72 + nt * 8 + lmhalf * 8) * 2;
                    uint32_t r0_, r1_, r2_, r3_;
                    ldmatrix_x4_t(r0_, r1_, r2_, r3_, addr);
                    uint32_t b0[2] = { r0_, r1_ };
                    uint32_t b1[2] = { r2_, r3_ };
                    mma_bf16(O[nt + 0], pf[kt], b0);
                    mma_bf16(O[nt + 1], pf[kt], b1);
                }
            }
        }

        float il1 = 1.0f / l1, il2 = 1.0f / l2;
        int gr1 = m0 + r0, gr2 = gr1 + 8;
        __nv_bfloat16* obase = g_ctxb4 + (size_t)e * NTOK * DM + h * DKH;
        if (gr1 < L) {
            __nv_bfloat16* o1 = obase + (size_t)(off + gr1) * DM;
#pragma unroll
            for (int nt = 0; nt < 8; nt++) {
                __nv_bfloat162 h2;
                h2.x = __float2bfloat16_rn(O[nt][0] * il1);
                h2.y = __float2bfloat16_rn(O[nt][1] * il1);
                *(__nv_bfloat162*)(o1 + nt * 8 + cq) = h2;
            }
        }
        if (gr2 < L) {
            __nv_bfloat16* o2 = obase + (size_t)(off + gr2) * DM;
#pragma unroll
            for (int nt = 0; nt < 8; nt++) {
                __nv_bfloat162 h2;
                h2.x = __float2bfloat16_rn(O[nt][2] * il2);
                h2.y = __float2bfloat16_rn(O[nt][3] * il2);
                *(__nv_bfloat162*)(o2 + nt * 8 + cq) = h2;
            }
        }
    }
}

// ================= host =================
extern "C" void kernel_launch(void* const* d_in, const int* in_sizes, int n_in,
                              void* d_out, int out_size)
{
    const float* vis  = (const float*)d_in[0];
    const float* txt  = (const float*)d_in[1];
    const float* Wq   = (const float*)d_in[2];
    const float* bq   = (const float*)d_in[3];
    const float* Wk   = (const float*)d_in[4];
    const float* bk   = (const float*)d_in[5];
    const float* Wv   = (const float*)d_in[6];
    const float* bv   = (const float*)d_in[7];
    const float* Wo   = (const float*)d_in[8];
    const float* bo   = (const float*)d_in[9];
    const float* g1   = (const float*)d_in[10];
    const float* be1  = (const float*)d_in[11];
    const float* W1   = (const float*)d_in[12];
    const float* b1   = (const float*)d_in[13];
    const float* W2   = (const float*)d_in[14];
    const float* b2   = (const float*)d_in[15];
    const float* g2   = (const float*)d_in[16];
    const float* be2  = (const float*)d_in[17];
    const int*   nobj = (const int*)d_in[18];
    float* out = (float*)d_out;

    float *T14, *OUT14, *BQKV;
    __nv_bfloat16 *QB4, *KB4, *VB4, *VISB, *TXTB, *CTXB4, *OUT1B4, *HB4;
    __nv_bfloat16 *WqkvT4, *WoT, *W1T, *W2T;
    cudaGetSymbolAddress((void**)&T14, g_t14);
    cudaGetSymbolAddress((void**)&OUT14, g_out14);
    cudaGetSymbolAddress((void**)&BQKV, g_bqkv);
    cudaGetSymbolAddress((void**)&QB4, g_Qb4);
    cudaGetSymbolAddress((void**)&KB4, g_KB4);
    cudaGetSymbolAddress((void**)&VB4, g_Vb4);
    cudaGetSymbolAddress((void**)&VISB, g_visb);
    cudaGetSymbolAddress((void**)&TXTB, g_txtb);
    cudaGetSymbolAddress((void**)&CTXB4, g_ctxb4);
    cudaGetSymbolAddress((void**)&OUT1B4, g_out1b4);
    cudaGetSymbolAddress((void**)&HB4, g_hb4);
    cudaGetSymbolAddress((void**)&WqkvT4, g_WqkvT4);
    cudaGetSymbolAddress((void**)&WoT, g_WoT);
    cudaGetSymbolAddress((void**)&W1T, g_W1T);
    cudaGetSymbolAddress((void**)&W2T, g_W2T);

    cudaFuncSetAttribute(gemm_bf16_k<false, false, false, false, true >, cudaFuncAttributeMaxDynamicSharedMemorySize, GEMM_SMEM);
    cudaFuncSetAttribute(gemm_bf16_k<false, true,  true,  false, false>, cudaFuncAttributeMaxDynamicSharedMemorySize, GEMM_SMEM);
    cudaFuncSetAttribute(gemm_bf16_k<true,  false, false, true,  false>, cudaFuncAttributeMaxDynamicSharedMemorySize, GEMM_SMEM);

    auto U4 = [](const void* a, const void* b, const void* c, const void* d) {
        ulong4 u; u.x = (u64)a; u.y = (u64)b; u.z = (u64)c; u.w = (u64)d; return u;
    };

    // 0: mega prepass
    {
        TT tt;
        const size_t BLK = (size_t)DM * DM;
        const u64 qoff[4] = {0, 6 * BLK, 1 * BLK, 7 * BLK};
        const u64 koff[4] = {2 * BLK, 10 * BLK, 8 * BLK, 4 * BLK};
        const u64 voff[4] = {3 * BLK, 11 * BLK, 9 * BLK, 5 * BLK};
        for (int p = 0; p < 4; p++) {
            tt.src[p]      = (u64)(Wq + (size_t)p * BLK); tt.dst[p]      = (u64)(WqkvT4 + qoff[p]);
            tt.src[4 + p]  = (u64)(Wk + (size_t)p * BLK); tt.dst[4 + p]  = (u64)(WqkvT4 + koff[p]);
            tt.src[8 + p]  = (u64)(Wv + (size_t)p * BLK); tt.dst[8 + p]  = (u64)(WqkvT4 + voff[p]);
            tt.src[12 + p] = (u64)(Wo + (size_t)p * BLK); tt.dst[12 + p] = (u64)(WoT + (size_t)p * BLK);
            tt.src[16 + p] = (u64)(W1 + (size_t)p * DM * DI); tt.dst[16 + p] = (u64)(W1T + (size_t)p * DI * DM);
            tt.src[20 + p] = (u64)(W2 + (size_t)p * DI * DM); tt.dst[20 + p] = (u64)(W2T + (size_t)p * DM * DI);
        }
        megaprep_kernel<<<25633, 256>>>(tt, vis, txt, bq, bk, bv, nobj);
    }

    const int MT = (NTOK + 127) / 128;
    const size_t SL = (size_t)NTOK * DM;
    const int perm[4] = {0, 2, 1, 3};
    ulong4 nullq; nullq.x = nullq.y = nullq.z = nullq.w = 0;

    // 1: fused QKV GEMM
    {
        ulong4 Aq = U4(VISB, TXTB, nullptr, nullptr);
        ulong4 Bq = U4(WqkvT4, WqkvT4 + (size_t)NQKV * DM, nullptr, nullptr);
        ulong4 bq_ = U4(BQKV, BQKV + NQKV, nullptr, nullptr);
        gemm_bf16_k<false, false, false, false, true><<<dim3(NQKV / 128, MT, 2), 256, GEMM_SMEM>>>(
            Aq, Bq, bq_, nullq, (float*)VB4, 0, QB4, (size_t)NTOK * NQ, KB4, NTOK, DM, NQKV);
    }

    // 2: tensor-core attention (4 warps / block)
    attn_tc_kernel<<<dim3(BATCH, NH, 4), 128>>>();

    // 3: proj + residual
    {
        const size_t BLK = (size_t)DM * DM;
        ulong4 Aq = U4(CTXB4, CTXB4 + SL, CTXB4 + 2 * SL, CTXB4 + 3 * SL);
        ulong4 Bq = U4(WoT + perm[0] * BLK, WoT + perm[1] * BLK, WoT + perm[2] * BLK, WoT + perm[3] * BLK);
        ulong4 bq_ = U4(bo + perm[0] * DM, bo + perm[1] * DM, bo + perm[2] * DM, bo + perm[3] * DM);
        ulong4 Rq = U4(vis, vis, txt, txt);
        gemm_bf16_k<false, true, true, false, false><<<dim3(DM / 128, MT, 4), 256, GEMM_SMEM>>>(
            Aq, Bq, bq_, Rq, T14, SL, nullptr, 0, nullptr, NTOK, DM, DM);
    }
    // 4: LN1 (warp-per-row)
    {
        ulong4 gq = U4(g1 + perm[0] * DM, g1 + perm[1] * DM, g1 + perm[2] * DM, g1 + perm[3] * DM);
        ulong4 bq_ = U4(be1 + perm[0] * DM, be1 + perm[1] * DM, be1 + perm[2] * DM, be1 + perm[3] * DM);
        ln1_kernel<<<dim3(NTOK / 8, 4), 256>>>(T14, SL, gq, bq_, OUT14, SL, OUT1B4, SL);
    }
    // 5: FFN1
    {
        ulong4 Aq = U4(OUT1B4, OUT1B4 + SL, OUT1B4 + 2 * SL, OUT1B4 + 3 * SL);
        const size_t WB = (size_t)DI * DM;
        ulong4 Bq = U4(W1T + perm[0] * WB, W1T + perm[1] * WB, W1T + perm[2] * WB, W1T + perm[3] * WB);
        ulong4 bq_ = U4(b1 + perm[0] * DI, b1 + perm[1] * DI, b1 + perm[2] * DI, b1 + perm[3] * DI);
        gemm_bf16_k<true, false, false, true, false><<<dim3(DI / 128, MT, 4), 256, GEMM_SMEM>>>(
            Aq, Bq, bq_, nullq, nullptr, 0, HB4, (size_t)NTOK * DI, nullptr, NTOK, DM, DI);
    }
    // 6: FFN2 + residual
    {
        const size_t HL = (size_t)NTOK * DI;
        ulong4 Aq = U4(HB4, HB4 + HL, HB4 + 2 * HL, HB4 + 3 * HL);
        const size_t WB = (size_t)DM * DI;
        ulong4 Bq = U4(W2T + perm[0] * WB, W2T + perm[1] * WB, W2T + perm[2] * WB, W2T + perm[3] * WB);
        ulong4 bq_ = U4(b2 + perm[0] * DM, b2 + perm[1] * DM, b2 + perm[2] * DM, b2 + perm[3] * DM);
        ulong4 Rq = U4(OUT14, OUT14 + SL, OUT14 + 2 * SL, OUT14 + 3 * SL);
        gemm_bf16_k<false, true, true, false, false><<<dim3(DM / 128, MT, 4), 256, GEMM_SMEM>>>(
            Aq, Bq, bq_, Rq, T14, SL, nullptr, 0, nullptr, NTOK, DI, DM);
    }
    // 7: LN2 + sum -> d_out (warp-per-row)
    {
        ulong4 gq = U4(g2 + perm[0] * DM, g2 + perm[1] * DM, g2 + perm[2] * DM, g2 + perm[3] * DM);
        ulong4 bq_ = U4(be2 + perm[0] * DM, be2 + perm[1] * DM, be2 + perm[2] * DM, be2 + perm[3] * DM);
        ln2_pair_kernel<<<dim3(NTOK / 8, 2), 256>>>(T14, SL, gq, bq_, out);
    }
}